// round 1
// baseline (speedup 1.0000x reference)
#include <cuda_runtime.h>
#include <cstdint>
#include <math.h>

#define N    8192
#define NW   (N/32)    // 256 adjacency words per row
#define FIN  512
#define KH   64        // per-head hidden
#define H    8
#define NCLS 16

// ---------------- scratch (no allocations allowed) ----------------
__device__ uint32_t g_bits[N * NW];        // 8 MB packed adjacency
__device__ float    g_Wh   [N * FIN];      // per-head Wh, concatenated [N, 512]
__device__ float    g_h    [N * FIN];      // head outputs, concatenated [N, 512]
__device__ float    g_Whout[N * NCLS];     // output-layer Wh [N, 16]
__device__ float    g_s1   [H * N];
__device__ float    g_s2   [H * N];
__device__ float    g_s1o  [N];
__device__ float    g_s2o  [N];

// ---------------- adjacency bit-pack ----------------
__global__ void pack_adj_kernel(const int* __restrict__ adj) {
    int warps = gridDim.x * (blockDim.x >> 5);
    int gw    = blockIdx.x * (blockDim.x >> 5) + (threadIdx.x >> 5);
    int lane  = threadIdx.x & 31;
    const int total = N * NW;
    for (int w = gw; w < total; w += warps) {
        int v = adj[(size_t)w * 32 + lane];
        unsigned m = __ballot_sync(0xffffffffu, v > 0);
        if (lane == 0) g_bits[w] = m;
    }
}

// ---------------- feature GEMM: C[:, head*BN : ] = A @ B[head] ----------------
// A: [N, lda] fp32.  B: [gridDim.y][512][BN] contiguous.  BM=128, BK=32, 256 thr,
// micro-tile 8 x MN (MN = BN/16).
template<int BN, int MN>
__global__ __launch_bounds__(256) void gemm_kernel(
    const float* __restrict__ A, int lda,
    const float* __restrict__ B,
    float* __restrict__ C, int ldc)
{
    constexpr int BM = 128, BK = 32;
    __shared__ float sAT[BK][BM + 1];
    __shared__ float sB[BK][BN];

    int t    = threadIdx.x;
    int head = blockIdx.y;
    int i0   = blockIdx.x * BM;
    const float* Bh = B + (size_t)head * FIN * BN;

    int tx = t & 15, ty = t >> 4;
    float acc[8][MN];
#pragma unroll
    for (int r = 0; r < 8; r++)
#pragma unroll
        for (int c = 0; c < MN; c++) acc[r][c] = 0.f;

    for (int k0 = 0; k0 < FIN; k0 += BK) {
        __syncthreads();
#pragma unroll
        for (int i = 0; i < (BM * BK) / 256; i++) {
            int l = t + i * 256;
            int r = l >> 5, c = l & 31;
            sAT[c][r] = A[(size_t)(i0 + r) * lda + k0 + c];
        }
#pragma unroll
        for (int i = 0; i < (BK * BN) / 256; i++) {
            int l = t + i * 256;
            int r = l / BN, c = l % BN;
            sB[r][c] = Bh[(size_t)(k0 + r) * BN + c];
        }
        __syncthreads();
#pragma unroll 8
        for (int kk = 0; kk < BK; kk++) {
            float a[8];
#pragma unroll
            for (int r = 0; r < 8; r++) a[r] = sAT[kk][ty * 8 + r];
            float b[MN];
#pragma unroll
            for (int c = 0; c < MN; c++) b[c] = sB[kk][tx * MN + c];
#pragma unroll
            for (int r = 0; r < 8; r++)
#pragma unroll
                for (int c = 0; c < MN; c++) acc[r][c] += a[r] * b[c];
        }
    }
#pragma unroll
    for (int r = 0; r < 8; r++) {
        int i = i0 + ty * 8 + r;
#pragma unroll
        for (int c = 0; c < MN; c++)
            C[(size_t)i * ldc + head * BN + tx * MN + c] = acc[r][c];
    }
}

// ---------------- attention scores s1, s2 (heads) ----------------
__global__ void s_heads_kernel(const float* __restrict__ a_heads) {
    int gw   = blockIdx.x * 8 + (threadIdx.x >> 5);
    int lane = threadIdx.x & 31;
    int i = gw >> 3, h = gw & 7;
    if (i >= N) return;
    const float* wh = g_Wh + (size_t)i * FIN + h * KH;
    const float* a  = a_heads + (size_t)h * 2 * KH;
    float v1 = wh[lane] * a[lane]      + wh[lane + 32] * a[lane + 32];
    float v2 = wh[lane] * a[KH + lane] + wh[lane + 32] * a[KH + lane + 32];
#pragma unroll
    for (int o = 16; o; o >>= 1) {
        v1 += __shfl_down_sync(0xffffffffu, v1, o);
        v2 += __shfl_down_sync(0xffffffffu, v2, o);
    }
    if (lane == 0) { g_s1[h * N + i] = v1; g_s2[h * N + i] = v2; }
}

// ---------------- attention scores s1, s2 (output layer) ----------------
__global__ void s_out_kernel(const float* __restrict__ a_out) {
    int gw   = blockIdx.x * 8 + (threadIdx.x >> 5);
    int lane = threadIdx.x & 31;
    if (gw >= N) return;
    float v1 = 0.f, v2 = 0.f;
    if (lane < NCLS) {
        float w = g_Whout[(size_t)gw * NCLS + lane];
        v1 = w * a_out[lane];
        v2 = w * a_out[NCLS + lane];
    }
#pragma unroll
    for (int o = 16; o; o >>= 1) {
        v1 += __shfl_down_sync(0xffffffffu, v1, o);
        v2 += __shfl_down_sync(0xffffffffu, v2, o);
    }
    if (lane == 0) { g_s1o[gw] = v1; g_s2o[gw] = v2; }
}

// ---------------- fused masked-softmax attention GEMM ----------------
// out[i, head*KD + k] = ( sum_j m[i,j] exp(leaky(s1[i]+s2[j])) Wh[j, head*KD+k] ) / den[i]
// IT=128 rows per block, JT=64 col tile, 256 threads, micro 8 x (KD/16).
template<int KD, bool DO_ELU>
__global__ __launch_bounds__(256) void attn_kernel(
    const float* __restrict__ Wh, int ldw,
    const float* __restrict__ s1g, const float* __restrict__ s2g,
    float* __restrict__ Out, int ldo)
{
    constexpr int IT = 128, JT = 64, MN = KD / 16;
    extern __shared__ float sm[];
    float* sP   = sm;                   // IT * 65
    float* sB   = sP + IT * 65;         // JT * KD
    float* sS2  = sB + JT * KD;         // JT
    float* sS1  = sS2 + JT;             // IT
    float* sDen = sS1 + IT;             // IT

    int t    = threadIdx.x;
    int head = blockIdx.y;
    int i0   = blockIdx.x * IT;
    const float* s1  = s1g + (size_t)head * N;
    const float* s2  = s2g + (size_t)head * N;
    const float* WhH = Wh + head * KD;

    if (t < IT) { sS1[t] = s1[i0 + t]; sDen[t] = 0.f; }

    int tx = t & 15, ty = t >> 4;       // GEMM mapping
    int prow = t & (IT - 1);            // P-compute mapping (conflict-free STS)
    int jseg = t >> 7;                  // 0/1 -> one adjacency word each

    float acc[8][MN];
#pragma unroll
    for (int r = 0; r < 8; r++)
#pragma unroll
        for (int c = 0; c < MN; c++) acc[r][c] = 0.f;

    for (int j0 = 0; j0 < N; j0 += JT) {
        __syncthreads();
        // load Wh tile [JT x KD] (float4, coalesced)
#pragma unroll
        for (int i = 0; i < (JT * KD / 4) / 256; i++) {
            int l = t + i * 256;
            int r = l / (KD / 4), c4 = l % (KD / 4);
            float4 v = *(const float4*)(WhH + (size_t)(j0 + r) * ldw + c4 * 4);
            *(float4*)(sB + r * KD + c4 * 4) = v;
        }
        if (t < JT) sS2[t] = s2[j0 + t];
        __syncthreads();

        // compute P tile: each thread = 1 row x 32 cols = exactly one adj word
        {
            float s1v = sS1[prow];
            uint32_t w = g_bits[(size_t)(i0 + prow) * NW + (j0 >> 5) + jseg];
            float lsum = 0.f;
            float* pr = sP + prow * 65 + jseg * 32;
            const float* s2p = sS2 + jseg * 32;
#pragma unroll
            for (int jj = 0; jj < 32; jj++) {
                float s = s1v + s2p[jj];
                float e = fmaxf(s, 0.2f * s);          // leaky_relu, slope 0.2
                float p = ((w >> jj) & 1u) ? __expf(e) : 0.f;
                pr[jj] = p;
                lsum += p;
            }
            atomicAdd(&sDen[prow], lsum);
        }
        __syncthreads();

        // register-tiled accumulate: acc += P_tile @ Wh_tile
#pragma unroll 8
        for (int jj = 0; jj < JT; jj++) {
            float a[8];
#pragma unroll
            for (int r = 0; r < 8; r++) a[r] = sP[(ty * 8 + r) * 65 + jj];
            if constexpr (MN == 4) {
                float4 b = *(const float4*)(sB + jj * KD + tx * 4);
#pragma unroll
                for (int r = 0; r < 8; r++) {
                    acc[r][0] += a[r] * b.x;
                    acc[r][1] += a[r] * b.y;
                    acc[r][2] += a[r] * b.z;
                    acc[r][3] += a[r] * b.w;
                }
            } else {
                float b = sB[jj * KD + tx];
#pragma unroll
                for (int r = 0; r < 8; r++) acc[r][0] += a[r] * b;
            }
        }
    }
    __syncthreads();

#pragma unroll
    for (int r = 0; r < 8; r++) {
        int i = i0 + ty * 8 + r;
        float inv = 1.0f / sDen[ty * 8 + r];
#pragma unroll
        for (int c = 0; c < MN; c++) {
            float v = acc[r][c] * inv;
            if (DO_ELU) v = (v > 0.f) ? v : expm1f(v);
            Out[(size_t)i * ldo + head * KD + tx * MN + c] = v;
        }
    }
}

// ---------------- launch ----------------
extern "C" void kernel_launch(void* const* d_in, const int* in_sizes, int n_in,
                              void* d_out, int out_size)
{
    const float* x       = nullptr;
    const int*   adj     = nullptr;
    const float* W_heads = nullptr;
    const float* a_heads = nullptr;
    const float* W_out   = nullptr;
    const float* a_out   = nullptr;

    for (int i = 0; i < n_in; i++) {
        switch (in_sizes[i]) {
            case N * FIN:        x       = (const float*)d_in[i]; break;  // 4194304
            case 67108864:       adj     = (const int*)  d_in[i]; break;  // N*N
            case H * FIN * KH:   W_heads = (const float*)d_in[i]; break;  // 262144
            case H * 2 * KH:     a_heads = (const float*)d_in[i]; break;  // 1024
            case FIN * NCLS:     W_out   = (const float*)d_in[i]; break;  // 8192
            case 2 * NCLS:       a_out   = (const float*)d_in[i]; break;  // 32
        }
    }

    float *whP, *hP, *whoP, *s1P, *s2P, *s1oP, *s2oP;
    cudaGetSymbolAddress((void**)&whP,  g_Wh);
    cudaGetSymbolAddress((void**)&hP,   g_h);
    cudaGetSymbolAddress((void**)&whoP, g_Whout);
    cudaGetSymbolAddress((void**)&s1P,  g_s1);
    cudaGetSymbolAddress((void**)&s2P,  g_s2);
    cudaGetSymbolAddress((void**)&s1oP, g_s1o);
    cudaGetSymbolAddress((void**)&s2oP, g_s2o);

    const int SMEM64 = (128 * 65 + 64 * 64 + 64 + 128 + 128) * 4;  // 50944
    const int SMEM16 = (128 * 65 + 64 * 16 + 64 + 128 + 128) * 4;  // 38656
    cudaFuncSetAttribute(attn_kernel<64, false>,
                         cudaFuncAttributeMaxDynamicSharedMemorySize, SMEM64);
    cudaFuncSetAttribute(attn_kernel<16, true>,
                         cudaFuncAttributeMaxDynamicSharedMemorySize, SMEM16);

    // 1. pack adjacency to bitmask (8 MB, L2-resident for all 9 layers)
    pack_adj_kernel<<<4096, 256>>>(adj);

    // 2. per-head feature GEMM: g_Wh[:, h*64:(h+1)*64] = x @ W_heads[h]
    gemm_kernel<64, 4><<<dim3(N / 128, H), 256>>>(x, FIN, W_heads, whP, FIN);

    // 3. attention scores per head
    s_heads_kernel<<<(N * H) / 8, 256>>>(a_heads);

    // 4. fused masked-softmax attention per head -> g_h
    attn_kernel<64, false><<<dim3(N / 128, H), 256, SMEM64>>>(
        whP, FIN, s1P, s2P, hP, FIN);

    // 5. output-layer feature GEMM: g_Whout = g_h @ W_out
    gemm_kernel<16, 1><<<dim3(N / 128, 1), 256>>>(hP, FIN, W_out, whoP, NCLS);

    // 6. output-layer scores
    s_out_kernel<<<N / 8, 256>>>(a_out);

    // 7. output-layer attention + ELU -> d_out
    attn_kernel<16, true><<<dim3(N / 128, 1), 256, SMEM16>>>(
        whoP, NCLS, s1oP, s2oP, (float*)d_out, NCLS);
}

// round 3
// speedup vs baseline: 2.3644x; 2.3644x over previous
#include <cuda_runtime.h>
#include <cuda_fp16.h>
#include <cstdint>
#include <math.h>

#define N    8192
#define NW   (N/32)
#define FIN  512
#define KH   64
#define H    8
#define NCLS 16

// ---------------- scratch ----------------
__device__ uint32_t g_bitsT[NW * N];       // transposed bitmap [word][row]
__device__ float    g_Wh   [N * FIN];      // layer-1 Wh fp32
__device__ __half   g_Wh16 [N * FIN];      // layer-1 Wh fp16 (row-major)
__device__ float    g_h    [N * FIN];      // head outputs
__device__ float    g_Whout[N * NCLS];
__device__ float    g_E1[H * N], g_F1[H * N];
__device__ float    g_E2[H * N], g_F2[H * N];
__device__ float    g_s1o[N], g_s2o[N];

#define SWZ128(o) ((o) ^ (((o) >> 3) & 0x70))

__device__ __forceinline__ uint32_t smem_u32(const void* p) {
    return (uint32_t)__cvta_generic_to_shared(p);
}
__device__ __forceinline__ void ldsm4(uint32_t& r0, uint32_t& r1, uint32_t& r2,
                                      uint32_t& r3, uint32_t a) {
    asm volatile("ldmatrix.sync.aligned.m8n8.x4.shared.b16 {%0,%1,%2,%3}, [%4];"
                 : "=r"(r0), "=r"(r1), "=r"(r2), "=r"(r3) : "r"(a));
}
__device__ __forceinline__ void ldsm4t(uint32_t& r0, uint32_t& r1, uint32_t& r2,
                                       uint32_t& r3, uint32_t a) {
    asm volatile("ldmatrix.sync.aligned.m8n8.x4.trans.shared.b16 {%0,%1,%2,%3}, [%4];"
                 : "=r"(r0), "=r"(r1), "=r"(r2), "=r"(r3) : "r"(a));
}
__device__ __forceinline__ void mma16816(float* d, uint32_t a0, uint32_t a1,
                                         uint32_t a2, uint32_t a3,
                                         uint32_t b0, uint32_t b1) {
    asm volatile(
        "mma.sync.aligned.m16n8k16.row.col.f32.f16.f16.f32 "
        "{%0,%1,%2,%3}, {%4,%5,%6,%7}, {%8,%9}, {%0,%1,%2,%3};"
        : "+f"(d[0]), "+f"(d[1]), "+f"(d[2]), "+f"(d[3])
        : "r"(a0), "r"(a1), "r"(a2), "r"(a3), "r"(b0), "r"(b1));
}
__device__ __forceinline__ uint32_t f2h2(float lo, float hi) {
    uint32_t r;
    asm("cvt.rn.f16x2.f32 %0, %1, %2;" : "=r"(r) : "f"(hi), "f"(lo));
    return r;
}

// ---------------- adjacency bit-pack (transposed output) ----------------
__global__ void pack_adj_kernel(const int* __restrict__ adj) {
    int warps = gridDim.x * (blockDim.x >> 5);
    int gw    = blockIdx.x * (blockDim.x >> 5) + (threadIdx.x >> 5);
    int lane  = threadIdx.x & 31;
    const int total = N * NW;
    for (int w = gw; w < total; w += warps) {
        int v = adj[(size_t)w * 32 + lane];
        unsigned m = __ballot_sync(0xffffffffu, v > 0);
        if (lane == 0) g_bitsT[(size_t)(w & (NW - 1)) * N + (w >> 8)] = m;
    }
}

// ---------------- fp32 feature GEMM (optional fp16 mirror) ----------------
template<int BN, int MN, bool WR16>
__global__ __launch_bounds__(256) void gemm_kernel(
    const float* __restrict__ A, int lda, const float* __restrict__ B,
    float* __restrict__ C, int ldc, __half* __restrict__ C16)
{
    constexpr int BM = 128, BK = 32;
    __shared__ float sAT[BK][BM + 1];
    __shared__ float sB[BK][BN];
    int t = threadIdx.x, head = blockIdx.y, i0 = blockIdx.x * BM;
    const float* Bh = B + (size_t)head * FIN * BN;
    int tx = t & 15, ty = t >> 4;
    float acc[8][MN];
#pragma unroll
    for (int r = 0; r < 8; r++)
#pragma unroll
        for (int c = 0; c < MN; c++) acc[r][c] = 0.f;
    for (int k0 = 0; k0 < FIN; k0 += BK) {
        __syncthreads();
#pragma unroll
        for (int i = 0; i < (BM * BK) / 256; i++) {
            int l = t + i * 256, r = l >> 5, c = l & 31;
            sAT[c][r] = A[(size_t)(i0 + r) * lda + k0 + c];
        }
#pragma unroll
        for (int i = 0; i < (BK * BN) / 256; i++) {
            int l = t + i * 256, r = l / BN, c = l % BN;
            sB[r][c] = Bh[(size_t)(k0 + r) * BN + c];
        }
        __syncthreads();
#pragma unroll 8
        for (int kk = 0; kk < BK; kk++) {
            float a[8];
#pragma unroll
            for (int r = 0; r < 8; r++) a[r] = sAT[kk][ty * 8 + r];
            float b[MN];
#pragma unroll
            for (int c = 0; c < MN; c++) b[c] = sB[kk][tx * MN + c];
#pragma unroll
            for (int r = 0; r < 8; r++)
#pragma unroll
                for (int c = 0; c < MN; c++) acc[r][c] += a[r] * b[c];
        }
    }
#pragma unroll
    for (int r = 0; r < 8; r++) {
        int i = i0 + ty * 8 + r;
#pragma unroll
        for (int c = 0; c < MN; c++) {
            float v = acc[r][c];
            C[(size_t)i * ldc + head * BN + tx * MN + c] = v;
            if (WR16)
                C16[(size_t)i * ldc + head * BN + tx * MN + c] = __float2half(v);
        }
    }
}

// ---------------- score factors per head-node ----------------
__global__ void s_heads_kernel(const float* __restrict__ a_heads) {
    int gw = blockIdx.x * 8 + (threadIdx.x >> 5);
    int lane = threadIdx.x & 31;
    int i = gw >> 3, h = gw & 7;
    if (i >= N) return;
    const float* wh = g_Wh + (size_t)i * FIN + h * KH;
    const float* a  = a_heads + (size_t)h * 2 * KH;
    float v1 = wh[lane] * a[lane]      + wh[lane + 32] * a[lane + 32];
    float v2 = wh[lane] * a[KH + lane] + wh[lane + 32] * a[KH + lane + 32];
#pragma unroll
    for (int o = 16; o; o >>= 1) {
        v1 += __shfl_down_sync(0xffffffffu, v1, o);
        v2 += __shfl_down_sync(0xffffffffu, v2, o);
    }
    if (lane == 0) {
        g_E1[h * N + i] = __expf(v1);
        g_F1[h * N + i] = __expf(0.2f * v1);
        g_E2[h * N + i] = __expf(v2);
        g_F2[h * N + i] = __expf(0.2f * v2);
    }
}

__global__ void s_out_kernel(const float* __restrict__ a_out) {
    int gw = blockIdx.x * 8 + (threadIdx.x >> 5);
    int lane = threadIdx.x & 31;
    if (gw >= N) return;
    float v1 = 0.f, v2 = 0.f;
    if (lane < NCLS) {
        float w = g_Whout[(size_t)gw * NCLS + lane];
        v1 = w * a_out[lane];
        v2 = w * a_out[NCLS + lane];
    }
#pragma unroll
    for (int o = 16; o; o >>= 1) {
        v1 += __shfl_down_sync(0xffffffffu, v1, o);
        v2 += __shfl_down_sync(0xffffffffu, v2, o);
    }
    if (lane == 0) { g_s1o[gw] = v1; g_s2o[gw] = v2; }
}

// ============ layer-1 attention: HMMA (mma.sync) flash-style ============
// grid (64, 8), 256 thr. O[128,64] = rownorm( mask.exp(leaky(s1+s2)) ) @ Wh64
__global__ __launch_bounds__(256, 2) void attn_hmma_kernel(float* __restrict__ Out)
{
    __shared__ __align__(1024) __half sP[128 * 64];   // 16 KB swizzled
    __shared__ __align__(1024) __half sB[64 * 64];    //  8 KB swizzled
    __shared__ float sE2[64], sF2[64], sDen[128];

    int t = threadIdx.x, warp = t >> 5, lane = t & 31;
    int head = blockIdx.y, i0 = blockIdx.x * 128;
    uint32_t spb = smem_u32(sP), sbb = smem_u32(sB);

    if (t < 128) sDen[t] = 0.f;

    // ---- P-gen mapping: row = t&127, seg = t>>7 (32 cols each) ----
    int row = t & 127, seg = t >> 7;
    float E1r = g_E1[head * N + i0 + row];
    float F1r = g_F1[head * N + i0 + row];
    const uint32_t* bitp = g_bitsT + (size_t)seg * N + i0 + row;  // +2N per step
    uint32_t aofs[4];
#pragma unroll
    for (int c = 0; c < 4; c++)
        aofs[c] = SWZ128((uint32_t)(row * 128 + seg * 64 + c * 16));

    // ---- B-tile loader mapping: two 16B chunks per thread ----
    int jr0 = t >> 3, jc0 = t & 7;
    uint32_t bo0 = SWZ128((uint32_t)(jr0 * 128 + jc0 * 16));
    uint32_t bo1 = SWZ128((uint32_t)((jr0 + 32) * 128 + jc0 * 16));
    const __half* bsrc = g_Wh16 + head * 64 + jc0 * 8;

    // ---- mma fragment address bases ----
    int l16 = lane & 15, lhi = lane >> 4;
    uint32_t abase = (uint32_t)((warp * 16 + l16) * 128 + lhi * 16);
    uint32_t bbase = (uint32_t)(l16 * 128 + lhi * 16);

    float acc[8][4];
#pragma unroll
    for (int n = 0; n < 8; n++)
#pragma unroll
        for (int q = 0; q < 4; q++) acc[n][q] = 0.f;

    float lsum = 0.f;
    const float* e2g = g_E2 + head * N;
    const float* f2g = g_F2 + head * N;

    for (int step = 0; step < N / 64; step++) {
        int j0 = step * 64;
        uint32_t w = bitp[(size_t)step * 2 * N];
        uint4 bv0 = *(const uint4*)(bsrc + (size_t)(j0 + jr0) * FIN);
        uint4 bv1 = *(const uint4*)(bsrc + (size_t)(j0 + jr0 + 32) * FIN);
        float e2v = 0.f, f2v = 0.f;
        if (t < 64) { e2v = e2g[j0 + t]; f2v = f2g[j0 + t]; }

        __syncthreads();                       // prev mma done reading sP/sB
        *(uint4*)((char*)sB + bo0) = bv0;
        *(uint4*)((char*)sB + bo1) = bv1;
        if (t < 64) { sE2[t] = e2v; sF2[t] = f2v; }
        __syncthreads();                       // sE2/sF2 visible

        // ---- P tile: 32 elems per thread ----
        const float* pe2 = sE2 + seg * 32;
        const float* pf2 = sF2 + seg * 32;
#pragma unroll
        for (int c = 0; c < 4; c++) {
            float4 ea = *(const float4*)(pe2 + c * 8);
            float4 eb = *(const float4*)(pe2 + c * 8 + 4);
            float4 fa = *(const float4*)(pf2 + c * 8);
            float4 fb = *(const float4*)(pf2 + c * 8 + 4);
            float E2v[8] = {ea.x, ea.y, ea.z, ea.w, eb.x, eb.y, eb.z, eb.w};
            float F2v[8] = {fa.x, fa.y, fa.z, fa.w, fb.x, fb.y, fb.z, fb.w};
            float p[8];
#pragma unroll
            for (int k = 0; k < 8; k++) {
                float p0 = E1r * E2v[k];
                float p1 = F1r * F2v[k];
                float pv = (p0 > 1.0f) ? p0 : p1;    // leaky_relu sign select
                p[k] = ((w >> (c * 8 + k)) & 1u) ? pv : 0.f;
                lsum += p[k];
            }
            uint4 v;
            v.x = f2h2(p[0], p[1]);
            v.y = f2h2(p[2], p[3]);
            v.z = f2h2(p[4], p[5]);
            v.w = f2h2(p[6], p[7]);
            *(uint4*)((char*)sP + aofs[c]) = v;
        }
        __syncthreads();                       // sP/sB ready

        // ---- mma: warp computes rows [16w,16w+16) x 64 cols ----
#pragma unroll
        for (int kc = 0; kc < 4; kc++) {
            uint32_t a0, a1, a2, a3;
            ldsm4(a0, a1, a2, a3, spb + SWZ128(abase + kc * 32));
#pragma unroll
            for (int np = 0; np < 4; np++) {
                uint32_t b0, b1, b2, b3;
                ldsm4t(b0, b1, b2, b3, sbb + SWZ128(bbase + kc * 2048 + np * 32));
                mma16816(acc[2 * np],     a0, a1, a2, a3, b0, b1);
                mma16816(acc[2 * np + 1], a0, a1, a2, a3, b2, b3);
            }
        }
    }

    atomicAdd(&sDen[row], lsum);
    __syncthreads();

    int r0 = warp * 16 + (lane >> 2);
    float inv0 = 1.0f / sDen[r0];
    float inv1 = 1.0f / sDen[r0 + 8];
    float* o0 = Out + (size_t)(i0 + r0) * FIN + head * 64 + (lane & 3) * 2;
    float* o1 = o0 + 8 * FIN;
#pragma unroll
    for (int nt = 0; nt < 8; nt++) {
        *(float2*)(o0 + nt * 8) = make_float2(acc[nt][0] * inv0, acc[nt][1] * inv0);
        *(float2*)(o1 + nt * 8) = make_float2(acc[nt][2] * inv1, acc[nt][3] * inv1);
    }
}

// ---------------- layer-2 attention (fp32 SIMT, exact) ----------------
template<int KD, bool DO_ELU>
__global__ __launch_bounds__(256) void attn_kernel(
    const float* __restrict__ Wh, int ldw,
    const float* __restrict__ s1g, const float* __restrict__ s2g,
    float* __restrict__ Out, int ldo)
{
    constexpr int IT = 128, JT = 64, MN = KD / 16;
    extern __shared__ float smf[];
    float* sP   = smf;
    float* sB   = sP + IT * 65;
    float* sS2  = sB + JT * KD;
    float* sS1  = sS2 + JT;
    float* sDen = sS1 + IT;

    int t = threadIdx.x, head = blockIdx.y, i0 = blockIdx.x * IT;
    const float* s1 = s1g + (size_t)head * N;
    const float* s2 = s2g + (size_t)head * N;
    const float* WhH = Wh + head * KD;
    if (t < IT) { sS1[t] = s1[i0 + t]; sDen[t] = 0.f; }
    int tx = t & 15, ty = t >> 4;
    int prow = t & (IT - 1), jseg = t >> 7;
    float acc[8][MN];
#pragma unroll
    for (int r = 0; r < 8; r++)
#pragma unroll
        for (int c = 0; c < MN; c++) acc[r][c] = 0.f;

    for (int j0 = 0; j0 < N; j0 += JT) {
        __syncthreads();
#pragma unroll
        for (int i = 0; i < (JT * KD / 4) / 256; i++) {
            int l = t + i * 256, r = l / (KD / 4), c4 = l % (KD / 4);
            float4 v = *(const float4*)(WhH + (size_t)(j0 + r) * ldw + c4 * 4);
            *(float4*)(sB + r * KD + c4 * 4) = v;
        }
        if (t < JT) sS2[t] = s2[j0 + t];
        __syncthreads();
        {
            float s1v = sS1[prow];
            uint32_t w = g_bitsT[(size_t)((j0 >> 5) + jseg) * N + i0 + prow];
            float ls = 0.f;
            float* pr = sP + prow * 65 + jseg * 32;
            const float* s2p = sS2 + jseg * 32;
#pragma unroll
            for (int jj = 0; jj < 32; jj++) {
                float s = s1v + s2p[jj];
                float e = fmaxf(s, 0.2f * s);
                float p = ((w >> jj) & 1u) ? __expf(e) : 0.f;
                pr[jj] = p;
                ls += p;
            }
            atomicAdd(&sDen[prow], ls);
        }
        __syncthreads();
#pragma unroll 8
        for (int jj = 0; jj < JT; jj++) {
            float a[8];
#pragma unroll
            for (int r = 0; r < 8; r++) a[r] = sP[(ty * 8 + r) * 65 + jj];
            float b = sB[jj * KD + tx];
#pragma unroll
            for (int r = 0; r < 8; r++) acc[r][0] += a[r] * b;
        }
    }
    __syncthreads();
#pragma unroll
    for (int r = 0; r < 8; r++) {
        int i = i0 + ty * 8 + r;
        float inv = 1.0f / sDen[ty * 8 + r];
#pragma unroll
        for (int c = 0; c < MN; c++) {
            float v = acc[r][c] * inv;
            if (DO_ELU) v = (v > 0.f) ? v : expm1f(v);
            Out[(size_t)i * ldo + head * KD + tx * MN + c] = v;
        }
    }
}

// ---------------- launch ----------------
extern "C" void kernel_launch(void* const* d_in, const int* in_sizes, int n_in,
                              void* d_out, int out_size)
{
    const float* x = nullptr;
    const int* adj = nullptr;
    const float *W_heads = nullptr, *a_heads = nullptr, *W_out = nullptr, *a_out = nullptr;
    for (int i = 0; i < n_in; i++) {
        switch (in_sizes[i]) {
            case N * FIN:      x       = (const float*)d_in[i]; break;
            case 67108864:     adj     = (const int*)  d_in[i]; break;
            case H * FIN * KH: W_heads = (const float*)d_in[i]; break;
            case H * 2 * KH:   a_heads = (const float*)d_in[i]; break;
            case FIN * NCLS:   W_out   = (const float*)d_in[i]; break;
            case 2 * NCLS:     a_out   = (const float*)d_in[i]; break;
        }
    }

    float *whP, *hP, *whoP, *s1oP, *s2oP;
    __half* wh16P;
    cudaGetSymbolAddress((void**)&whP,  g_Wh);
    cudaGetSymbolAddress((void**)&wh16P, g_Wh16);
    cudaGetSymbolAddress((void**)&hP,   g_h);
    cudaGetSymbolAddress((void**)&whoP, g_Whout);
    cudaGetSymbolAddress((void**)&s1oP, g_s1o);
    cudaGetSymbolAddress((void**)&s2oP, g_s2o);

    const int SMEM16 = (128 * 65 + 64 * 16 + 64 + 128 + 128) * 4;
    cudaFuncSetAttribute(attn_kernel<16, true>,
                         cudaFuncAttributeMaxDynamicSharedMemorySize, SMEM16);

    pack_adj_kernel<<<4096, 256>>>(adj);
    gemm_kernel<64, 4, true><<<dim3(N / 128, H), 256>>>(x, FIN, W_heads, whP, FIN, wh16P);
    s_heads_kernel<<<(N * H) / 8, 256>>>(a_heads);
    attn_hmma_kernel<<<dim3(N / 128, H), 256>>>(hP);
    gemm_kernel<16, 1, false><<<dim3(N / 128, 1), 256>>>(hP, FIN, W_out, whoP, NCLS, nullptr);
    s_out_kernel<<<N / 8, 256>>>(a_out);
    attn_kernel<16, true><<<dim3(N / 128, 1), 256, SMEM16>>>(
        whoP, NCLS, s1oP, s2oP, (float*)d_out, NCLS);
}

// round 5
// speedup vs baseline: 3.5929x; 1.5196x over previous
#include <cuda_runtime.h>
#include <cuda_fp16.h>
#include <cstdint>
#include <math.h>

#define N    8192
#define NW   (N/32)
#define FIN  512
#define KH   64
#define H    8
#define NCLS 16

// ---------------- scratch ----------------
__device__ uint32_t g_bitsT[NW * N];       // transposed bitmap [word][row]
__device__ float    g_Wh   [N * FIN];      // layer-1 Wh fp32
__device__ __half   g_Wh16 [N * FIN];      // layer-1 Wh fp16
__device__ float    g_h    [N * FIN];      // head outputs
__device__ float    g_Whout[N * NCLS];
__device__ __half   g_Whout16[N * NCLS];
__device__ float    g_E1[H * N], g_F1[H * N];
__device__ __half   g_E2h[H * N], g_F2h[H * N];
__device__ float    g_E1o[N], g_F1o[N];
__device__ __half   g_E2oh[N], g_F2oh[N];

#define SWZ128(o) ((o) ^ (((o) >> 3) & 0x70))

// dyn smem layout (1KB-aligned base): sP 2x16KB | sB 2x8KB | sE2 2x64h | sF2 2x64h
#define OFF_SP   0
#define OFF_SB   32768
#define OFF_SE2  49152
#define OFF_SF2  49408
#define ATT_DSMEM (49664 + 1024)

__device__ __forceinline__ uint32_t smem_u32(const void* p) {
    return (uint32_t)__cvta_generic_to_shared(p);
}
__device__ __forceinline__ void ldsm4(uint32_t& r0, uint32_t& r1, uint32_t& r2,
                                      uint32_t& r3, uint32_t a) {
    asm volatile("ldmatrix.sync.aligned.m8n8.x4.shared.b16 {%0,%1,%2,%3}, [%4];"
                 : "=r"(r0), "=r"(r1), "=r"(r2), "=r"(r3) : "r"(a));
}
__device__ __forceinline__ void ldsm4t(uint32_t& r0, uint32_t& r1, uint32_t& r2,
                                       uint32_t& r3, uint32_t a) {
    asm volatile("ldmatrix.sync.aligned.m8n8.x4.trans.shared.b16 {%0,%1,%2,%3}, [%4];"
                 : "=r"(r0), "=r"(r1), "=r"(r2), "=r"(r3) : "r"(a));
}
__device__ __forceinline__ void mma16816(float* d, uint32_t a0, uint32_t a1,
                                         uint32_t a2, uint32_t a3,
                                         uint32_t b0, uint32_t b1) {
    asm volatile(
        "mma.sync.aligned.m16n8k16.row.col.f32.f16.f16.f32 "
        "{%0,%1,%2,%3}, {%4,%5,%6,%7}, {%8,%9}, {%0,%1,%2,%3};"
        : "+f"(d[0]), "+f"(d[1]), "+f"(d[2]), "+f"(d[3])
        : "r"(a0), "r"(a1), "r"(a2), "r"(a3), "r"(b0), "r"(b1));
}

// ---------------- adjacency bit-pack (transposed output) ----------------
__global__ void pack_adj_kernel(const int* __restrict__ adj) {
    int warps = gridDim.x * (blockDim.x >> 5);
    int gw    = blockIdx.x * (blockDim.x >> 5) + (threadIdx.x >> 5);
    int lane  = threadIdx.x & 31;
    const int total = N * NW;
    for (int w = gw; w < total; w += warps) {
        int v = adj[(size_t)w * 32 + lane];
        unsigned m = __ballot_sync(0xffffffffu, v > 0);
        if (lane == 0) g_bitsT[(size_t)(w & (NW - 1)) * N + (w >> 8)] = m;
    }
}

// ---------------- fp32 feature GEMM (optional fp16 mirror) ----------------
template<int BN, int MN, bool WR16>
__global__ __launch_bounds__(256) void gemm_kernel(
    const float* __restrict__ A, int lda, const float* __restrict__ B,
    float* __restrict__ C, int ldc, __half* __restrict__ C16)
{
    constexpr int BM = 128, BK = 32;
    __shared__ float sAT[BK][BM + 1];
    __shared__ float sB[BK][BN];
    int t = threadIdx.x, head = blockIdx.y, i0 = blockIdx.x * BM;
    const float* Bh = B + (size_t)head * FIN * BN;
    int tx = t & 15, ty = t >> 4;
    float acc[8][MN];
#pragma unroll
    for (int r = 0; r < 8; r++)
#pragma unroll
        for (int c = 0; c < MN; c++) acc[r][c] = 0.f;
    for (int k0 = 0; k0 < FIN; k0 += BK) {
        __syncthreads();
#pragma unroll
        for (int i = 0; i < (BM * BK) / 256; i++) {
            int l = t + i * 256, r = l >> 5, c = l & 31;
            sAT[c][r] = A[(size_t)(i0 + r) * lda + k0 + c];
        }
#pragma unroll
        for (int i = 0; i < (BK * BN) / 256; i++) {
            int l = t + i * 256, r = l / BN, c = l % BN;
            sB[r][c] = Bh[(size_t)(k0 + r) * BN + c];
        }
        __syncthreads();
#pragma unroll 8
        for (int kk = 0; kk < BK; kk++) {
            float a[8];
#pragma unroll
            for (int r = 0; r < 8; r++) a[r] = sAT[kk][ty * 8 + r];
            float b[MN];
#pragma unroll
            for (int c = 0; c < MN; c++) b[c] = sB[kk][tx * MN + c];
#pragma unroll
            for (int r = 0; r < 8; r++)
#pragma unroll
                for (int c = 0; c < MN; c++) acc[r][c] += a[r] * b[c];
        }
    }
#pragma unroll
    for (int r = 0; r < 8; r++) {
        int i = i0 + ty * 8 + r;
#pragma unroll
        for (int c = 0; c < MN; c++) {
            float v = acc[r][c];
            C[(size_t)i * ldc + head * BN + tx * MN + c] = v;
            if (WR16)
                C16[(size_t)i * ldc + head * BN + tx * MN + c] = __float2half(v);
        }
    }
}

// ---------------- score factors ----------------
__global__ void s_heads_kernel(const float* __restrict__ a_heads) {
    int gw = blockIdx.x * 8 + (threadIdx.x >> 5);
    int lane = threadIdx.x & 31;
    int i = gw >> 3, h = gw & 7;
    if (i >= N) return;
    const float* wh = g_Wh + (size_t)i * FIN + h * KH;
    const float* a  = a_heads + (size_t)h * 2 * KH;
    float v1 = wh[lane] * a[lane]      + wh[lane + 32] * a[lane + 32];
    float v2 = wh[lane] * a[KH + lane] + wh[lane + 32] * a[KH + lane + 32];
#pragma unroll
    for (int o = 16; o; o >>= 1) {
        v1 += __shfl_down_sync(0xffffffffu, v1, o);
        v2 += __shfl_down_sync(0xffffffffu, v2, o);
    }
    if (lane == 0) {
        g_E1[h * N + i] = __expf(v1);
        g_F1[h * N + i] = __expf(0.2f * v1);
        g_E2h[h * N + i] = __float2half(__expf(v2));
        g_F2h[h * N + i] = __float2half(__expf(0.2f * v2));
    }
}

__global__ void s_out_kernel(const float* __restrict__ a_out) {
    int gw = blockIdx.x * 8 + (threadIdx.x >> 5);
    int lane = threadIdx.x & 31;
    if (gw >= N) return;
    float v1 = 0.f, v2 = 0.f;
    if (lane < NCLS) {
        float w = g_Whout[(size_t)gw * NCLS + lane];
        v1 = w * a_out[lane];
        v2 = w * a_out[NCLS + lane];
    }
#pragma unroll
    for (int o = 16; o; o >>= 1) {
        v1 += __shfl_down_sync(0xffffffffu, v1, o);
        v2 += __shfl_down_sync(0xffffffffu, v2, o);
    }
    if (lane == 0) {
        g_E1o[gw] = __expf(v1);
        g_F1o[gw] = __expf(0.2f * v1);
        g_E2oh[gw] = __float2half(__expf(v2));
        g_F2oh[gw] = __float2half(__expf(0.2f * v2));
    }
}

// ============ fused masked-softmax attention, HMMA, templated cols ============
// O[128, NC] = rownorm( mask .* max(E1E2, F1F2) ) @ B[:, NC]   (+optional ELU)
template<int NC, bool DO_ELU>
__global__ __launch_bounds__(256, 2) void attn_hmma(
    const float* __restrict__ E1g, const float* __restrict__ F1g,
    const __half* __restrict__ E2g, const __half* __restrict__ F2g,
    const __half* __restrict__ Bg, int ldb,
    float* __restrict__ Out, int ldo)
{
    extern __shared__ char rawsm[];
    uint32_t rawu = smem_u32(rawsm);
    uint32_t base = (rawu + 1023) & ~1023u;
    char* sm = rawsm + (base - rawu);
    __half* sE2 = (__half*)(sm + OFF_SE2);     // [2][64]
    __half* sF2 = (__half*)(sm + OFF_SF2);     // [2][64]
    uint32_t spb = base + OFF_SP, sbb = base + OFF_SB;

    int t = threadIdx.x, warp = t >> 5, lane = t & 31;
    int head = blockIdx.y, i0 = blockIdx.x * 128;
    int bcol = (NC == 64) ? head * 64 : 0;

    // ---- P-gen mapping ----
    int row = t & 127, seg = t >> 7;
    __half2 e1h2 = __float2half2_rn(E1g[head * N + i0 + row]);
    __half2 f1h2 = __float2half2_rn(F1g[head * N + i0 + row]);
    const uint32_t* bitp = g_bitsT + (size_t)seg * N + i0 + row;
    uint32_t aofs[4];
#pragma unroll
    for (int c = 0; c < 4; c++)
        aofs[c] = SWZ128((uint32_t)(row * 128 + seg * 64 + c * 16));

    // ---- B loader mapping ----
    constexpr int NCH = 64 * NC / 8;            // 16B chunks per tile
    constexpr int CPT = (NCH + 255) / 256;      // chunks per thread
    const __half* bsrc[CPT];
    uint32_t bofs[CPT];
    bool bval[CPT];
#pragma unroll
    for (int i = 0; i < CPT; i++) {
        int ch = t + i * 256;
        bval[i] = ch < NCH;
        int br = ch / (NC / 8), bc = ch % (NC / 8);
        bsrc[i] = Bg + (size_t)br * ldb + bcol + bc * 8;
        bofs[i] = SWZ128((uint32_t)(br * 128 + bc * 16));
    }

    // ---- mma fragment bases ----
    int l16 = lane & 15, lhi = lane >> 4;
    uint32_t abase = (uint32_t)((warp * 16 + l16) * 128 + lhi * 16);
    uint32_t bbase = (uint32_t)(l16 * 128 + lhi * 16);
    uint32_t ones0 = (lane < 4) ? 0x3C003C00u : 0u;   // B ones-col fragment

    float acc[NC / 8][4];
#pragma unroll
    for (int n = 0; n < NC / 8; n++)
#pragma unroll
        for (int q = 0; q < 4; q++) acc[n][q] = 0.f;
    float accd[4] = {0.f, 0.f, 0.f, 0.f};

    const __half* e2base = E2g + head * N;
    const __half* f2base = F2g + head * N;

    for (int step = 0; step < N / 64; step++) {
        int b = step & 1;
        int j0 = step * 64;
        uint32_t w = bitp[(size_t)step * 2 * N];
        uint4 bv[CPT];
#pragma unroll
        for (int i = 0; i < CPT; i++)
            if (bval[i]) bv[i] = *(const uint4*)(bsrc[i] + (size_t)j0 * ldb);
        uint32_t efw = 0;
        if (t < 32)      efw = *((const uint32_t*)(e2base + j0) + t);
        else if (t < 64) efw = *((const uint32_t*)(f2base + j0) + (t - 32));

        // stores into buffer b (last touched 2 steps ago; barriers in between)
#pragma unroll
        for (int i = 0; i < CPT; i++)
            if (bval[i]) *(uint4*)(sm + OFF_SB + b * 8192 + bofs[i]) = bv[i];
        if (t < 32)      ((uint32_t*)(sE2 + b * 64))[t] = efw;
        else if (t < 64) ((uint32_t*)(sF2 + b * 64))[t - 32] = efw;
        __syncthreads();

        // ---- P tile: 32 elems/thread, packed half2 ----
        const uint4* pe = (const uint4*)(sE2 + b * 64 + seg * 32);
        const uint4* pf = (const uint4*)(sF2 + b * 64 + seg * 32);
#pragma unroll
        for (int c = 0; c < 4; c++) {
            uint4 e4 = pe[c];
            uint4 f4 = pf[c];
            uint32_t bb = w >> (c * 8);
            uint32_t vp[4];
#pragma unroll
            for (int k = 0; k < 4; k++) {
                uint32_t eu = (&e4.x)[k], fu = (&f4.x)[k];
                __half2 pex = __hmul2(e1h2, *(__half2*)&eu);
                __half2 pfx = __hmul2(f1h2, *(__half2*)&fu);
                __half2 pm  = __hmax2(pex, pfx);
                uint32_t bk = bb >> (2 * k);
                uint32_t m = (bk & 1u) * 0xFFFFu + (bk & 2u) * 0x7FFF8000u;
                vp[k] = (*(uint32_t*)&pm) & m;
            }
            uint4 vv;
            vv.x = vp[0]; vv.y = vp[1]; vv.z = vp[2]; vv.w = vp[3];
            *(uint4*)(sm + OFF_SP + b * 16384 + aofs[c]) = vv;
        }
        __syncthreads();

        // ---- mma phase ----
        uint32_t pab = spb + b * 16384;
        uint32_t pbb = sbb + b * 8192;
#pragma unroll
        for (int kc = 0; kc < 4; kc++) {
            uint32_t a0, a1, a2, a3;
            ldsm4(a0, a1, a2, a3, pab + SWZ128(abase + kc * 32));
            mma16816(accd, a0, a1, a2, a3, ones0, ones0);   // denominator
#pragma unroll
            for (int np = 0; np < NC / 16; np++) {
                uint32_t b0, b1, b2, b3;
                ldsm4t(b0, b1, b2, b3, pbb + SWZ128(bbase + kc * 2048 + np * 32));
                mma16816(acc[2 * np],     a0, a1, a2, a3, b0, b1);
                mma16816(acc[2 * np + 1], a0, a1, a2, a3, b2, b3);
            }
        }
    }

    // ---- epilogue: normalize (den from ones-col, lane&3==0 holds col 0) ----
    float den0 = __shfl_sync(0xffffffffu, accd[0], lane & 0x1C);
    float den1 = __shfl_sync(0xffffffffu, accd[2], lane & 0x1C);
    float inv0 = 1.0f / den0, inv1 = 1.0f / den1;
    int r0 = warp * 16 + (lane >> 2);
    float* o0 = Out + (size_t)(i0 + r0) * ldo + bcol + (lane & 3) * 2;
    float* o1 = o0 + 8 * ldo;
#pragma unroll
    for (int nt = 0; nt < NC / 8; nt++) {
        float2 v0 = make_float2(acc[nt][0] * inv0, acc[nt][1] * inv0);
        float2 v1 = make_float2(acc[nt][2] * inv1, acc[nt][3] * inv1);
        if (DO_ELU) {
            v0.x = (v0.x > 0.f) ? v0.x : expm1f(v0.x);
            v0.y = (v0.y > 0.f) ? v0.y : expm1f(v0.y);
            v1.x = (v1.x > 0.f) ? v1.x : expm1f(v1.x);
            v1.y = (v1.y > 0.f) ? v1.y : expm1f(v1.y);
        }
        *(float2*)(o0 + nt * 8) = v0;
        *(float2*)(o1 + nt * 8) = v1;
    }
}

// ---------------- launch ----------------
extern "C" void kernel_launch(void* const* d_in, const int* in_sizes, int n_in,
                              void* d_out, int out_size)
{
    const float* x = nullptr;
    const int* adj = nullptr;
    const float *W_heads = nullptr, *a_heads = nullptr, *W_out = nullptr, *a_out = nullptr;
    for (int i = 0; i < n_in; i++) {
        switch (in_sizes[i]) {
            case N * FIN:      x       = (const float*)d_in[i]; break;
            case 67108864:     adj     = (const int*)  d_in[i]; break;
            case H * FIN * KH: W_heads = (const float*)d_in[i]; break;
            case H * 2 * KH:   a_heads = (const float*)d_in[i]; break;
            case FIN * NCLS:   W_out   = (const float*)d_in[i]; break;
            case 2 * NCLS:     a_out   = (const float*)d_in[i]; break;
        }
    }

    float *whP, *hP, *whoP, *e1P, *f1P, *e1oP, *f1oP;
    __half *wh16P, *who16P, *e2hP, *f2hP, *e2ohP, *f2ohP;
    cudaGetSymbolAddress((void**)&whP,   g_Wh);
    cudaGetSymbolAddress((void**)&wh16P, g_Wh16);
    cudaGetSymbolAddress((void**)&hP,    g_h);
    cudaGetSymbolAddress((void**)&whoP,  g_Whout);
    cudaGetSymbolAddress((void**)&who16P, g_Whout16);
    cudaGetSymbolAddress((void**)&e1P,  g_E1);
    cudaGetSymbolAddress((void**)&f1P,  g_F1);
    cudaGetSymbolAddress((void**)&e2hP, g_E2h);
    cudaGetSymbolAddress((void**)&f2hP, g_F2h);
    cudaGetSymbolAddress((void**)&e1oP, g_E1o);
    cudaGetSymbolAddress((void**)&f1oP, g_F1o);
    cudaGetSymbolAddress((void**)&e2ohP, g_E2oh);
    cudaGetSymbolAddress((void**)&f2ohP, g_F2oh);

    cudaFuncSetAttribute(attn_hmma<64, false>,
                         cudaFuncAttributeMaxDynamicSharedMemorySize, ATT_DSMEM);
    cudaFuncSetAttribute(attn_hmma<16, true>,
                         cudaFuncAttributeMaxDynamicSharedMemorySize, ATT_DSMEM);

    pack_adj_kernel<<<4096, 256>>>(adj);
    gemm_kernel<64, 4, true><<<dim3(N / 128, H), 256>>>(x, FIN, W_heads, whP, FIN, wh16P);
    s_heads_kernel<<<(N * H) / 8, 256>>>(a_heads);
    attn_hmma<64, false><<<dim3(N / 128, H), 256, ATT_DSMEM>>>(
        e1P, f1P, e2hP, f2hP, wh16P, FIN, hP, FIN);
    gemm_kernel<16, 1, true><<<dim3(N / 128, 1), 256>>>(hP, FIN, W_out, whoP, NCLS, who16P);
    s_out_kernel<<<N / 8, 256>>>(a_out);
    attn_hmma<16, true><<<dim3(N / 128, 1), 256, ATT_DSMEM>>>(
        e1oP, f1oP, e2ohP, f2ohP, who16P, NCLS, (float*)d_out, NCLS);
}

// round 6
// speedup vs baseline: 4.4894x; 1.2495x over previous
#include <cuda_runtime.h>
#include <cuda_fp16.h>
#include <cstdint>
#include <math.h>

#define N    8192
#define NW   (N/32)
#define FIN  512
#define KH   64
#define H    8
#define NCLS 16

// ---------------- scratch ----------------
__device__ uint32_t g_bitsT[NW * N];       // transposed bitmap [word][row]
__device__ float    g_Wh   [N * FIN];      // layer-1 Wh fp32
__device__ __half   g_Wh16 [N * FIN];      // layer-1 Wh fp16
__device__ float    g_h    [N * FIN];      // head outputs
__device__ float    g_Whout[N * NCLS];
__device__ __half   g_Whout16[N * NCLS];
__device__ float    g_E1[H * N], g_F1[H * N];
__device__ __half   g_E2h[H * N], g_F2h[H * N];
__device__ float    g_E1o[N], g_F1o[N];
__device__ __half   g_E2oh[N], g_F2oh[N];
__device__ float    g_numO[N * NCLS];      // split-j partial numerators
__device__ float    g_denO[N];             // split-j partial denominators

#define SWZ128(o) ((o) ^ (((o) >> 3) & 0x70))

__device__ __forceinline__ uint32_t smem_u32(const void* p) {
    return (uint32_t)__cvta_generic_to_shared(p);
}
__device__ __forceinline__ void ldsm4(uint32_t& r0, uint32_t& r1, uint32_t& r2,
                                      uint32_t& r3, uint32_t a) {
    asm volatile("ldmatrix.sync.aligned.m8n8.x4.shared.b16 {%0,%1,%2,%3}, [%4];"
                 : "=r"(r0), "=r"(r1), "=r"(r2), "=r"(r3) : "r"(a));
}
__device__ __forceinline__ void ldsm4t(uint32_t& r0, uint32_t& r1, uint32_t& r2,
                                       uint32_t& r3, uint32_t a) {
    asm volatile("ldmatrix.sync.aligned.m8n8.x4.trans.shared.b16 {%0,%1,%2,%3}, [%4];"
                 : "=r"(r0), "=r"(r1), "=r"(r2), "=r"(r3) : "r"(a));
}
__device__ __forceinline__ void mma16816(float* d, uint32_t a0, uint32_t a1,
                                         uint32_t a2, uint32_t a3,
                                         uint32_t b0, uint32_t b1) {
    asm volatile(
        "mma.sync.aligned.m16n8k16.row.col.f32.f16.f16.f32 "
        "{%0,%1,%2,%3}, {%4,%5,%6,%7}, {%8,%9}, {%0,%1,%2,%3};"
        : "+f"(d[0]), "+f"(d[1]), "+f"(d[2]), "+f"(d[3])
        : "r"(a0), "r"(a1), "r"(a2), "r"(a3), "r"(b0), "r"(b1));
}

// ---------------- adjacency bit-pack (transposed output) ----------------
__global__ void pack_adj_kernel(const int* __restrict__ adj) {
    int warps = gridDim.x * (blockDim.x >> 5);
    int gw    = blockIdx.x * (blockDim.x >> 5) + (threadIdx.x >> 5);
    int lane  = threadIdx.x & 31;
    const int total = N * NW;
    for (int w = gw; w < total; w += warps) {
        int v = adj[(size_t)w * 32 + lane];
        unsigned m = __ballot_sync(0xffffffffu, v > 0);
        if (lane == 0) g_bitsT[(size_t)(w & (NW - 1)) * N + (w >> 8)] = m;
    }
}

// ---------------- fp32 feature GEMM (optional fp16 mirror) ----------------
template<int BN, int MN, bool WR16>
__global__ __launch_bounds__(256) void gemm_kernel(
    const float* __restrict__ A, int lda, const float* __restrict__ B,
    float* __restrict__ C, int ldc, __half* __restrict__ C16)
{
    constexpr int BM = 128, BK = 32;
    __shared__ float sAT[BK][BM + 1];
    __shared__ float sB[BK][BN];
    int t = threadIdx.x, head = blockIdx.y, i0 = blockIdx.x * BM;
    const float* Bh = B + (size_t)head * FIN * BN;
    int tx = t & 15, ty = t >> 4;
    float acc[8][MN];
#pragma unroll
    for (int r = 0; r < 8; r++)
#pragma unroll
        for (int c = 0; c < MN; c++) acc[r][c] = 0.f;
    for (int k0 = 0; k0 < FIN; k0 += BK) {
        __syncthreads();
#pragma unroll
        for (int i = 0; i < (BM * BK) / 256; i++) {
            int l = t + i * 256, r = l >> 5, c = l & 31;
            sAT[c][r] = A[(size_t)(i0 + r) * lda + k0 + c];
        }
#pragma unroll
        for (int i = 0; i < (BK * BN) / 256; i++) {
            int l = t + i * 256, r = l / BN, c = l % BN;
            sB[r][c] = Bh[(size_t)(k0 + r) * BN + c];
        }
        __syncthreads();
#pragma unroll 8
        for (int kk = 0; kk < BK; kk++) {
            float a[8];
#pragma unroll
            for (int r = 0; r < 8; r++) a[r] = sAT[kk][ty * 8 + r];
            float b[MN];
#pragma unroll
            for (int c = 0; c < MN; c++) b[c] = sB[kk][tx * MN + c];
#pragma unroll
            for (int r = 0; r < 8; r++)
#pragma unroll
                for (int c = 0; c < MN; c++) acc[r][c] += a[r] * b[c];
        }
    }
#pragma unroll
    for (int r = 0; r < 8; r++) {
        int i = i0 + ty * 8 + r;
#pragma unroll
        for (int c = 0; c < MN; c++) {
            float v = acc[r][c];
            C[(size_t)i * ldc + head * BN + tx * MN + c] = v;
            if (WR16)
                C16[(size_t)i * ldc + head * BN + tx * MN + c] = __float2half(v);
        }
    }
}

// ---------------- score factors ----------------
__global__ void s_heads_kernel(const float* __restrict__ a_heads) {
    int gw = blockIdx.x * 8 + (threadIdx.x >> 5);
    int lane = threadIdx.x & 31;
    int i = gw >> 3, h = gw & 7;
    if (i >= N) return;
    const float* wh = g_Wh + (size_t)i * FIN + h * KH;
    const float* a  = a_heads + (size_t)h * 2 * KH;
    float v1 = wh[lane] * a[lane]      + wh[lane + 32] * a[lane + 32];
    float v2 = wh[lane] * a[KH + lane] + wh[lane + 32] * a[KH + lane + 32];
#pragma unroll
    for (int o = 16; o; o >>= 1) {
        v1 += __shfl_down_sync(0xffffffffu, v1, o);
        v2 += __shfl_down_sync(0xffffffffu, v2, o);
    }
    if (lane == 0) {
        g_E1[h * N + i] = __expf(v1);
        g_F1[h * N + i] = __expf(0.2f * v1);
        g_E2h[h * N + i] = __float2half(__expf(v2));
        g_F2h[h * N + i] = __float2half(__expf(0.2f * v2));
    }
}

__global__ void s_out_kernel(const float* __restrict__ a_out) {
    int gw = blockIdx.x * 8 + (threadIdx.x >> 5);
    int lane = threadIdx.x & 31;
    if (gw >= N) return;
    float v1 = 0.f, v2 = 0.f;
    if (lane < NCLS) {
        float w = g_Whout[(size_t)gw * NCLS + lane];
        v1 = w * a_out[lane];
        v2 = w * a_out[NCLS + lane];
    }
#pragma unroll
    for (int o = 16; o; o >>= 1) {
        v1 += __shfl_down_sync(0xffffffffu, v1, o);
        v2 += __shfl_down_sync(0xffffffffu, v2, o);
    }
    if (lane == 0) {
        g_E1o[gw] = __expf(v1);
        g_F1o[gw] = __expf(0.2f * v1);
        g_E2oh[gw] = __float2half(__expf(v2));
        g_F2oh[gw] = __float2half(__expf(0.2f * v2));
    }
}

// ---------------- zero split-j accumulators ----------------
__global__ void zero_acc_kernel() {
    int i = blockIdx.x * 256 + threadIdx.x;
    if (i < N * NCLS) g_numO[i] = 0.f;
    if (i < N)        g_denO[i] = 0.f;
}

// ---------------- finalize: out = elu(num/den) ----------------
__global__ void finalize_kernel(float* __restrict__ Out) {
    int i = blockIdx.x * 256 + threadIdx.x;
    if (i >= N * NCLS) return;
    float v = g_numO[i] / g_denO[i >> 4];
    Out[i] = (v > 0.f) ? v : expm1f(v);
}

// ============ fused masked-softmax attention, HMMA, warp-private P ============
// O[128, NC] = rownorm( mask .* max(E1E2, F1F2) ) @ B[:, NC]
// SPLIT: partial sums over a j-range via atomicAdd into g_numO/g_denO.
template<int NC, bool SPLIT>
__global__ __launch_bounds__(256, 2) void attn_hmma(
    const float* __restrict__ E1g, const float* __restrict__ F1g,
    const __half* __restrict__ E2g, const __half* __restrict__ F2g,
    const __half* __restrict__ Bg, int ldb,
    float* __restrict__ Out, int ldo)
{
    __shared__ __align__(1024) __half sP[128 * 64];      // 16 KB, warp-private stripes
    __shared__ __align__(1024) __half sBs[2][64 * 64];   // 16 KB double-buffered
    __shared__ __half sE2[2][64], sF2[2][64];

    int t = threadIdx.x, warp = t >> 5, lane = t & 31;
    int head  = SPLIT ? 0 : blockIdx.y;
    int jbase = SPLIT ? blockIdx.y * (N / 8) : 0;
    constexpr int NSTEP_T = SPLIT ? (N / 8) / 64 : N / 64;
    int i0 = blockIdx.x * 128;
    int bcol = (NC == 64) ? head * 64 : 0;
    uint32_t spb = smem_u32(sP), sbb = smem_u32(sBs);

    // ---- per-warp P mapping: warp owns rows [16w, 16w+16) ----
    int l16 = lane & 15, seg = lane >> 4;
    int row = warp * 16 + l16;
    __half2 e1h2 = __float2half2_rn(E1g[head * N + i0 + row]);
    __half2 f1h2 = __float2half2_rn(F1g[head * N + i0 + row]);
    const uint32_t* bitp = g_bitsT + (size_t)((jbase >> 5) + seg) * N + i0 + row;
    uint32_t aofs[4];
#pragma unroll
    for (int c = 0; c < 4; c++)
        aofs[c] = SWZ128((uint32_t)(row * 128 + seg * 64 + c * 16));

    // ---- B loader mapping ----
    constexpr int NCH = 64 * NC / 8;            // 16B chunks per tile
    constexpr int CPT = (NCH + 255) / 256;      // chunks per thread
    const __half* bsrc[CPT];
    uint32_t bofs[CPT];
    bool bval[CPT];
#pragma unroll
    for (int i = 0; i < CPT; i++) {
        int ch = t + i * 256;
        bval[i] = ch < NCH;
        int br = ch / (NC / 8), bc = ch % (NC / 8);
        bsrc[i] = Bg + (size_t)br * ldb + bcol + bc * 8;
        bofs[i] = SWZ128((uint32_t)(br * 128 + bc * 16));
    }

    // ---- mma fragment bases ----
    int lhi = lane >> 4;
    uint32_t abase = (uint32_t)((warp * 16 + l16) * 128 + lhi * 16);
    uint32_t bbase = (uint32_t)(l16 * 128 + lhi * 16);
    uint32_t ones0 = (lane < 4) ? 0x3C003C00u : 0u;

    float acc[NC / 8][4];
#pragma unroll
    for (int n = 0; n < NC / 8; n++)
#pragma unroll
        for (int q = 0; q < 4; q++) acc[n][q] = 0.f;
    float accd[4] = {0.f, 0.f, 0.f, 0.f};

    const __half* e2base = E2g + head * N + jbase;
    const __half* f2base = F2g + head * N + jbase;

    // ---- prologue: prefetch step 0 ----
    uint32_t wreg[2], efreg[2];
    uint4 bvreg[2][CPT];
    wreg[0] = bitp[0];
#pragma unroll
    for (int i = 0; i < CPT; i++)
        if (bval[i]) bvreg[0][i] = *(const uint4*)(bsrc[i] + (size_t)jbase * ldb);
    efreg[0] = 0;
    if (t < 32)      efreg[0] = *((const uint32_t*)e2base + t);
    else if (t < 64) efreg[0] = *((const uint32_t*)f2base + (t - 32));

#pragma unroll 2
    for (int step = 0; step < NSTEP_T; step++) {
        int b = step & 1;
        // ---- stage current step's regs into smem buffer b ----
#pragma unroll
        for (int i = 0; i < CPT; i++)
            if (bval[i]) *(uint4*)((char*)sBs + b * 8192 + bofs[i]) = bvreg[b][i];
        if (t < 32)      ((uint32_t*)(sE2[b]))[t] = efreg[b];
        else if (t < 64) ((uint32_t*)(sF2[b]))[t - 32] = efreg[b];
        __syncthreads();

        // ---- prefetch step+1 ----
        if (step + 1 < NSTEP_T) {
            int nb = b ^ 1;
            int j1 = (step + 1) * 64;
            wreg[nb] = bitp[(size_t)(step + 1) * 2 * N];
#pragma unroll
            for (int i = 0; i < CPT; i++)
                if (bval[i]) bvreg[nb][i] =
                    *(const uint4*)(bsrc[i] + (size_t)(jbase + j1) * ldb);
            if (t < 32)      efreg[nb] = *((const uint32_t*)(e2base + j1) + t);
            else if (t < 64) efreg[nb] = *((const uint32_t*)(f2base + j1) + (t - 32));
        }

        // ---- P tile: warp-private 16 rows; 32 elems/thread, packed half2 ----
        {
            uint32_t w = wreg[b];
            const uint4* pe = (const uint4*)(sE2[b] + seg * 32);
            const uint4* pf = (const uint4*)(sF2[b] + seg * 32);
#pragma unroll
            for (int c = 0; c < 4; c++) {
                uint4 e4 = pe[c];
                uint4 f4 = pf[c];
                uint32_t bb = w >> (c * 8);
                uint32_t vp[4];
#pragma unroll
                for (int k = 0; k < 4; k++) {
                    uint32_t eu = (&e4.x)[k], fu = (&f4.x)[k];
                    __half2 pex = __hmul2(e1h2, *(__half2*)&eu);
                    __half2 pfx = __hmul2(f1h2, *(__half2*)&fu);
                    __half2 pm  = __hmax2(pex, pfx);
                    uint32_t bk = bb >> (2 * k);
                    uint32_t m = (bk & 1u) * 0xFFFFu + (bk & 2u) * 0x7FFF8000u;
                    vp[k] = (*(uint32_t*)&pm) & m;
                }
                uint4 vv;
                vv.x = vp[0]; vv.y = vp[1]; vv.z = vp[2]; vv.w = vp[3];
                *(uint4*)((char*)sP + aofs[c]) = vv;
            }
        }
        __syncwarp();

        // ---- mma phase (A from warp-private sP stripe) ----
        uint32_t pbb = sbb + b * 8192;
#pragma unroll
        for (int kc = 0; kc < 4; kc++) {
            uint32_t a0, a1, a2, a3;
            ldsm4(a0, a1, a2, a3, spb + SWZ128(abase + kc * 32));
            mma16816(accd, a0, a1, a2, a3, ones0, ones0);   // denominator
#pragma unroll
            for (int np = 0; np < NC / 16; np++) {
                uint32_t b0, b1, b2, b3;
                ldsm4t(b0, b1, b2, b3, pbb + SWZ128(bbase + kc * 2048 + np * 32));
                mma16816(acc[2 * np],     a0, a1, a2, a3, b0, b1);
                mma16816(acc[2 * np + 1], a0, a1, a2, a3, b2, b3);
            }
        }
        __syncwarp();   // all lanes done reading sP before next-step writes
    }

    int r0 = warp * 16 + (lane >> 2);
    if constexpr (SPLIT) {
        // partial sums -> global atomics
        if ((lane & 3) == 0) {
            atomicAdd(&g_denO[i0 + r0],     accd[0]);
            atomicAdd(&g_denO[i0 + r0 + 8], accd[2]);
        }
        int c0 = (lane & 3) * 2;
#pragma unroll
        for (int nt = 0; nt < NC / 8; nt++) {
            atomicAdd(&g_numO[(i0 + r0) * NCLS + nt * 8 + c0],     acc[nt][0]);
            atomicAdd(&g_numO[(i0 + r0) * NCLS + nt * 8 + c0 + 1], acc[nt][1]);
            atomicAdd(&g_numO[(i0 + r0 + 8) * NCLS + nt * 8 + c0],     acc[nt][2]);
            atomicAdd(&g_numO[(i0 + r0 + 8) * NCLS + nt * 8 + c0 + 1], acc[nt][3]);
        }
    } else {
        float den0 = __shfl_sync(0xffffffffu, accd[0], lane & 0x1C);
        float den1 = __shfl_sync(0xffffffffu, accd[2], lane & 0x1C);
        float inv0 = 1.0f / den0, inv1 = 1.0f / den1;
        float* o0 = Out + (size_t)(i0 + r0) * ldo + bcol + (lane & 3) * 2;
        float* o1 = o0 + 8 * ldo;
#pragma unroll
        for (int nt = 0; nt < NC / 8; nt++) {
            *(float2*)(o0 + nt * 8) = make_float2(acc[nt][0] * inv0, acc[nt][1] * inv0);
            *(float2*)(o1 + nt * 8) = make_float2(acc[nt][2] * inv1, acc[nt][3] * inv1);
        }
    }
}

// ---------------- launch ----------------
extern "C" void kernel_launch(void* const* d_in, const int* in_sizes, int n_in,
                              void* d_out, int out_size)
{
    const float* x = nullptr;
    const int* adj = nullptr;
    const float *W_heads = nullptr, *a_heads = nullptr, *W_out = nullptr, *a_out = nullptr;
    for (int i = 0; i < n_in; i++) {
        switch (in_sizes[i]) {
            case N * FIN:      x       = (const float*)d_in[i]; break;
            case 67108864:     adj     = (const int*)  d_in[i]; break;
            case H * FIN * KH: W_heads = (const float*)d_in[i]; break;
            case H * 2 * KH:   a_heads = (const float*)d_in[i]; break;
            case FIN * NCLS:   W_out   = (const float*)d_in[i]; break;
            case 2 * NCLS:     a_out   = (const float*)d_in[i]; break;
        }
    }

    float *whP, *hP, *whoP, *e1P, *f1P, *e1oP, *f1oP;
    __half *wh16P, *who16P, *e2hP, *f2hP, *e2ohP, *f2ohP;
    cudaGetSymbolAddress((void**)&whP,   g_Wh);
    cudaGetSymbolAddress((void**)&wh16P, g_Wh16);
    cudaGetSymbolAddress((void**)&hP,    g_h);
    cudaGetSymbolAddress((void**)&whoP,  g_Whout);
    cudaGetSymbolAddress((void**)&who16P, g_Whout16);
    cudaGetSymbolAddress((void**)&e1P,  g_E1);
    cudaGetSymbolAddress((void**)&f1P,  g_F1);
    cudaGetSymbolAddress((void**)&e2hP, g_E2h);
    cudaGetSymbolAddress((void**)&f2hP, g_F2h);
    cudaGetSymbolAddress((void**)&e1oP, g_E1o);
    cudaGetSymbolAddress((void**)&f1oP, g_F1o);
    cudaGetSymbolAddress((void**)&e2ohP, g_E2oh);
    cudaGetSymbolAddress((void**)&f2ohP, g_F2oh);

    pack_adj_kernel<<<4096, 256>>>(adj);
    gemm_kernel<64, 4, true><<<dim3(N / 128, H), 256>>>(x, FIN, W_heads, whP, FIN, wh16P);
    s_heads_kernel<<<(N * H) / 8, 256>>>(a_heads);
    zero_acc_kernel<<<(N * NCLS + 255) / 256, 256>>>();
    attn_hmma<64, false><<<dim3(N / 128, H), 256>>>(
        e1P, f1P, e2hP, f2hP, wh16P, FIN, hP, FIN);
    gemm_kernel<16, 1, true><<<dim3(N / 128, 1), 256>>>(hP, FIN, W_out, whoP, NCLS, who16P);
    s_out_kernel<<<N / 8, 256>>>(a_out);
    attn_hmma<16, true><<<dim3(N / 128, 8), 256>>>(
        e1oP, f1oP, e2ohP, f2ohP, who16P, NCLS, nullptr, NCLS);
    finalize_kernel<<<(N * NCLS + 255) / 256, 256>>>((float*)d_out);
}

// round 8
// speedup vs baseline: 4.6156x; 1.0281x over previous
#include <cuda_runtime.h>
#include <cuda_fp16.h>
#include <cstdint>
#include <math.h>

#define N    8192
#define NW   (N/32)
#define FIN  512
#define KH   64
#define H    8
#define NCLS 16

__device__ uint32_t g_bitsT[NW * N];
__device__ float    g_Wh   [N * FIN];
__device__ __half   g_Wh16 [N * FIN];
__device__ float    g_h    [N * FIN];
__device__ float    g_Whout[N * NCLS];
__device__ __half   g_Whout16[N * NCLS];
__device__ float    g_E1[H * N], g_F1[H * N];
__device__ __half   g_E2h[H * N], g_F2h[H * N];
__device__ float    g_E1o[N], g_F1o[N];
__device__ __half   g_E2oh[N], g_F2oh[N];
__device__ float    g_numO[N * NCLS];
__device__ float    g_denO[N];

#define SWZ128(o) ((o) ^ (((o) >> 3) & 0x70))
#define SWZA(o)   ((o) ^ (((o) >> 4) & 0x70))

#define OFF_SP   0
#define OFF_SB   32768
#define OFF_SE2  81920
#define OFF_SF2  82688
#define ATT_DSMEM (83456 + 1024)

__device__ __forceinline__ uint32_t smem_u32(const void* p) {
    return (uint32_t)__cvta_generic_to_shared(p);
}
__device__ __forceinline__ void cpasync16(uint32_t dst, const void* src) {
    asm volatile("cp.async.cg.shared.global [%0], [%1], 16;" :: "r"(dst), "l"(src));
}
__device__ __forceinline__ void cpcommit() {
    asm volatile("cp.async.commit_group;");
}
__device__ __forceinline__ void cpwait1() {
    asm volatile("cp.async.wait_group 1;");
}
__device__ __forceinline__ void sts16(uint32_t addr, uint4 v) {
    asm volatile("st.shared.v4.b32 [%0], {%1,%2,%3,%4};"
                 :: "r"(addr), "r"(v.x), "r"(v.y), "r"(v.z), "r"(v.w));
}
__device__ __forceinline__ uint4 lds16(uint32_t addr) {
    uint4 v;
    asm volatile("ld.shared.v4.b32 {%0,%1,%2,%3}, [%4];"
                 : "=r"(v.x), "=r"(v.y), "=r"(v.z), "=r"(v.w) : "r"(addr));
    return v;
}
__device__ __forceinline__ void ldsm4(uint32_t& r0, uint32_t& r1, uint32_t& r2,
                                      uint32_t& r3, uint32_t a) {
    asm volatile("ldmatrix.sync.aligned.m8n8.x4.shared.b16 {%0,%1,%2,%3}, [%4];"
                 : "=r"(r0), "=r"(r1), "=r"(r2), "=r"(r3) : "r"(a));
}
__device__ __forceinline__ void ldsm4t(uint32_t& r0, uint32_t& r1, uint32_t& r2,
                                       uint32_t& r3, uint32_t a) {
    asm volatile("ldmatrix.sync.aligned.m8n8.x4.trans.shared.b16 {%0,%1,%2,%3}, [%4];"
                 : "=r"(r0), "=r"(r1), "=r"(r2), "=r"(r3) : "r"(a));
}
__device__ __forceinline__ void mma16816(float* d, uint32_t a0, uint32_t a1,
                                         uint32_t a2, uint32_t a3,
                                         uint32_t b0, uint32_t b1) {
    asm volatile(
        "mma.sync.aligned.m16n8k16.row.col.f32.f16.f16.f32 "
        "{%0,%1,%2,%3}, {%4,%5,%6,%7}, {%8,%9}, {%0,%1,%2,%3};"
        : "+f"(d[0]), "+f"(d[1]), "+f"(d[2]), "+f"(d[3])
        : "r"(a0), "r"(a1), "r"(a2), "r"(a3), "r"(b0), "r"(b1));
}

__global__ void pack_adj_kernel(const int* __restrict__ adj) {
    int warps = gridDim.x * (blockDim.x >> 5);
    int gw    = blockIdx.x * (blockDim.x >> 5) + (threadIdx.x >> 5);
    int lane  = threadIdx.x & 31;
    const int total = N * NW;
    for (int w = gw; w < total; w += warps) {
        int v = adj[(size_t)w * 32 + lane];
        unsigned m = __ballot_sync(0xffffffffu, v > 0);
        if (lane == 0) g_bitsT[(size_t)(w & (NW - 1)) * N + (w >> 8)] = m;
    }
}

template<int BN, int MN, bool WR16>
__global__ __launch_bounds__(256) void gemm_kernel(
    const float* __restrict__ A, int lda, const float* __restrict__ B,
    float* __restrict__ C, int ldc, __half* __restrict__ C16)
{
    constexpr int BM = 128, BK = 32;
    __shared__ float sAT[BK][BM + 1];
    __shared__ float sB[BK][BN];
    int t = threadIdx.x, head = blockIdx.y, i0 = blockIdx.x * BM;
    const float* Bh = B + (size_t)head * FIN * BN;
    int tx = t & 15, ty = t >> 4;
    float acc[8][MN];
#pragma unroll
    for (int r = 0; r < 8; r++)
#pragma unroll
        for (int c = 0; c < MN; c++) acc[r][c] = 0.f;
    for (int k0 = 0; k0 < FIN; k0 += BK) {
        __syncthreads();
#pragma unroll
        for (int i = 0; i < (BM * BK) / 256; i++) {
            int l = t + i * 256, r = l >> 5, c = l & 31;
            sAT[c][r] = A[(size_t)(i0 + r) * lda + k0 + c];
        }
#pragma unroll
        for (int i = 0; i < (BK * BN) / 256; i++) {
            int l = t + i * 256, r = l / BN, c = l % BN;
            sB[r][c] = Bh[(size_t)(k0 + r) * BN + c];
        }
        __syncthreads();
#pragma unroll 8
        for (int kk = 0; kk < BK; kk++) {
            float a[8];
#pragma unroll
            for (int r = 0; r < 8; r++) a[r] = sAT[kk][ty * 8 + r];
            float b[MN];
#pragma unroll
            for (int c = 0; c < MN; c++) b[c] = sB[kk][tx * MN + c];
#pragma unroll
            for (int r = 0; r < 8; r++)
#pragma unroll
                for (int c = 0; c < MN; c++) acc[r][c] += a[r] * b[c];
        }
    }
#pragma unroll
    for (int r = 0; r < 8; r++) {
        int i = i0 + ty * 8 + r;
#pragma unroll
        for (int c = 0; c < MN; c++) {
            float v = acc[r][c];
            C[(size_t)i * ldc + head * BN + tx * MN + c] = v;
            if (WR16)
                C16[(size_t)i * ldc + head * BN + tx * MN + c] = __float2half(v);
        }
    }
}

__global__ void s_heads_kernel(const float* __restrict__ a_heads) {
    int gw = blockIdx.x * 8 + (threadIdx.x >> 5);
    int lane = threadIdx.x & 31;
    int i = gw >> 3, h = gw & 7;
    if (i >= N) return;
    const float* wh = g_Wh + (size_t)i * FIN + h * KH;
    const float* a  = a_heads + (size_t)h * 2 * KH;
    float v1 = wh[lane] * a[lane]      + wh[lane + 32] * a[lane + 32];
    float v2 = wh[lane] * a[KH + lane] + wh[lane + 32] * a[KH + lane + 32];
#pragma unroll
    for (int o = 16; o; o >>= 1) {
        v1 += __shfl_down_sync(0xffffffffu, v1, o);
        v2 += __shfl_down_sync(0xffffffffu, v2, o);
    }
    if (lane == 0) {
        g_E1[h * N + i] = __expf(v1);
        g_F1[h * N + i] = __expf(0.2f * v1);
        g_E2h[h * N + i] = __float2half(__expf(v2));
        g_F2h[h * N + i] = __float2half(__expf(0.2f * v2));
    }
}

__global__ void s_out_kernel(const float* __restrict__ a_out) {
    int gw = blockIdx.x * 8 + (threadIdx.x >> 5);
    int lane = threadIdx.x & 31;
    if (gw >= N) return;
    float v1 = 0.f, v2 = 0.f;
    if (lane < NCLS) {
        float w = g_Whout[(size_t)gw * NCLS + lane];
        v1 = w * a_out[lane];
        v2 = w * a_out[NCLS + lane];
    }
#pragma unroll
    for (int o = 16; o; o >>= 1) {
        v1 += __shfl_down_sync(0xffffffffu, v1, o);
        v2 += __shfl_down_sync(0xffffffffu, v2, o);
    }
    if (lane == 0) {
        g_E1o[gw] = __expf(v1);
        g_F1o[gw] = __expf(0.2f * v1);
        g_E2oh[gw] = __float2half(__expf(v2));
        g_F2oh[gw] = __float2half(__expf(0.2f * v2));
    }
}

__global__ void zero_acc_kernel() {
    int i = blockIdx.x * 256 + threadIdx.x;
    if (i < N * NCLS) g_numO[i] = 0.f;
    if (i < N)        g_denO[i] = 0.f;
}

__global__ void finalize_kernel(float* __restrict__ Out) {
    int i = blockIdx.x * 256 + threadIdx.x;
    if (i >= N * NCLS) return;
    float v = g_numO[i] / g_denO[i >> 4];
    Out[i] = (v > 0.f) ? v : expm1f(v);
}

// ============ fused masked-softmax attention, HMMA, JT=128, cp.async x3 ============
template<int NC, bool SPLIT>
__global__ __launch_bounds__(256, 2) void attn_hmma(
    const float* __restrict__ E1g, const float* __restrict__ F1g,
    const __half* __restrict__ E2g, const __half* __restrict__ F2g,
    const __half* __restrict__ Bg, int ldb,
    float* __restrict__ Out, int ldo)
{
    extern __shared__ char rawsm[];
    uint32_t rawu = smem_u32(rawsm);
    uint32_t base = (rawu + 1023) & ~1023u;
    uint32_t spb = base + OFF_SP, sbb = base + OFF_SB;
    uint32_t se2b = base + OFF_SE2, sf2b = base + OFF_SF2;

    int t = threadIdx.x, warp = t >> 5, lane = t & 31;
    int head  = SPLIT ? 0 : blockIdx.y;
    int jbase = SPLIT ? blockIdx.y * (N / 8) : 0;
    constexpr int NSTEP = SPLIT ? (N / 8) / 128 : N / 128;
    int i0 = blockIdx.x * 128;
    int bcol = (NC == 64) ? head * 64 : 0;

    int l16 = lane & 15, seg = lane >> 4;
    int row = warp * 16 + l16;
    __half2 e1h2 = __float2half2_rn(E1g[head * N + i0 + row]);
    __half2 f1h2 = __float2half2_rn(F1g[head * N + i0 + row]);
    const uint32_t* bp = g_bitsT + (size_t)((jbase >> 5) + seg * 2) * N + i0 + row;
    uint32_t aofs[8];
#pragma unroll
    for (int c = 0; c < 8; c++)
        aofs[c] = spb + SWZA((uint32_t)(row * 256 + seg * 128 + c * 16));

    constexpr int NCH = 128 * NC / 8;
    constexpr int CPT = NCH / 256;
    const __half* bsrc[CPT];
    uint32_t bofs[CPT];
#pragma unroll
    for (int i = 0; i < CPT; i++) {
        int ch = t + i * 256;
        int br = ch / (NC / 8), bc = ch % (NC / 8);
        bsrc[i] = Bg + (size_t)(jbase + br) * ldb + bcol + bc * 8;
        bofs[i] = sbb + SWZ128((uint32_t)(br * 128 + bc * 16));
    }
    const __half* e2base = E2g + head * N + jbase;
    const __half* f2base = F2g + head * N + jbase;

    int lhi = lane >> 4;
    // linear (pre-swizzle) A-fragment offset; swizzle applied per full offset
    uint32_t alin = (uint32_t)(row * 256 + lhi * 16);
    uint32_t bbase = (uint32_t)(l16 * 128 + lhi * 16);
    uint32_t ones0 = (lane < 4) ? 0x3C003C00u : 0u;

    float acc[NC / 8][4];
#pragma unroll
    for (int n = 0; n < NC / 8; n++)
#pragma unroll
        for (int q = 0; q < 4; q++) acc[n][q] = 0.f;
    float accd[4] = {0.f, 0.f, 0.f, 0.f};

    auto issue = [&](int s, int buf) {
        int j0 = s * 128;
#pragma unroll
        for (int i = 0; i < CPT; i++)
            cpasync16(bofs[i] + buf * 16384, bsrc[i] + (size_t)j0 * ldb);
        if (t < 16)      cpasync16(se2b + buf * 256 + t * 16, e2base + j0 + t * 8);
        else if (t < 32) cpasync16(sf2b + buf * 256 + (t - 16) * 16,
                                   f2base + j0 + (t - 16) * 8);
    };

    issue(0, 0); cpcommit();
    issue(1, 1); cpcommit();
    uint32_t w0 = bp[0], w1 = bp[N];

#pragma unroll 1
    for (int step = 0; step < NSTEP; step++) {
        int buf = step % 3;
        cpwait1();
        __syncthreads();

        if (step + 2 < NSTEP) issue(step + 2, (step + 2) % 3);
        cpcommit();

        uint32_t nw0 = 0, nw1 = 0;
        if (step + 1 < NSTEP) {
            nw0 = bp[(size_t)(step + 1) * 4 * N];
            nw1 = bp[(size_t)(step + 1) * 4 * N + N];
        }

        // ---- P tile: warp-private 16 rows x 128 j; 64 elems/thread ----
        {
            uint32_t peb = se2b + buf * 256 + seg * 128;
            uint32_t pfb = sf2b + buf * 256 + seg * 128;
#pragma unroll
            for (int c = 0; c < 8; c++) {
                uint4 e4 = lds16(peb + c * 16);
                uint4 f4 = lds16(pfb + c * 16);
                uint32_t bb = (c < 4 ? w0 : w1) >> ((c & 3) * 8);
                uint32_t vp[4];
#pragma unroll
                for (int k = 0; k < 4; k++) {
                    uint32_t eu = (&e4.x)[k], fu = (&f4.x)[k];
                    __half2 pex = __hmul2(e1h2, *(__half2*)&eu);
                    __half2 pfx = __hmul2(f1h2, *(__half2*)&fu);
                    __half2 pm  = __hmax2(pex, pfx);
                    uint32_t bk = bb >> (2 * k);
                    uint32_t m = (bk & 1u) * 0xFFFFu + (bk & 2u) * 0x7FFF8000u;
                    vp[k] = (*(uint32_t*)&pm) & m;
                }
                uint4 vv;
                vv.x = vp[0]; vv.y = vp[1]; vv.z = vp[2]; vv.w = vp[3];
                sts16(aofs[c], vv);
            }
        }
        __syncwarp();

        // ---- mma: 8 k-chunks of 16 (swizzle applied to FULL offset) ----
        uint32_t pbb = sbb + buf * 16384;
#pragma unroll
        for (int kc = 0; kc < 8; kc++) {
            uint32_t a0, a1, a2, a3;
            ldsm4(a0, a1, a2, a3, spb + SWZA(alin + kc * 32));
            mma16816(accd, a0, a1, a2, a3, ones0, ones0);
#pragma unroll
            for (int np = 0; np < NC / 16; np++) {
                uint32_t b0, b1, b2, b3;
                ldsm4t(b0, b1, b2, b3, pbb + SWZ128(bbase + kc * 2048 + np * 32));
                mma16816(acc[2 * np],     a0, a1, a2, a3, b0, b1);
                mma16816(acc[2 * np + 1], a0, a1, a2, a3, b2, b3);
            }
        }
        __syncwarp();
        w0 = nw0; w1 = nw1;
    }

    int r0 = warp * 16 + (lane >> 2);
    if constexpr (SPLIT) {
        if ((lane & 3) == 0) {
            atomicAdd(&g_denO[i0 + r0],     accd[0]);
            atomicAdd(&g_denO[i0 + r0 + 8], accd[2]);
        }
        int c0 = (lane & 3) * 2;
#pragma unroll
        for (int nt = 0; nt < NC / 8; nt++) {
            atomicAdd(&g_numO[(i0 + r0) * NCLS + nt * 8 + c0],     acc[nt][0]);
            atomicAdd(&g_numO[(i0 + r0) * NCLS + nt * 8 + c0 + 1], acc[nt][1]);
            atomicAdd(&g_numO[(i0 + r0 + 8) * NCLS + nt * 8 + c0],     acc[nt][2]);
            atomicAdd(&g_numO[(i0 + r0 + 8) * NCLS + nt * 8 + c0 + 1], acc[nt][3]);
        }
    } else {
        float den0 = __shfl_sync(0xffffffffu, accd[0], lane & 0x1C);
        float den1 = __shfl_sync(0xffffffffu, accd[2], lane & 0x1C);
        float inv0 = 1.0f / den0, inv1 = 1.0f / den1;
        float* o0 = Out + (size_t)(i0 + r0) * ldo + bcol + (lane & 3) * 2;
        float* o1 = o0 + 8 * ldo;
#pragma unroll
        for (int nt = 0; nt < NC / 8; nt++) {
            *(float2*)(o0 + nt * 8) = make_float2(acc[nt][0] * inv0, acc[nt][1] * inv0);
            *(float2*)(o1 + nt * 8) = make_float2(acc[nt][2] * inv1, acc[nt][3] * inv1);
        }
    }
}

extern "C" void kernel_launch(void* const* d_in, const int* in_sizes, int n_in,
                              void* d_out, int out_size)
{
    const float* x = nullptr;
    const int* adj = nullptr;
    const float *W_heads = nullptr, *a_heads = nullptr, *W_out = nullptr, *a_out = nullptr;
    for (int i = 0; i < n_in; i++) {
        switch (in_sizes[i]) {
            case N * FIN:      x       = (const float*)d_in[i]; break;
            case 67108864:     adj     = (const int*)  d_in[i]; break;
            case H * FIN * KH: W_heads = (const float*)d_in[i]; break;
            case H * 2 * KH:   a_heads = (const float*)d_in[i]; break;
            case FIN * NCLS:   W_out   = (const float*)d_in[i]; break;
            case 2 * NCLS:     a_out   = (const float*)d_in[i]; break;
        }
    }

    float *whP, *hP, *whoP, *e1P, *f1P, *e1oP, *f1oP;
    __half *wh16P, *who16P, *e2hP, *f2hP, *e2ohP, *f2ohP;
    cudaGetSymbolAddress((void**)&whP,   g_Wh);
    cudaGetSymbolAddress((void**)&wh16P, g_Wh16);
    cudaGetSymbolAddress((void**)&hP,    g_h);
    cudaGetSymbolAddress((void**)&whoP,  g_Whout);
    cudaGetSymbolAddress((void**)&who16P, g_Whout16);
    cudaGetSymbolAddress((void**)&e1P,  g_E1);
    cudaGetSymbolAddress((void**)&f1P,  g_F1);
    cudaGetSymbolAddress((void**)&e2hP, g_E2h);
    cudaGetSymbolAddress((void**)&f2hP, g_F2h);
    cudaGetSymbolAddress((void**)&e1oP, g_E1o);
    cudaGetSymbolAddress((void**)&f1oP, g_F1o);
    cudaGetSymbolAddress((void**)&e2ohP, g_E2oh);
    cudaGetSymbolAddress((void**)&f2ohP, g_F2oh);

    cudaFuncSetAttribute(attn_hmma<64, false>,
                         cudaFuncAttributeMaxDynamicSharedMemorySize, ATT_DSMEM);
    cudaFuncSetAttribute(attn_hmma<16, true>,
                         cudaFuncAttributeMaxDynamicSharedMemorySize, ATT_DSMEM);

    pack_adj_kernel<<<4096, 256>>>(adj);
    gemm_kernel<64, 4, true><<<dim3(N / 128, H), 256>>>(x, FIN, W_heads, whP, FIN, wh16P);
    s_heads_kernel<<<(N * H) / 8, 256>>>(a_heads);
    zero_acc_kernel<<<(N * NCLS + 255) / 256, 256>>>();
    attn_hmma<64, false><<<dim3(N / 128, H), 256, ATT_DSMEM>>>(
        e1P, f1P, e2hP, f2hP, wh16P, FIN, hP, FIN);
    gemm_kernel<16, 1, true><<<dim3(N / 128, 1), 256>>>(hP, FIN, W_out, whoP, NCLS, who16P);
    s_out_kernel<<<N / 8, 256>>>(a_out);
    attn_hmma<16, true><<<dim3(N / 128, 8), 256, ATT_DSMEM>>>(
        e1oP, f1oP, e2ohP, f2ohP, who16P, NCLS, nullptr, NCLS);
    finalize_kernel<<<(N * NCLS + 255) / 256, 256>>>((float*)d_out);
}

// round 9
// speedup vs baseline: 5.4658x; 1.1842x over previous
#include <cuda_runtime.h>
#include <cuda_fp16.h>
#include <cstdint>
#include <math.h>

#define N    8192
#define NW   (N/32)
#define FIN  512
#define KH   64
#define H    8
#define NCLS 16

__device__ uint32_t g_bitsT[NW * N];
__device__ __half   g_x16  [N * FIN];      // fp16 input features
__device__ __half   g_W16  [H * FIN * KH]; // fp16 head weights
__device__ __half   g_Wh16 [N * FIN];      // layer-1 Wh fp16 (feature-GEMM out)
__device__ float    g_h    [N * FIN];
__device__ float    g_Whout[N * NCLS];
__device__ __half   g_Whout16[N * NCLS];
__device__ float    g_E1[H * N], g_F1[H * N];
__device__ __half   g_E2h[H * N], g_F2h[H * N];
__device__ float    g_E1o[N], g_F1o[N];
__device__ __half   g_E2oh[N], g_F2oh[N];
__device__ float    g_numO[N * NCLS];
__device__ float    g_denO[N];

#define SWZ128(o) ((o) ^ (((o) >> 3) & 0x70))
#define SWZA(o)   ((o) ^ (((o) >> 4) & 0x70))

// attn dyn smem: sP 32KB | sB 3x16KB | sE2 3x256B | sF2 3x256B
#define OFF_SP   0
#define OFF_SB   32768
#define OFF_SE2  81920
#define OFF_SF2  82688
#define ATT_DSMEM (83456 + 1024)
// gemm dyn smem: sA 3x16KB | sB 3x8KB
#define GOFF_SB  49152
#define GEMM_DSMEM (73728 + 1024)

__device__ __forceinline__ uint32_t smem_u32(const void* p) {
    return (uint32_t)__cvta_generic_to_shared(p);
}
__device__ __forceinline__ void cpasync16(uint32_t dst, const void* src) {
    asm volatile("cp.async.cg.shared.global [%0], [%1], 16;" :: "r"(dst), "l"(src));
}
__device__ __forceinline__ void cpcommit() {
    asm volatile("cp.async.commit_group;");
}
__device__ __forceinline__ void cpwait1() {
    asm volatile("cp.async.wait_group 1;");
}
__device__ __forceinline__ void sts16(uint32_t addr, uint4 v) {
    asm volatile("st.shared.v4.b32 [%0], {%1,%2,%3,%4};"
                 :: "r"(addr), "r"(v.x), "r"(v.y), "r"(v.z), "r"(v.w));
}
__device__ __forceinline__ uint4 lds16(uint32_t addr) {
    uint4 v;
    asm volatile("ld.shared.v4.b32 {%0,%1,%2,%3}, [%4];"
                 : "=r"(v.x), "=r"(v.y), "=r"(v.z), "=r"(v.w) : "r"(addr));
    return v;
}
__device__ __forceinline__ void ldsm4(uint32_t& r0, uint32_t& r1, uint32_t& r2,
                                      uint32_t& r3, uint32_t a) {
    asm volatile("ldmatrix.sync.aligned.m8n8.x4.shared.b16 {%0,%1,%2,%3}, [%4];"
                 : "=r"(r0), "=r"(r1), "=r"(r2), "=r"(r3) : "r"(a));
}
__device__ __forceinline__ void ldsm4t(uint32_t& r0, uint32_t& r1, uint32_t& r2,
                                       uint32_t& r3, uint32_t a) {
    asm volatile("ldmatrix.sync.aligned.m8n8.x4.trans.shared.b16 {%0,%1,%2,%3}, [%4];"
                 : "=r"(r0), "=r"(r1), "=r"(r2), "=r"(r3) : "r"(a));
}
__device__ __forceinline__ void mma16816(float* d, uint32_t a0, uint32_t a1,
                                         uint32_t a2, uint32_t a3,
                                         uint32_t b0, uint32_t b1) {
    asm volatile(
        "mma.sync.aligned.m16n8k16.row.col.f32.f16.f16.f32 "
        "{%0,%1,%2,%3}, {%4,%5,%6,%7}, {%8,%9}, {%0,%1,%2,%3};"
        : "+f"(d[0]), "+f"(d[1]), "+f"(d[2]), "+f"(d[3])
        : "r"(a0), "r"(a1), "r"(a2), "r"(a3), "r"(b0), "r"(b1));
}

__global__ void pack_adj_kernel(const int* __restrict__ adj) {
    int warps = gridDim.x * (blockDim.x >> 5);
    int gw    = blockIdx.x * (blockDim.x >> 5) + (threadIdx.x >> 5);
    int lane  = threadIdx.x & 31;
    const int total = N * NW;
    for (int w = gw; w < total; w += warps) {
        int v = adj[(size_t)w * 32 + lane];
        unsigned m = __ballot_sync(0xffffffffu, v > 0);
        if (lane == 0) g_bitsT[(size_t)(w & (NW - 1)) * N + (w >> 8)] = m;
    }
}

// ---------------- fp32 -> fp16 conversions ----------------
__global__ void convert16_kernel(const float* __restrict__ x,
                                 const float* __restrict__ W_heads) {
    int stride = gridDim.x * blockDim.x;
    int tid = blockIdx.x * blockDim.x + threadIdx.x;
    for (int i = tid; i < (N * FIN) / 4; i += stride) {
        float4 v = *((const float4*)x + i);
        __half2 h0 = __floats2half2_rn(v.x, v.y);
        __half2 h1 = __floats2half2_rn(v.z, v.w);
        *((__half2*)g_x16 + i * 2)     = h0;
        *((__half2*)g_x16 + i * 2 + 1) = h1;
    }
    for (int i = tid; i < (H * FIN * KH) / 4; i += stride) {
        float4 v = *((const float4*)W_heads + i);
        __half2 h0 = __floats2half2_rn(v.x, v.y);
        __half2 h1 = __floats2half2_rn(v.z, v.w);
        *((__half2*)g_W16 + i * 2)     = h0;
        *((__half2*)g_W16 + i * 2 + 1) = h1;
    }
}

// ---------------- layer-1 feature GEMM on HMMA ----------------
// g_Wh16[i, head*64+n] = sum_k x16[i,k] * W16[head][k][n]
__global__ __launch_bounds__(256, 2) void gemm_hmma_kernel()
{
    extern __shared__ char rawsm[];
    uint32_t rawu = smem_u32(rawsm);
    uint32_t base = (rawu + 1023) & ~1023u;
    uint32_t sab = base, sbb = base + GOFF_SB;

    int t = threadIdx.x, warp = t >> 5, lane = t & 31;
    int head = blockIdx.y, i0 = blockIdx.x * 128;
    int l16 = lane & 15, lhi = lane >> 4;
    int row = warp * 16 + l16;

    // A loader: 4 chunks/thread (128 rows x 64 halves = 16KB)
    const __half* asrc[4];
    uint32_t aofs_[4];
#pragma unroll
    for (int i = 0; i < 4; i++) {
        int ch = t + i * 256, r = ch >> 3, c8 = ch & 7;
        asrc[i]  = g_x16 + (size_t)(i0 + r) * FIN + c8 * 8;
        aofs_[i] = sab + SWZ128((uint32_t)(r * 128 + c8 * 16));
    }
    // B loader: 2 chunks/thread (64 k-rows x 64 halves = 8KB)
    const __half* bsrc[2];
    uint32_t bofs_[2];
#pragma unroll
    for (int i = 0; i < 2; i++) {
        int ch = t + i * 256, r = ch >> 3, c8 = ch & 7;
        bsrc[i]  = g_W16 + (size_t)head * FIN * KH + r * KH + c8 * 8;
        bofs_[i] = sbb + SWZ128((uint32_t)(r * 128 + c8 * 16));
    }

    uint32_t alin  = (uint32_t)(row * 128 + lhi * 16);
    uint32_t bbase = (uint32_t)(l16 * 128 + lhi * 16);

    float acc[8][4];
#pragma unroll
    for (int n = 0; n < 8; n++)
#pragma unroll
        for (int q = 0; q < 4; q++) acc[n][q] = 0.f;

    auto issue = [&](int s, int buf) {
        int k0 = s * 64;
#pragma unroll
        for (int i = 0; i < 4; i++)
            cpasync16(aofs_[i] + buf * 16384, asrc[i] + k0);
#pragma unroll
        for (int i = 0; i < 2; i++)
            cpasync16(bofs_[i] + buf * 8192, bsrc[i] + (size_t)k0 * KH);
    };

    issue(0, 0); cpcommit();
    issue(1, 1); cpcommit();

    constexpr int NSTEP = FIN / 64;   // 8
#pragma unroll 1
    for (int step = 0; step < NSTEP; step++) {
        int buf = step % 3;
        cpwait1();
        __syncthreads();
        if (step + 2 < NSTEP) issue(step + 2, (step + 2) % 3);
        cpcommit();

        uint32_t pab = sab + buf * 16384;
        uint32_t pbb = sbb + buf * 8192;
#pragma unroll
        for (int kc = 0; kc < 4; kc++) {
            uint32_t a0, a1, a2, a3;
            ldsm4(a0, a1, a2, a3, pab + SWZ128(alin + kc * 32));
#pragma unroll
            for (int np = 0; np < 4; np++) {
                uint32_t b0, b1, b2, b3;
                ldsm4t(b0, b1, b2, b3, pbb + SWZ128(bbase + kc * 2048 + np * 32));
                mma16816(acc[2 * np],     a0, a1, a2, a3, b0, b1);
                mma16816(acc[2 * np + 1], a0, a1, a2, a3, b2, b3);
            }
        }
    }

    int r0 = warp * 16 + (lane >> 2), c0 = (lane & 3) * 2;
    __half* o0 = g_Wh16 + (size_t)(i0 + r0) * FIN + head * KH + c0;
    __half* o1 = o0 + 8 * FIN;
#pragma unroll
    for (int nt = 0; nt < 8; nt++) {
        *(__half2*)(o0 + nt * 8) = __floats2half2_rn(acc[nt][0], acc[nt][1]);
        *(__half2*)(o1 + nt * 8) = __floats2half2_rn(acc[nt][2], acc[nt][3]);
    }
}

// ---------------- fp32 feature GEMM (layer-2 only) ----------------
template<int BN, int MN, bool WR16>
__global__ __launch_bounds__(256) void gemm_kernel(
    const float* __restrict__ A, int lda, const float* __restrict__ B,
    float* __restrict__ C, int ldc, __half* __restrict__ C16)
{
    constexpr int BM = 128, BK = 32;
    __shared__ float sAT[BK][BM + 1];
    __shared__ float sB[BK][BN];
    int t = threadIdx.x, head = blockIdx.y, i0 = blockIdx.x * BM;
    const float* Bh = B + (size_t)head * FIN * BN;
    int tx = t & 15, ty = t >> 4;
    float acc[8][MN];
#pragma unroll
    for (int r = 0; r < 8; r++)
#pragma unroll
        for (int c = 0; c < MN; c++) acc[r][c] = 0.f;
    for (int k0 = 0; k0 < FIN; k0 += BK) {
        __syncthreads();
#pragma unroll
        for (int i = 0; i < (BM * BK) / 256; i++) {
            int l = t + i * 256, r = l >> 5, c = l & 31;
            sAT[c][r] = A[(size_t)(i0 + r) * lda + k0 + c];
        }
#pragma unroll
        for (int i = 0; i < (BK * BN) / 256; i++) {
            int l = t + i * 256, r = l / BN, c = l % BN;
            sB[r][c] = Bh[(size_t)(k0 + r) * BN + c];
        }
        __syncthreads();
#pragma unroll 8
        for (int kk = 0; kk < BK; kk++) {
            float a[8];
#pragma unroll
            for (int r = 0; r < 8; r++) a[r] = sAT[kk][ty * 8 + r];
            float b[MN];
#pragma unroll
            for (int c = 0; c < MN; c++) b[c] = sB[kk][tx * MN + c];
#pragma unroll
            for (int r = 0; r < 8; r++)
#pragma unroll
                for (int c = 0; c < MN; c++) acc[r][c] += a[r] * b[c];
        }
    }
#pragma unroll
    for (int r = 0; r < 8; r++) {
        int i = i0 + ty * 8 + r;
#pragma unroll
        for (int c = 0; c < MN; c++) {
            float v = acc[r][c];
            C[(size_t)i * ldc + head * BN + tx * MN + c] = v;
            if (WR16)
                C16[(size_t)i * ldc + head * BN + tx * MN + c] = __float2half(v);
        }
    }
}

// ---------------- score factors (reads fp16 Wh) ----------------
__global__ void s_heads_kernel(const float* __restrict__ a_heads) {
    int gw = blockIdx.x * 8 + (threadIdx.x >> 5);
    int lane = threadIdx.x & 31;
    int i = gw >> 3, h = gw & 7;
    if (i >= N) return;
    const __half* wh = g_Wh16 + (size_t)i * FIN + h * KH;
    const float* a  = a_heads + (size_t)h * 2 * KH;
    float w0 = __half2float(wh[lane]);
    float w1 = __half2float(wh[lane + 32]);
    float v1 = w0 * a[lane]      + w1 * a[lane + 32];
    float v2 = w0 * a[KH + lane] + w1 * a[KH + lane + 32];
#pragma unroll
    for (int o = 16; o; o >>= 1) {
        v1 += __shfl_down_sync(0xffffffffu, v1, o);
        v2 += __shfl_down_sync(0xffffffffu, v2, o);
    }
    if (lane == 0) {
        g_E1[h * N + i] = __expf(v1);
        g_F1[h * N + i] = __expf(0.2f * v1);
        g_E2h[h * N + i] = __float2half(__expf(v2));
        g_F2h[h * N + i] = __float2half(__expf(0.2f * v2));
    }
}

__global__ void s_out_kernel(const float* __restrict__ a_out) {
    int gw = blockIdx.x * 8 + (threadIdx.x >> 5);
    int lane = threadIdx.x & 31;
    if (gw >= N) return;
    float v1 = 0.f, v2 = 0.f;
    if (lane < NCLS) {
        float w = g_Whout[(size_t)gw * NCLS + lane];
        v1 = w * a_out[lane];
        v2 = w * a_out[NCLS + lane];
    }
#pragma unroll
    for (int o = 16; o; o >>= 1) {
        v1 += __shfl_down_sync(0xffffffffu, v1, o);
        v2 += __shfl_down_sync(0xffffffffu, v2, o);
    }
    if (lane == 0) {
        g_E1o[gw] = __expf(v1);
        g_F1o[gw] = __expf(0.2f * v1);
        g_E2oh[gw] = __float2half(__expf(v2));
        g_F2oh[gw] = __float2half(__expf(0.2f * v2));
    }
}

__global__ void finalize_kernel(float* __restrict__ Out) {
    int i = blockIdx.x * 256 + threadIdx.x;
    if (i >= N * NCLS) return;
    float v = g_numO[i] / g_denO[i >> 4];
    Out[i] = (v > 0.f) ? v : expm1f(v);
}

// ============ fused masked-softmax attention, HMMA, JT=128, cp.async x3 ============
template<int NC, bool SPLIT>
__global__ __launch_bounds__(256, 2) void attn_hmma(
    const float* __restrict__ E1g, const float* __restrict__ F1g,
    const __half* __restrict__ E2g, const __half* __restrict__ F2g,
    const __half* __restrict__ Bg, int ldb,
    float* __restrict__ Out, int ldo)
{
    extern __shared__ char rawsm[];
    uint32_t rawu = smem_u32(rawsm);
    uint32_t base = (rawu + 1023) & ~1023u;
    uint32_t spb = base + OFF_SP, sbb = base + OFF_SB;
    uint32_t se2b = base + OFF_SE2, sf2b = base + OFF_SF2;

    int t = threadIdx.x, warp = t >> 5, lane = t & 31;
    int head  = SPLIT ? 0 : blockIdx.y;
    int jbase = SPLIT ? blockIdx.y * (N / 8) : 0;
    constexpr int NSTEP = SPLIT ? (N / 8) / 128 : N / 128;
    int i0 = blockIdx.x * 128;
    int bcol = (NC == 64) ? head * 64 : 0;

    int l16 = lane & 15, seg = lane >> 4;
    int row = warp * 16 + l16;
    __half2 e1h2 = __float2half2_rn(E1g[head * N + i0 + row]);
    __half2 f1h2 = __float2half2_rn(F1g[head * N + i0 + row]);
    const uint32_t* bp = g_bitsT + (size_t)((jbase >> 5) + seg * 2) * N + i0 + row;
    uint32_t aofs[8];
#pragma unroll
    for (int c = 0; c < 8; c++)
        aofs[c] = spb + SWZA((uint32_t)(row * 256 + seg * 128 + c * 16));

    constexpr int NCH = 128 * NC / 8;
    constexpr int CPT = NCH / 256;
    const __half* bsrc[CPT];
    uint32_t bofs[CPT];
#pragma unroll
    for (int i = 0; i < CPT; i++) {
        int ch = t + i * 256;
        int br = ch / (NC / 8), bc = ch % (NC / 8);
        bsrc[i] = Bg + (size_t)(jbase + br) * ldb + bcol + bc * 8;
        bofs[i] = sbb + SWZ128((uint32_t)(br * 128 + bc * 16));
    }
    const __half* e2base = E2g + head * N + jbase;
    const __half* f2base = F2g + head * N + jbase;

    int lhi = lane >> 4;
    uint32_t alin = (uint32_t)(row * 256 + lhi * 16);
    uint32_t bbase = (uint32_t)(l16 * 128 + lhi * 16);
    uint32_t ones0 = (lane < 4) ? 0x3C003C00u : 0u;

    float acc[NC / 8][4];
#pragma unroll
    for (int n = 0; n < NC / 8; n++)
#pragma unroll
        for (int q = 0; q < 4; q++) acc[n][q] = 0.f;
    float accd[4] = {0.f, 0.f, 0.f, 0.f};

    auto issue = [&](int s, int buf) {
        int j0 = s * 128;
#pragma unroll
        for (int i = 0; i < CPT; i++)
            cpasync16(bofs[i] + buf * 16384, bsrc[i] + (size_t)j0 * ldb);
        if (t < 16)      cpasync16(se2b + buf * 256 + t * 16, e2base + j0 + t * 8);
        else if (t < 32) cpasync16(sf2b + buf * 256 + (t - 16) * 16,
                                   f2base + j0 + (t - 16) * 8);
    };

    issue(0, 0); cpcommit();
    issue(1, 1); cpcommit();
    uint32_t w0 = bp[0], w1 = bp[N];

#pragma unroll 1
    for (int step = 0; step < NSTEP; step++) {
        int buf = step % 3;
        cpwait1();
        __syncthreads();

        if (step + 2 < NSTEP) issue(step + 2, (step + 2) % 3);
        cpcommit();

        uint32_t nw0 = 0, nw1 = 0;
        if (step + 1 < NSTEP) {
            nw0 = bp[(size_t)(step + 1) * 4 * N];
            nw1 = bp[(size_t)(step + 1) * 4 * N + N];
        }

        {
            uint32_t peb = se2b + buf * 256 + seg * 128;
            uint32_t pfb = sf2b + buf * 256 + seg * 128;
#pragma unroll
            for (int c = 0; c < 8; c++) {
                uint4 e4 = lds16(peb + c * 16);
                uint4 f4 = lds16(pfb + c * 16);
                uint32_t bb = (c < 4 ? w0 : w1) >> ((c & 3) * 8);
                uint32_t vp[4];
#pragma unroll
                for (int k = 0; k < 4; k++) {
                    uint32_t eu = (&e4.x)[k], fu = (&f4.x)[k];
                    __half2 pex = __hmul2(e1h2, *(__half2*)&eu);
                    __half2 pfx = __hmul2(f1h2, *(__half2*)&fu);
                    __half2 pm  = __hmax2(pex, pfx);
                    uint32_t bk = bb >> (2 * k);
                    uint32_t m = (bk & 1u) * 0xFFFFu + (bk & 2u) * 0x7FFF8000u;
                    vp[k] = (*(uint32_t*)&pm) & m;
                }
                uint4 vv;
                vv.x = vp[0]; vv.y = vp[1]; vv.z = vp[2]; vv.w = vp[3];
                sts16(aofs[c], vv);
            }
        }
        __syncwarp();

        uint32_t pbb = sbb + buf * 16384;
#pragma unroll
        for (int kc = 0; kc < 8; kc++) {
            uint32_t a0, a1, a2, a3;
            ldsm4(a0, a1, a2, a3, spb + SWZA(alin + kc * 32));
            mma16816(accd, a0, a1, a2, a3, ones0, ones0);
#pragma unroll
            for (int np = 0; np < NC / 16; np++) {
                uint32_t b0, b1, b2, b3;
                ldsm4t(b0, b1, b2, b3, pbb + SWZ128(bbase + kc * 2048 + np * 32));
                mma16816(acc[2 * np],     a0, a1, a2, a3, b0, b1);
                mma16816(acc[2 * np + 1], a0, a1, a2, a3, b2, b3);
            }
        }
        __syncwarp();
        w0 = nw0; w1 = nw1;
    }

    int r0 = warp * 16 + (lane >> 2);
    if constexpr (SPLIT) {
        if ((lane & 3) == 0) {
            atomicAdd(&g_denO[i0 + r0],     accd[0]);
            atomicAdd(&g_denO[i0 + r0 + 8], accd[2]);
        }
        int c0 = (lane & 3) * 2;
#pragma unroll
        for (int nt = 0; nt < NC / 8; nt++) {
            atomicAdd(&g_numO[(i0 + r0) * NCLS + nt * 8 + c0],     acc[nt][0]);
            atomicAdd(&g_numO[(i0 + r0) * NCLS + nt * 8 + c0 + 1], acc[nt][1]);
            atomicAdd(&g_numO[(i0 + r0 + 8) * NCLS + nt * 8 + c0],     acc[nt][2]);
            atomicAdd(&g_numO[(i0 + r0 + 8) * NCLS + nt * 8 + c0 + 1], acc[nt][3]);
        }
    } else {
        float den0 = __shfl_sync(0xffffffffu, accd[0], lane & 0x1C);
        float den1 = __shfl_sync(0xffffffffu, accd[2], lane & 0x1C);
        float inv0 = 1.0f / den0, inv1 = 1.0f / den1;
        float* o0 = Out + (size_t)(i0 + r0) * ldo + bcol + (lane & 3) * 2;
        float* o1 = o0 + 8 * ldo;
#pragma unroll
        for (int nt = 0; nt < NC / 8; nt++) {
            *(float2*)(o0 + nt * 8) = make_float2(acc[nt][0] * inv0, acc[nt][1] * inv0);
            *(float2*)(o1 + nt * 8) = make_float2(acc[nt][2] * inv1, acc[nt][3] * inv1);
        }
    }
}

extern "C" void kernel_launch(void* const* d_in, const int* in_sizes, int n_in,
                              void* d_out, int out_size)
{
    const float* x = nullptr;
    const int* adj = nullptr;
    const float *W_heads = nullptr, *a_heads = nullptr, *W_out = nullptr, *a_out = nullptr;
    for (int i = 0; i < n_in; i++) {
        switch (in_sizes[i]) {
            case N * FIN:      x       = (const float*)d_in[i]; break;
            case 67108864:     adj     = (const int*)  d_in[i]; break;
            case H * FIN * KH: W_heads = (const float*)d_in[i]; break;
            case H * 2 * KH:   a_heads = (const float*)d_in[i]; break;
            case FIN * NCLS:   W_out   = (const float*)d_in[i]; break;
            case 2 * NCLS:     a_out   = (const float*)d_in[i]; break;
        }
    }

    float *hP, *whoP, *e1P, *f1P, *e1oP, *f1oP, *numP, *denP;
    __half *wh16P, *who16P, *e2hP, *f2hP, *e2ohP, *f2ohP;
    cudaGetSymbolAddress((void**)&wh16P, g_Wh16);
    cudaGetSymbolAddress((void**)&hP,    g_h);
    cudaGetSymbolAddress((void**)&whoP,  g_Whout);
    cudaGetSymbolAddress((void**)&who16P, g_Whout16);
    cudaGetSymbolAddress((void**)&e1P,  g_E1);
    cudaGetSymbolAddress((void**)&f1P,  g_F1);
    cudaGetSymbolAddress((void**)&e2hP, g_E2h);
    cudaGetSymbolAddress((void**)&f2hP, g_F2h);
    cudaGetSymbolAddress((void**)&e1oP, g_E1o);
    cudaGetSymbolAddress((void**)&f1oP, g_F1o);
    cudaGetSymbolAddress((void**)&e2ohP, g_E2oh);
    cudaGetSymbolAddress((void**)&f2ohP, g_F2oh);
    cudaGetSymbolAddress((void**)&numP, g_numO);
    cudaGetSymbolAddress((void**)&denP, g_denO);

    cudaFuncSetAttribute(attn_hmma<64, false>,
                         cudaFuncAttributeMaxDynamicSharedMemorySize, ATT_DSMEM);
    cudaFuncSetAttribute(attn_hmma<16, true>,
                         cudaFuncAttributeMaxDynamicSharedMemorySize, ATT_DSMEM);
    cudaFuncSetAttribute(gemm_hmma_kernel,
                         cudaFuncAttributeMaxDynamicSharedMemorySize, GEMM_DSMEM);

    pack_adj_kernel<<<4096, 256>>>(adj);
    convert16_kernel<<<2048, 256>>>(x, W_heads);
    gemm_hmma_kernel<<<dim3(N / 128, H), 256, GEMM_DSMEM>>>();
    s_heads_kernel<<<(N * H) / 8, 256>>>(a_heads);
    cudaMemsetAsync(numP, 0, N * NCLS * sizeof(float));
    cudaMemsetAsync(denP, 0, N * sizeof(float));
    attn_hmma<64, false><<<dim3(N / 128, H), 256, ATT_DSMEM>>>(
        e1P, f1P, e2hP, f2hP, wh16P, FIN, hP, FIN);
    gemm_kernel<16, 1, true><<<dim3(N / 128, 1), 256>>>(hP, FIN, W_out, whoP, NCLS, who16P);
    s_out_kernel<<<N / 8, 256>>>(a_out);
    attn_hmma<16, true><<<dim3(N / 128, 8), 256, ATT_DSMEM>>>(
        e1oP, f1oP, e2ohP, f2ohP, who16P, NCLS, nullptr, NCLS);
    finalize_kernel<<<(N * NCLS + 255) / 256, 256>>>((float*)d_out);
}

// round 10
// speedup vs baseline: 5.5759x; 1.0201x over previous
#include <cuda_runtime.h>
#include <cuda_fp16.h>
#include <cstdint>
#include <math.h>

#define N    8192
#define NW   (N/32)
#define FIN  512
#define KH   64
#define H    8
#define NCLS 16

__device__ uint32_t g_bitsT[NW * N];
__device__ __half   g_x16  [N * FIN];
__device__ __half   g_W16  [H * FIN * KH];
__device__ __half   g_Wh16 [N * FIN];
__device__ float    g_h    [N * FIN];
__device__ float    g_Whout[N * NCLS];
__device__ __half   g_Whout16[N * NCLS];
__device__ float    g_E1[H * N], g_F1[H * N];
__device__ __half   g_E2h[H * N], g_F2h[H * N];
__device__ float    g_E1o[N], g_F1o[N];
__device__ __half   g_E2oh[N], g_F2oh[N];
__device__ float    g_numO[N * NCLS];
__device__ float    g_denO[N];

#define SWZ128(o) ((o) ^ (((o) >> 3) & 0x70))

// attn dyn smem: sB 3x16KB | sE2 3x256B | sF2 3x256B | sMask 3x2KB
#define OFF_SB   0
#define OFF_SE2  49152
#define OFF_SF2  49920
#define OFF_SM   50688
#define ATT_DSMEM (56832 + 1024)
// gemm dyn smem: sA 3x16KB | sB 3x8KB
#define GOFF_SB  49152
#define GEMM_DSMEM (73728 + 1024)

__device__ __forceinline__ uint32_t smem_u32(const void* p) {
    return (uint32_t)__cvta_generic_to_shared(p);
}
__device__ __forceinline__ void cpasync16(uint32_t dst, const void* src) {
    asm volatile("cp.async.cg.shared.global [%0], [%1], 16;" :: "r"(dst), "l"(src));
}
__device__ __forceinline__ void cpcommit() {
    asm volatile("cp.async.commit_group;");
}
__device__ __forceinline__ void cpwait1() {
    asm volatile("cp.async.wait_group 1;");
}
__device__ __forceinline__ uint32_t lds32(uint32_t addr) {
    uint32_t v;
    asm volatile("ld.shared.b32 %0, [%1];" : "=r"(v) : "r"(addr));
    return v;
}
__device__ __forceinline__ void ldsm4(uint32_t& r0, uint32_t& r1, uint32_t& r2,
                                      uint32_t& r3, uint32_t a) {
    asm volatile("ldmatrix.sync.aligned.m8n8.x4.shared.b16 {%0,%1,%2,%3}, [%4];"
                 : "=r"(r0), "=r"(r1), "=r"(r2), "=r"(r3) : "r"(a));
}
__device__ __forceinline__ void ldsm4t(uint32_t& r0, uint32_t& r1, uint32_t& r2,
                                       uint32_t& r3, uint32_t a) {
    asm volatile("ldmatrix.sync.aligned.m8n8.x4.trans.shared.b16 {%0,%1,%2,%3}, [%4];"
                 : "=r"(r0), "=r"(r1), "=r"(r2), "=r"(r3) : "r"(a));
}
__device__ __forceinline__ void mma16816(float* d, uint32_t a0, uint32_t a1,
                                         uint32_t a2, uint32_t a3,
                                         uint32_t b0, uint32_t b1) {
    asm volatile(
        "mma.sync.aligned.m16n8k16.row.col.f32.f16.f16.f32 "
        "{%0,%1,%2,%3}, {%4,%5,%6,%7}, {%8,%9}, {%0,%1,%2,%3};"
        : "+f"(d[0]), "+f"(d[1]), "+f"(d[2]), "+f"(d[3])
        : "r"(a0), "r"(a1), "r"(a2), "r"(a3), "r"(b0), "r"(b1));
}
// P fragment element pair: mask .* max(E1*E2, F1*F2)  (half2)
__device__ __forceinline__ uint32_t fragP(uint32_t e1, uint32_t f1,
                                          uint32_t e2, uint32_t f2, uint32_t bits) {
    __half2 pe = __hmul2(*(__half2*)&e1, *(__half2*)&e2);
    __half2 pf = __hmul2(*(__half2*)&f1, *(__half2*)&f2);
    __half2 pm = __hmax2(pe, pf);
    uint32_t m = (bits & 1u) * 0xFFFFu + (bits & 2u) * 0x7FFF8000u;
    return (*(uint32_t*)&pm) & m;
}

__global__ void pack_adj_kernel(const int* __restrict__ adj) {
    int warps = gridDim.x * (blockDim.x >> 5);
    int gw    = blockIdx.x * (blockDim.x >> 5) + (threadIdx.x >> 5);
    int lane  = threadIdx.x & 31;
    const int total = N * NW;
    for (int w = gw; w < total; w += warps) {
        int v = adj[(size_t)w * 32 + lane];
        unsigned m = __ballot_sync(0xffffffffu, v > 0);
        if (lane == 0) g_bitsT[(size_t)(w & (NW - 1)) * N + (w >> 8)] = m;
    }
}

__global__ void convert16_kernel(const float* __restrict__ x,
                                 const float* __restrict__ W_heads) {
    int stride = gridDim.x * blockDim.x;
    int tid = blockIdx.x * blockDim.x + threadIdx.x;
    for (int i = tid; i < (N * FIN) / 4; i += stride) {
        float4 v = *((const float4*)x + i);
        *((__half2*)g_x16 + i * 2)     = __floats2half2_rn(v.x, v.y);
        *((__half2*)g_x16 + i * 2 + 1) = __floats2half2_rn(v.z, v.w);
    }
    for (int i = tid; i < (H * FIN * KH) / 4; i += stride) {
        float4 v = *((const float4*)W_heads + i);
        *((__half2*)g_W16 + i * 2)     = __floats2half2_rn(v.x, v.y);
        *((__half2*)g_W16 + i * 2 + 1) = __floats2half2_rn(v.z, v.w);
    }
}

// ---------------- layer-1 feature GEMM on HMMA ----------------
__global__ __launch_bounds__(256, 2) void gemm_hmma_kernel()
{
    extern __shared__ char rawsm[];
    uint32_t rawu = smem_u32(rawsm);
    uint32_t base = (rawu + 1023) & ~1023u;
    uint32_t sab = base, sbb = base + GOFF_SB;

    int t = threadIdx.x, warp = t >> 5, lane = t & 31;
    int head = blockIdx.y, i0 = blockIdx.x * 128;
    int l16 = lane & 15, lhi = lane >> 4;
    int row = warp * 16 + l16;

    const __half* asrc[4];
    uint32_t aofs_[4];
#pragma unroll
    for (int i = 0; i < 4; i++) {
        int ch = t + i * 256, r = ch >> 3, c8 = ch & 7;
        asrc[i]  = g_x16 + (size_t)(i0 + r) * FIN + c8 * 8;
        aofs_[i] = sab + SWZ128((uint32_t)(r * 128 + c8 * 16));
    }
    const __half* bsrc[2];
    uint32_t bofs_[2];
#pragma unroll
    for (int i = 0; i < 2; i++) {
        int ch = t + i * 256, r = ch >> 3, c8 = ch & 7;
        bsrc[i]  = g_W16 + (size_t)head * FIN * KH + r * KH + c8 * 8;
        bofs_[i] = sbb + SWZ128((uint32_t)(r * 128 + c8 * 16));
    }

    uint32_t alin  = (uint32_t)(row * 128 + lhi * 16);
    uint32_t bbase = (uint32_t)(l16 * 128 + lhi * 16);

    float acc[8][4];
#pragma unroll
    for (int n = 0; n < 8; n++)
#pragma unroll
        for (int q = 0; q < 4; q++) acc[n][q] = 0.f;

    auto issue = [&](int s, int buf) {
        int k0 = s * 64;
#pragma unroll
        for (int i = 0; i < 4; i++)
            cpasync16(aofs_[i] + buf * 16384, asrc[i] + k0);
#pragma unroll
        for (int i = 0; i < 2; i++)
            cpasync16(bofs_[i] + buf * 8192, bsrc[i] + (size_t)k0 * KH);
    };

    issue(0, 0); cpcommit();
    issue(1, 1); cpcommit();

    constexpr int NSTEP = FIN / 64;
#pragma unroll 1
    for (int step = 0; step < NSTEP; step++) {
        int buf = step % 3;
        cpwait1();
        __syncthreads();
        if (step + 2 < NSTEP) issue(step + 2, (step + 2) % 3);
        cpcommit();

        uint32_t pab = sab + buf * 16384;
        uint32_t pbb = sbb + buf * 8192;
#pragma unroll
        for (int kc = 0; kc < 4; kc++) {
            uint32_t a0, a1, a2, a3;
            ldsm4(a0, a1, a2, a3, pab + SWZ128(alin + kc * 32));
#pragma unroll
            for (int np = 0; np < 4; np++) {
                uint32_t b0, b1, b2, b3;
                ldsm4t(b0, b1, b2, b3, pbb + SWZ128(bbase + kc * 2048 + np * 32));
                mma16816(acc[2 * np],     a0, a1, a2, a3, b0, b1);
                mma16816(acc[2 * np + 1], a0, a1, a2, a3, b2, b3);
            }
        }
    }

    int r0 = warp * 16 + (lane >> 2), c0 = (lane & 3) * 2;
    __half* o0 = g_Wh16 + (size_t)(i0 + r0) * FIN + head * KH + c0;
    __half* o1 = o0 + 8 * FIN;
#pragma unroll
    for (int nt = 0; nt < 8; nt++) {
        *(__half2*)(o0 + nt * 8) = __floats2half2_rn(acc[nt][0], acc[nt][1]);
        *(__half2*)(o1 + nt * 8) = __floats2half2_rn(acc[nt][2], acc[nt][3]);
    }
}

// ---------------- fp32 feature GEMM (layer-2 only) ----------------
template<int BN, int MN, bool WR16>
__global__ __launch_bounds__(256) void gemm_kernel(
    const float* __restrict__ A, int lda, const float* __restrict__ B,
    float* __restrict__ C, int ldc, __half* __restrict__ C16)
{
    constexpr int BM = 128, BK = 32;
    __shared__ float sAT[BK][BM + 1];
    __shared__ float sB[BK][BN];
    int t = threadIdx.x, head = blockIdx.y, i0 = blockIdx.x * BM;
    const float* Bh = B + (size_t)head * FIN * BN;
    int tx = t & 15, ty = t >> 4;
    float acc[8][MN];
#pragma unroll
    for (int r = 0; r < 8; r++)
#pragma unroll
        for (int c = 0; c < MN; c++) acc[r][c] = 0.f;
    for (int k0 = 0; k0 < FIN; k0 += BK) {
        __syncthreads();
#pragma unroll
        for (int i = 0; i < (BM * BK) / 256; i++) {
            int l = t + i * 256, r = l >> 5, c = l & 31;
            sAT[c][r] = A[(size_t)(i0 + r) * lda + k0 + c];
        }
#pragma unroll
        for (int i = 0; i < (BK * BN) / 256; i++) {
            int l = t + i * 256, r = l / BN, c = l % BN;
            sB[r][c] = Bh[(size_t)(k0 + r) * BN + c];
        }
        __syncthreads();
#pragma unroll 8
        for (int kk = 0; kk < BK; kk++) {
            float a[8];
#pragma unroll
            for (int r = 0; r < 8; r++) a[r] = sAT[kk][ty * 8 + r];
            float b[MN];
#pragma unroll
            for (int c = 0; c < MN; c++) b[c] = sB[kk][tx * MN + c];
#pragma unroll
            for (int r = 0; r < 8; r++)
#pragma unroll
                for (int c = 0; c < MN; c++) acc[r][c] += a[r] * b[c];
        }
    }
#pragma unroll
    for (int r = 0; r < 8; r++) {
        int i = i0 + ty * 8 + r;
#pragma unroll
        for (int c = 0; c < MN; c++) {
            float v = acc[r][c];
            C[(size_t)i * ldc + head * BN + tx * MN + c] = v;
            if (WR16)
                C16[(size_t)i * ldc + head * BN + tx * MN + c] = __float2half(v);
        }
    }
}

__global__ void s_heads_kernel(const float* __restrict__ a_heads) {
    int gw = blockIdx.x * 8 + (threadIdx.x >> 5);
    int lane = threadIdx.x & 31;
    int i = gw >> 3, h = gw & 7;
    if (i >= N) return;
    const __half* wh = g_Wh16 + (size_t)i * FIN + h * KH;
    const float* a  = a_heads + (size_t)h * 2 * KH;
    float w0 = __half2float(wh[lane]);
    float w1 = __half2float(wh[lane + 32]);
    float v1 = w0 * a[lane]      + w1 * a[lane + 32];
    float v2 = w0 * a[KH + lane] + w1 * a[KH + lane + 32];
#pragma unroll
    for (int o = 16; o; o >>= 1) {
        v1 += __shfl_down_sync(0xffffffffu, v1, o);
        v2 += __shfl_down_sync(0xffffffffu, v2, o);
    }
    if (lane == 0) {
        g_E1[h * N + i] = __expf(v1);
        g_F1[h * N + i] = __expf(0.2f * v1);
        g_E2h[h * N + i] = __float2half(__expf(v2));
        g_F2h[h * N + i] = __float2half(__expf(0.2f * v2));
    }
}

__global__ void s_out_kernel(const float* __restrict__ a_out) {
    int gw = blockIdx.x * 8 + (threadIdx.x >> 5);
    int lane = threadIdx.x & 31;
    if (gw >= N) return;
    float v1 = 0.f, v2 = 0.f;
    if (lane < NCLS) {
        float w = g_Whout[(size_t)gw * NCLS + lane];
        v1 = w * a_out[lane];
        v2 = w * a_out[NCLS + lane];
    }
#pragma unroll
    for (int o = 16; o; o >>= 1) {
        v1 += __shfl_down_sync(0xffffffffu, v1, o);
        v2 += __shfl_down_sync(0xffffffffu, v2, o);
    }
    if (lane == 0) {
        g_E1o[gw] = __expf(v1);
        g_F1o[gw] = __expf(0.2f * v1);
        g_E2oh[gw] = __float2half(__expf(v2));
        g_F2oh[gw] = __float2half(__expf(0.2f * v2));
    }
}

__global__ void finalize_kernel(float* __restrict__ Out) {
    int i = blockIdx.x * 256 + threadIdx.x;
    if (i >= N * NCLS) return;
    float v = g_numO[i] / g_denO[i >> 4];
    Out[i] = (v > 0.f) ? v : expm1f(v);
}

// ============ attention: direct-fragment P-gen, HMMA, cp.async x3 ============
template<int NC, bool SPLIT>
__global__ __launch_bounds__(256, 3) void attn_hmma(
    const float* __restrict__ E1g, const float* __restrict__ F1g,
    const __half* __restrict__ E2g, const __half* __restrict__ F2g,
    const __half* __restrict__ Bg, int ldb,
    float* __restrict__ Out, int ldo)
{
    extern __shared__ char rawsm[];
    uint32_t rawu = smem_u32(rawsm);
    uint32_t base = (rawu + 1023) & ~1023u;
    uint32_t sbb = base + OFF_SB;
    uint32_t se2b = base + OFF_SE2, sf2b = base + OFF_SF2;
    uint32_t smb = base + OFF_SM;

    int t = threadIdx.x, warp = t >> 5, lane = t & 31;
    int head  = SPLIT ? 0 : blockIdx.y;
    int jbase = SPLIT ? blockIdx.y * (N / 8) : 0;
    constexpr int NSTEP = SPLIT ? (N / 8) / 128 : N / 128;
    int i0 = blockIdx.x * 128;
    int bcol = (NC == 64) ? head * 64 : 0;
    int wbase0 = jbase >> 5;

    int l16 = lane & 15, lhi = lane >> 4;
    // fragment rows owned by this thread: r0l and r0l+8 (warp owns 16 rows)
    int r0l = warp * 16 + (lane >> 2);
    int c0 = (lane & 3) * 2;   // fragment k-col pair base within 16-col chunk
    uint32_t e1r0, f1r0, e1r1, f1r1;
    {
        float a = E1g[head * N + i0 + r0l];
        float b = E1g[head * N + i0 + r0l + 8];
        float c = F1g[head * N + i0 + r0l];
        float d = F1g[head * N + i0 + r0l + 8];
        __half2 ha = __float2half2_rn(a); e1r0 = *(uint32_t*)&ha;
        __half2 hb = __float2half2_rn(b); e1r1 = *(uint32_t*)&hb;
        __half2 hc = __float2half2_rn(c); f1r0 = *(uint32_t*)&hc;
        __half2 hd = __float2half2_rn(d); f1r1 = *(uint32_t*)&hd;
    }

    // B loader
    constexpr int NCH = 128 * NC / 8;
    constexpr int CPT = NCH / 256;
    const __half* bsrc[CPT];
    uint32_t bofs[CPT];
#pragma unroll
    for (int i = 0; i < CPT; i++) {
        int ch = t + i * 256;
        int br = ch / (NC / 8), bc = ch % (NC / 8);
        bsrc[i] = Bg + (size_t)(jbase + br) * ldb + bcol + bc * 8;
        bofs[i] = sbb + SWZ128((uint32_t)(br * 128 + bc * 16));
    }
    const __half* e2base = E2g + head * N + jbase;
    const __half* f2base = F2g + head * N + jbase;

    uint32_t bbase = (uint32_t)(l16 * 128 + lhi * 16);
    uint32_t ones0 = (lane < 4) ? 0x3C003C00u : 0u;

    float acc[NC / 8][4];
#pragma unroll
    for (int n = 0; n < NC / 8; n++)
#pragma unroll
        for (int q = 0; q < 4; q++) acc[n][q] = 0.f;
    float accd[4] = {0.f, 0.f, 0.f, 0.f};

    // mask loader src (t<128): q-th word-plane, 4 rows per 16B chunk
    int mq = t >> 5, ms = t & 31;
    const uint32_t* msrc = g_bitsT + (size_t)mq * N + i0 + ms * 4;

    auto issue = [&](int s, int buf) {
        int j0 = s * 128;
#pragma unroll
        for (int i = 0; i < CPT; i++)
            cpasync16(bofs[i] + buf * 16384, bsrc[i] + (size_t)j0 * ldb);
        if (t < 128)
            cpasync16(smb + buf * 2048 + mq * 512 + ms * 16,
                      msrc + (size_t)(wbase0 + s * 4) * N);
        else if (t < 144)
            cpasync16(se2b + buf * 256 + (t - 128) * 16, e2base + j0 + (t - 128) * 8);
        else if (t < 160)
            cpasync16(sf2b + buf * 256 + (t - 144) * 16, f2base + j0 + (t - 144) * 8);
    };

    issue(0, 0); cpcommit();
    issue(1, 1); cpcommit();

#pragma unroll 1
    for (int step = 0; step < NSTEP; step++) {
        int buf = step % 3;
        cpwait1();
        __syncthreads();
        if (step + 2 < NSTEP) issue(step + 2, (step + 2) % 3);
        cpcommit();

        uint32_t peb = se2b + buf * 256;
        uint32_t pfb = sf2b + buf * 256;
        uint32_t pmb = smb + buf * 2048 + r0l * 4;
        uint32_t pbb = sbb + buf * 16384;
#pragma unroll
        for (int kc = 0; kc < 8; kc++) {
            // adjacency words for this thread's two rows (plane kc>>1)
            uint32_t wr0 = lds32(pmb + (kc >> 1) * 512);
            uint32_t wr1 = lds32(pmb + (kc >> 1) * 512 + 32);
            // E2/F2 half2 pairs at cols (c0,c0+1) and (c0+8,c0+9)
            uint32_t e2lo = lds32(peb + kc * 32 + c0 * 2);
            uint32_t e2hi = lds32(peb + kc * 32 + c0 * 2 + 16);
            uint32_t f2lo = lds32(pfb + kc * 32 + c0 * 2);
            uint32_t f2hi = lds32(pfb + kc * 32 + c0 * 2 + 16);
            uint32_t sh = (uint32_t)((kc & 1) * 16 + c0);
            uint32_t a0 = fragP(e1r0, f1r0, e2lo, f2lo, (wr0 >> sh) & 3u);
            uint32_t a1 = fragP(e1r1, f1r1, e2lo, f2lo, (wr1 >> sh) & 3u);
            uint32_t a2 = fragP(e1r0, f1r0, e2hi, f2hi, (wr0 >> (sh + 8)) & 3u);
            uint32_t a3 = fragP(e1r1, f1r1, e2hi, f2hi, (wr1 >> (sh + 8)) & 3u);

            mma16816(accd, a0, a1, a2, a3, ones0, ones0);   // denominator
#pragma unroll
            for (int np = 0; np < NC / 16; np++) {
                uint32_t b0, b1, b2, b3;
                ldsm4t(b0, b1, b2, b3, pbb + SWZ128(bbase + kc * 2048 + np * 32));
                mma16816(acc[2 * np],     a0, a1, a2, a3, b0, b1);
                mma16816(acc[2 * np + 1], a0, a1, a2, a3, b2, b3);
            }
        }
    }

    int r0 = r0l;
    if constexpr (SPLIT) {
        if ((lane & 3) == 0) {
            atomicAdd(&g_denO[i0 + r0],     accd[0]);
            atomicAdd(&g_denO[i0 + r0 + 8], accd[2]);
        }
#pragma unroll
        for (int nt = 0; nt < NC / 8; nt++) {
            atomicAdd(&g_numO[(i0 + r0) * NCLS + nt * 8 + c0],     acc[nt][0]);
            atomicAdd(&g_numO[(i0 + r0) * NCLS + nt * 8 + c0 + 1], acc[nt][1]);
            atomicAdd(&g_numO[(i0 + r0 + 8) * NCLS + nt * 8 + c0],     acc[nt][2]);
            atomicAdd(&g_numO[(i0 + r0 + 8) * NCLS + nt * 8 + c0 + 1], acc[nt][3]);
        }
    } else {
        float den0 = __shfl_sync(0xffffffffu, accd[0], lane & 0x1C);
        float den1 = __shfl_sync(0xffffffffu, accd[2], lane & 0x1C);
        float inv0 = 1.0f / den0, inv1 = 1.0f / den1;
        float* o0 = Out + (size_t)(i0 + r0) * ldo + bcol + c0;
        float* o1 = o0 + 8 * ldo;
#pragma unroll
        for (int nt = 0; nt < NC / 8; nt++) {
            *(float2*)(o0 + nt * 8) = make_float2(acc[nt][0] * inv0, acc[nt][1] * inv0);
            *(float2*)(o1 + nt * 8) = make_float2(acc[nt][2] * inv1, acc[nt][3] * inv1);
        }
    }
}

extern "C" void kernel_launch(void* const* d_in, const int* in_sizes, int n_in,
                              void* d_out, int out_size)
{
    const float* x = nullptr;
    const int* adj = nullptr;
    const float *W_heads = nullptr, *a_heads = nullptr, *W_out = nullptr, *a_out = nullptr;
    for (int i = 0; i < n_in; i++) {
        switch (in_sizes[i]) {
            case N * FIN:      x       = (const float*)d_in[i]; break;
            case 67108864:     adj     = (const int*)  d_in[i]; break;
            case H * FIN * KH: W_heads = (const float*)d_in[i]; break;
            case H * 2 * KH:   a_heads = (const float*)d_in[i]; break;
            case FIN * NCLS:   W_out   = (const float*)d_in[i]; break;
            case 2 * NCLS:     a_out   = (const float*)d_in[i]; break;
        }
    }

    float *hP, *whoP, *e1P, *f1P, *e1oP, *f1oP, *numP, *denP;
    __half *wh16P, *who16P, *e2hP, *f2hP, *e2ohP, *f2ohP;
    cudaGetSymbolAddress((void**)&wh16P, g_Wh16);
    cudaGetSymbolAddress((void**)&hP,    g_h);
    cudaGetSymbolAddress((void**)&whoP,  g_Whout);
    cudaGetSymbolAddress((void**)&who16P, g_Whout16);
    cudaGetSymbolAddress((void**)&e1P,  g_E1);
    cudaGetSymbolAddress((void**)&f1P,  g_F1);
    cudaGetSymbolAddress((void**)&e2hP, g_E2h);
    cudaGetSymbolAddress((void**)&f2hP, g_F2h);
    cudaGetSymbolAddress((void**)&e1oP, g_E1o);
    cudaGetSymbolAddress((void**)&f1oP, g_F1o);
    cudaGetSymbolAddress((void**)&e2ohP, g_E2oh);
    cudaGetSymbolAddress((void**)&f2ohP, g_F2oh);
    cudaGetSymbolAddress((void**)&numP, g_numO);
    cudaGetSymbolAddress((void**)&denP, g_denO);

    cudaFuncSetAttribute(attn_hmma<64, false>,
                         cudaFuncAttributeMaxDynamicSharedMemorySize, ATT_DSMEM);
    cudaFuncSetAttribute(attn_hmma<16, true>,
                         cudaFuncAttributeMaxDynamicSharedMemorySize, ATT_DSMEM);
    cudaFuncSetAttribute(gemm_hmma_kernel,
                         cudaFuncAttributeMaxDynamicSharedMemorySize, GEMM_DSMEM);

    pack_adj_kernel<<<4096, 256>>>(adj);
    convert16_kernel<<<2048, 256>>>(x, W_heads);
    gemm_hmma_kernel<<<dim3(N / 128, H), 256, GEMM_DSMEM>>>();
    s_heads_kernel<<<(N * H) / 8, 256>>>(a_heads);
    cudaMemsetAsync(numP, 0, N * NCLS * sizeof(float));
    cudaMemsetAsync(denP, 0, N * sizeof(float));
    attn_hmma<64, false><<<dim3(N / 128, H), 256, ATT_DSMEM>>>(
        e1P, f1P, e2hP, f2hP, wh16P, FIN, hP, FIN);
    gemm_kernel<16, 1, true><<<dim3(N / 128, 1), 256>>>(hP, FIN, W_out, whoP, NCLS, who16P);
    s_out_kernel<<<N / 8, 256>>>(a_out);
    attn_hmma<16, true><<<dim3(N / 128, 8), 256, ATT_DSMEM>>>(
        e1oP, f1oP, e2ohP, f2ohP, who16P, NCLS, nullptr, NCLS);
    finalize_kernel<<<(N * NCLS + 255) / 256, 256>>>((float*)d_out);
}

// round 11
// speedup vs baseline: 5.7057x; 1.0233x over previous
#include <cuda_runtime.h>
#include <cuda_fp16.h>
#include <cstdint>
#include <math.h>

#define N    8192
#define NW   (N/32)
#define FIN  512
#define KH   64
#define H    8
#define NCLS 16
#define NSPL1 4          // j-splits for layer-1 attention

__device__ uint32_t g_bitsT[NW * N];
__device__ __half   g_x16  [N * FIN];
__device__ __half   g_W16  [H * FIN * KH];
__device__ __half   g_Wh16 [N * FIN];
__device__ float    g_h    [N * FIN];
__device__ float    g_Whout[N * NCLS];
__device__ __half   g_Whout16[N * NCLS];
__device__ float    g_E1[H * N], g_F1[H * N];
__device__ __half   g_E2h[H * N], g_F2h[H * N];
__device__ float    g_E1o[N], g_F1o[N];
__device__ __half   g_E2oh[N], g_F2oh[N];
__device__ float    g_numO[N * NCLS];
__device__ float    g_denO[N];
__device__ float    g_part1[NSPL1 * N * FIN];   // 64 MB partial numerators
__device__ float    g_dpart1[NSPL1 * H * N];    // partial denominators

#define SWZ128(o) ((o) ^ (((o) >> 3) & 0x70))

// attn dyn smem: sB 3x16KB | sE2 3x256B | sF2 3x256B | sMask 3x2KB
#define OFF_SB   0
#define OFF_SE2  49152
#define OFF_SF2  49920
#define OFF_SM   50688
#define ATT_DSMEM (56832 + 1024)
// gemm dyn smem: sA 3x16KB | sB 3x8KB
#define GOFF_SB  49152
#define GEMM_DSMEM (73728 + 1024)

__device__ __forceinline__ uint32_t smem_u32(const void* p) {
    return (uint32_t)__cvta_generic_to_shared(p);
}
__device__ __forceinline__ void cpasync16(uint32_t dst, const void* src) {
    asm volatile("cp.async.cg.shared.global [%0], [%1], 16;" :: "r"(dst), "l"(src));
}
__device__ __forceinline__ void cpcommit() {
    asm volatile("cp.async.commit_group;");
}
__device__ __forceinline__ void cpwait1() {
    asm volatile("cp.async.wait_group 1;");
}
__device__ __forceinline__ uint32_t lds32(uint32_t addr) {
    uint32_t v;
    asm volatile("ld.shared.b32 %0, [%1];" : "=r"(v) : "r"(addr));
    return v;
}
__device__ __forceinline__ void ldsm4(uint32_t& r0, uint32_t& r1, uint32_t& r2,
                                      uint32_t& r3, uint32_t a) {
    asm volatile("ldmatrix.sync.aligned.m8n8.x4.shared.b16 {%0,%1,%2,%3}, [%4];"
                 : "=r"(r0), "=r"(r1), "=r"(r2), "=r"(r3) : "r"(a));
}
__device__ __forceinline__ void ldsm4t(uint32_t& r0, uint32_t& r1, uint32_t& r2,
                                       uint32_t& r3, uint32_t a) {
    asm volatile("ldmatrix.sync.aligned.m8n8.x4.trans.shared.b16 {%0,%1,%2,%3}, [%4];"
                 : "=r"(r0), "=r"(r1), "=r"(r2), "=r"(r3) : "r"(a));
}
__device__ __forceinline__ void mma16816(float* d, uint32_t a0, uint32_t a1,
                                         uint32_t a2, uint32_t a3,
                                         uint32_t b0, uint32_t b1) {
    asm volatile(
        "mma.sync.aligned.m16n8k16.row.col.f32.f16.f16.f32 "
        "{%0,%1,%2,%3}, {%4,%5,%6,%7}, {%8,%9}, {%0,%1,%2,%3};"
        : "+f"(d[0]), "+f"(d[1]), "+f"(d[2]), "+f"(d[3])
        : "r"(a0), "r"(a1), "r"(a2), "r"(a3), "r"(b0), "r"(b1));
}
__device__ __forceinline__ uint32_t fragP(uint32_t e1, uint32_t f1,
                                          uint32_t e2, uint32_t f2, uint32_t bits) {
    __half2 pe = __hmul2(*(__half2*)&e1, *(__half2*)&e2);
    __half2 pf = __hmul2(*(__half2*)&f1, *(__half2*)&f2);
    __half2 pm = __hmax2(pe, pf);
    uint32_t m = (bits & 1u) * 0xFFFFu + (bits & 2u) * 0x7FFF8000u;
    return (*(uint32_t*)&pm) & m;
}

__global__ void pack_adj_kernel(const int* __restrict__ adj) {
    int warps = gridDim.x * (blockDim.x >> 5);
    int gw    = blockIdx.x * (blockDim.x >> 5) + (threadIdx.x >> 5);
    int lane  = threadIdx.x & 31;
    const int total = N * NW;
    for (int w = gw; w < total; w += warps) {
        int v = adj[(size_t)w * 32 + lane];
        unsigned m = __ballot_sync(0xffffffffu, v > 0);
        if (lane == 0) g_bitsT[(size_t)(w & (NW - 1)) * N + (w >> 8)] = m;
    }
}

__global__ void convert16_kernel(const float* __restrict__ x,
                                 const float* __restrict__ W_heads) {
    int stride = gridDim.x * blockDim.x;
    int tid = blockIdx.x * blockDim.x + threadIdx.x;
    for (int i = tid; i < (N * FIN) / 4; i += stride) {
        float4 v = *((const float4*)x + i);
        *((__half2*)g_x16 + i * 2)     = __floats2half2_rn(v.x, v.y);
        *((__half2*)g_x16 + i * 2 + 1) = __floats2half2_rn(v.z, v.w);
    }
    for (int i = tid; i < (H * FIN * KH) / 4; i += stride) {
        float4 v = *((const float4*)W_heads + i);
        *((__half2*)g_W16 + i * 2)     = __floats2half2_rn(v.x, v.y);
        *((__half2*)g_W16 + i * 2 + 1) = __floats2half2_rn(v.z, v.w);
    }
}

// ---------------- layer-1 feature GEMM on HMMA ----------------
__global__ __launch_bounds__(256, 2) void gemm_hmma_kernel()
{
    extern __shared__ char rawsm[];
    uint32_t rawu = smem_u32(rawsm);
    uint32_t base = (rawu + 1023) & ~1023u;
    uint32_t sab = base, sbb = base + GOFF_SB;

    int t = threadIdx.x, warp = t >> 5, lane = t & 31;
    int head = blockIdx.y, i0 = blockIdx.x * 128;
    int l16 = lane & 15, lhi = lane >> 4;
    int row = warp * 16 + l16;

    const __half* asrc[4];
    uint32_t aofs_[4];
#pragma unroll
    for (int i = 0; i < 4; i++) {
        int ch = t + i * 256, r = ch >> 3, c8 = ch & 7;
        asrc[i]  = g_x16 + (size_t)(i0 + r) * FIN + c8 * 8;
        aofs_[i] = sab + SWZ128((uint32_t)(r * 128 + c8 * 16));
    }
    const __half* bsrc[2];
    uint32_t bofs_[2];
#pragma unroll
    for (int i = 0; i < 2; i++) {
        int ch = t + i * 256, r = ch >> 3, c8 = ch & 7;
        bsrc[i]  = g_W16 + (size_t)head * FIN * KH + r * KH + c8 * 8;
        bofs_[i] = sbb + SWZ128((uint32_t)(r * 128 + c8 * 16));
    }

    uint32_t alin  = (uint32_t)(row * 128 + lhi * 16);
    uint32_t bbase = (uint32_t)(l16 * 128 + lhi * 16);

    float acc[8][4];
#pragma unroll
    for (int n = 0; n < 8; n++)
#pragma unroll
        for (int q = 0; q < 4; q++) acc[n][q] = 0.f;

    auto issue = [&](int s, int buf) {
        int k0 = s * 64;
#pragma unroll
        for (int i = 0; i < 4; i++)
            cpasync16(aofs_[i] + buf * 16384, asrc[i] + k0);
#pragma unroll
        for (int i = 0; i < 2; i++)
            cpasync16(bofs_[i] + buf * 8192, bsrc[i] + (size_t)k0 * KH);
    };

    issue(0, 0); cpcommit();
    issue(1, 1); cpcommit();

    constexpr int NSTEP = FIN / 64;
#pragma unroll 1
    for (int step = 0; step < NSTEP; step++) {
        int buf = step % 3;
        cpwait1();
        __syncthreads();
        if (step + 2 < NSTEP) issue(step + 2, (step + 2) % 3);
        cpcommit();

        uint32_t pab = sab + buf * 16384;
        uint32_t pbb = sbb + buf * 8192;
#pragma unroll
        for (int kc = 0; kc < 4; kc++) {
            uint32_t a0, a1, a2, a3;
            ldsm4(a0, a1, a2, a3, pab + SWZ128(alin + kc * 32));
#pragma unroll
            for (int np = 0; np < 4; np++) {
                uint32_t b0, b1, b2, b3;
                ldsm4t(b0, b1, b2, b3, pbb + SWZ128(bbase + kc * 2048 + np * 32));
                mma16816(acc[2 * np],     a0, a1, a2, a3, b0, b1);
                mma16816(acc[2 * np + 1], a0, a1, a2, a3, b2, b3);
            }
        }
    }

    int r0 = warp * 16 + (lane >> 2), c0 = (lane & 3) * 2;
    __half* o0 = g_Wh16 + (size_t)(i0 + r0) * FIN + head * KH + c0;
    __half* o1 = o0 + 8 * FIN;
#pragma unroll
    for (int nt = 0; nt < 8; nt++) {
        *(__half2*)(o0 + nt * 8) = __floats2half2_rn(acc[nt][0], acc[nt][1]);
        *(__half2*)(o1 + nt * 8) = __floats2half2_rn(acc[nt][2], acc[nt][3]);
    }
}

// ---------------- fp32 feature GEMM (layer-2 only) ----------------
template<int BN, int MN, bool WR16>
__global__ __launch_bounds__(256) void gemm_kernel(
    const float* __restrict__ A, int lda, const float* __restrict__ B,
    float* __restrict__ C, int ldc, __half* __restrict__ C16)
{
    constexpr int BM = 128, BK = 32;
    __shared__ float sAT[BK][BM + 1];
    __shared__ float sB[BK][BN];
    int t = threadIdx.x, head = blockIdx.y, i0 = blockIdx.x * BM;
    const float* Bh = B + (size_t)head * FIN * BN;
    int tx = t & 15, ty = t >> 4;
    float acc[8][MN];
#pragma unroll
    for (int r = 0; r < 8; r++)
#pragma unroll
        for (int c = 0; c < MN; c++) acc[r][c] = 0.f;
    for (int k0 = 0; k0 < FIN; k0 += BK) {
        __syncthreads();
#pragma unroll
        for (int i = 0; i < (BM * BK) / 256; i++) {
            int l = t + i * 256, r = l >> 5, c = l & 31;
            sAT[c][r] = A[(size_t)(i0 + r) * lda + k0 + c];
        }
#pragma unroll
        for (int i = 0; i < (BK * BN) / 256; i++) {
            int l = t + i * 256, r = l / BN, c = l % BN;
            sB[r][c] = Bh[(size_t)(k0 + r) * BN + c];
        }
        __syncthreads();
#pragma unroll 8
        for (int kk = 0; kk < BK; kk++) {
            float a[8];
#pragma unroll
            for (int r = 0; r < 8; r++) a[r] = sAT[kk][ty * 8 + r];
            float b[MN];
#pragma unroll
            for (int c = 0; c < MN; c++) b[c] = sB[kk][tx * MN + c];
#pragma unroll
            for (int r = 0; r < 8; r++)
#pragma unroll
                for (int c = 0; c < MN; c++) acc[r][c] += a[r] * b[c];
        }
    }
#pragma unroll
    for (int r = 0; r < 8; r++) {
        int i = i0 + ty * 8 + r;
#pragma unroll
        for (int c = 0; c < MN; c++) {
            float v = acc[r][c];
            C[(size_t)i * ldc + head * BN + tx * MN + c] = v;
            if (WR16)
                C16[(size_t)i * ldc + head * BN + tx * MN + c] = __float2half(v);
        }
    }
}

__global__ void s_heads_kernel(const float* __restrict__ a_heads) {
    int gw = blockIdx.x * 8 + (threadIdx.x >> 5);
    int lane = threadIdx.x & 31;
    int i = gw >> 3, h = gw & 7;
    if (i >= N) return;
    const __half* wh = g_Wh16 + (size_t)i * FIN + h * KH;
    const float* a  = a_heads + (size_t)h * 2 * KH;
    float w0 = __half2float(wh[lane]);
    float w1 = __half2float(wh[lane + 32]);
    float v1 = w0 * a[lane]      + w1 * a[lane + 32];
    float v2 = w0 * a[KH + lane] + w1 * a[KH + lane + 32];
#pragma unroll
    for (int o = 16; o; o >>= 1) {
        v1 += __shfl_down_sync(0xffffffffu, v1, o);
        v2 += __shfl_down_sync(0xffffffffu, v2, o);
    }
    if (lane == 0) {
        g_E1[h * N + i] = __expf(v1);
        g_F1[h * N + i] = __expf(0.2f * v1);
        g_E2h[h * N + i] = __float2half(__expf(v2));
        g_F2h[h * N + i] = __float2half(__expf(0.2f * v2));
    }
}

__global__ void s_out_kernel(const float* __restrict__ a_out) {
    int gw = blockIdx.x * 8 + (threadIdx.x >> 5);
    int lane = threadIdx.x & 31;
    if (gw >= N) return;
    float v1 = 0.f, v2 = 0.f;
    if (lane < NCLS) {
        float w = g_Whout[(size_t)gw * NCLS + lane];
        v1 = w * a_out[lane];
        v2 = w * a_out[NCLS + lane];
    }
#pragma unroll
    for (int o = 16; o; o >>= 1) {
        v1 += __shfl_down_sync(0xffffffffu, v1, o);
        v2 += __shfl_down_sync(0xffffffffu, v2, o);
    }
    if (lane == 0) {
        g_E1o[gw] = __expf(v1);
        g_F1o[gw] = __expf(0.2f * v1);
        g_E2oh[gw] = __float2half(__expf(v2));
        g_F2oh[gw] = __float2half(__expf(0.2f * v2));
    }
}

// ---- layer-1 finalize: g_h = (sum_z part[z]) / (sum_z den[z]) ----
__global__ void finalize1_kernel() {
    int idx = blockIdx.x * 256 + threadIdx.x;
    if (idx >= N * FIN) return;
    int i = idx >> 9, head = (idx & 511) >> 6;
    float num = 0.f, den = 0.f;
#pragma unroll
    for (int z = 0; z < NSPL1; z++) {
        num += g_part1[(size_t)z * N * FIN + idx];
        den += g_dpart1[(z * H + head) * N + i];
    }
    g_h[idx] = num / den;
}

__global__ void finalize_kernel(float* __restrict__ Out) {
    int i = blockIdx.x * 256 + threadIdx.x;
    if (i >= N * NCLS) return;
    float v = g_numO[i] / g_denO[i >> 4];
    Out[i] = (v > 0.f) ? v : expm1f(v);
}

// ============ attention: direct-fragment P-gen, HMMA, j-split ============
// NSPL splits along j (blockIdx.z). ATOMIC: accumulate via global atomics
// (layer-2); else write partial num/den to g_part1/g_dpart1 (layer-1).
template<int NC, int NSPL, bool ATOMIC>
__global__ __launch_bounds__(256, 3) void attn_hmma(
    const float* __restrict__ E1g, const float* __restrict__ F1g,
    const __half* __restrict__ E2g, const __half* __restrict__ F2g,
    const __half* __restrict__ Bg, int ldb)
{
    extern __shared__ char rawsm[];
    uint32_t rawu = smem_u32(rawsm);
    uint32_t base = (rawu + 1023) & ~1023u;
    uint32_t sbb = base + OFF_SB;
    uint32_t se2b = base + OFF_SE2, sf2b = base + OFF_SF2;
    uint32_t smb = base + OFF_SM;

    int t = threadIdx.x, warp = t >> 5, lane = t & 31;
    int head  = blockIdx.y;
    int zspl  = blockIdx.z;
    int jbase = zspl * (N / NSPL);
    constexpr int NSTEP = (N / NSPL) / 128;
    int i0 = blockIdx.x * 128;
    int bcol = (NC == 64) ? head * 64 : 0;
    int wbase0 = jbase >> 5;

    int l16 = lane & 15, lhi = lane >> 4;
    int r0l = warp * 16 + (lane >> 2);
    int c0 = (lane & 3) * 2;
    uint32_t e1r0, f1r0, e1r1, f1r1;
    {
        float a = E1g[head * N + i0 + r0l];
        float b = E1g[head * N + i0 + r0l + 8];
        float c = F1g[head * N + i0 + r0l];
        float d = F1g[head * N + i0 + r0l + 8];
        __half2 ha = __float2half2_rn(a); e1r0 = *(uint32_t*)&ha;
        __half2 hb = __float2half2_rn(b); e1r1 = *(uint32_t*)&hb;
        __half2 hc = __float2half2_rn(c); f1r0 = *(uint32_t*)&hc;
        __half2 hd = __float2half2_rn(d); f1r1 = *(uint32_t*)&hd;
    }

    constexpr int NCH = 128 * NC / 8;
    constexpr int CPT = NCH / 256;
    const __half* bsrc[CPT];
    uint32_t bofs[CPT];
#pragma unroll
    for (int i = 0; i < CPT; i++) {
        int ch = t + i * 256;
        int br = ch / (NC / 8), bc = ch % (NC / 8);
        bsrc[i] = Bg + (size_t)(jbase + br) * ldb + bcol + bc * 8;
        bofs[i] = sbb + SWZ128((uint32_t)(br * 128 + bc * 16));
    }
    const __half* e2base = E2g + head * N + jbase;
    const __half* f2base = F2g + head * N + jbase;

    uint32_t bbase = (uint32_t)(l16 * 128 + lhi * 16);
    uint32_t ones0 = (lane < 4) ? 0x3C003C00u : 0u;

    float acc[NC / 8][4];
#pragma unroll
    for (int n = 0; n < NC / 8; n++)
#pragma unroll
        for (int q = 0; q < 4; q++) acc[n][q] = 0.f;
    float accd[4] = {0.f, 0.f, 0.f, 0.f};

    int mq = t >> 5, ms = t & 31;
    const uint32_t* msrc = g_bitsT + (size_t)mq * N + i0 + ms * 4;

    auto issue = [&](int s, int buf) {
        int j0 = s * 128;
#pragma unroll
        for (int i = 0; i < CPT; i++)
            cpasync16(bofs[i] + buf * 16384, bsrc[i] + (size_t)j0 * ldb);
        if (t < 128)
            cpasync16(smb + buf * 2048 + mq * 512 + ms * 16,
                      msrc + (size_t)(wbase0 + s * 4) * N);
        else if (t < 144)
            cpasync16(se2b + buf * 256 + (t - 128) * 16, e2base + j0 + (t - 128) * 8);
        else if (t < 160)
            cpasync16(sf2b + buf * 256 + (t - 144) * 16, f2base + j0 + (t - 144) * 8);
    };

    issue(0, 0); cpcommit();
    if (NSTEP > 1) issue(1, 1);
    cpcommit();

#pragma unroll 1
    for (int step = 0; step < NSTEP; step++) {
        int buf = step % 3;
        cpwait1();
        __syncthreads();
        if (step + 2 < NSTEP) issue(step + 2, (step + 2) % 3);
        cpcommit();

        uint32_t peb = se2b + buf * 256;
        uint32_t pfb = sf2b + buf * 256;
        uint32_t pmb = smb + buf * 2048 + r0l * 4;
        uint32_t pbb = sbb + buf * 16384;
#pragma unroll
        for (int kc = 0; kc < 8; kc++) {
            uint32_t wr0 = lds32(pmb + (kc >> 1) * 512);
            uint32_t wr1 = lds32(pmb + (kc >> 1) * 512 + 32);
            uint32_t e2lo = lds32(peb + kc * 32 + c0 * 2);
            uint32_t e2hi = lds32(peb + kc * 32 + c0 * 2 + 16);
            uint32_t f2lo = lds32(pfb + kc * 32 + c0 * 2);
            uint32_t f2hi = lds32(pfb + kc * 32 + c0 * 2 + 16);
            uint32_t sh = (uint32_t)((kc & 1) * 16 + c0);
            uint32_t a0 = fragP(e1r0, f1r0, e2lo, f2lo, (wr0 >> sh) & 3u);
            uint32_t a1 = fragP(e1r1, f1r1, e2lo, f2lo, (wr1 >> sh) & 3u);
            uint32_t a2 = fragP(e1r0, f1r0, e2hi, f2hi, (wr0 >> (sh + 8)) & 3u);
            uint32_t a3 = fragP(e1r1, f1r1, e2hi, f2hi, (wr1 >> (sh + 8)) & 3u);

            mma16816(accd, a0, a1, a2, a3, ones0, ones0);
#pragma unroll
            for (int np = 0; np < NC / 16; np++) {
                uint32_t b0, b1, b2, b3;
                ldsm4t(b0, b1, b2, b3, pbb + SWZ128(bbase + kc * 2048 + np * 32));
                mma16816(acc[2 * np],     a0, a1, a2, a3, b0, b1);
                mma16816(acc[2 * np + 1], a0, a1, a2, a3, b2, b3);
            }
        }
    }

    int r0 = r0l;
    if constexpr (ATOMIC) {
        if ((lane & 3) == 0) {
            atomicAdd(&g_denO[i0 + r0],     accd[0]);
            atomicAdd(&g_denO[i0 + r0 + 8], accd[2]);
        }
#pragma unroll
        for (int nt = 0; nt < NC / 8; nt++) {
            atomicAdd(&g_numO[(i0 + r0) * NCLS + nt * 8 + c0],     acc[nt][0]);
            atomicAdd(&g_numO[(i0 + r0) * NCLS + nt * 8 + c0 + 1], acc[nt][1]);
            atomicAdd(&g_numO[(i0 + r0 + 8) * NCLS + nt * 8 + c0],     acc[nt][2]);
            atomicAdd(&g_numO[(i0 + r0 + 8) * NCLS + nt * 8 + c0 + 1], acc[nt][3]);
        }
    } else {
        // partial store (no normalization) to split-private buffers
        if ((lane & 3) == 0) {
            g_dpart1[(zspl * H + head) * N + i0 + r0]     = accd[0];
            g_dpart1[(zspl * H + head) * N + i0 + r0 + 8] = accd[2];
        }
        float* po0 = g_part1 + (size_t)zspl * N * FIN
                   + (size_t)(i0 + r0) * FIN + bcol + c0;
        float* po1 = po0 + 8 * FIN;
#pragma unroll
        for (int nt = 0; nt < NC / 8; nt++) {
            *(float2*)(po0 + nt * 8) = make_float2(acc[nt][0], acc[nt][1]);
            *(float2*)(po1 + nt * 8) = make_float2(acc[nt][2], acc[nt][3]);
        }
    }
}

extern "C" void kernel_launch(void* const* d_in, const int* in_sizes, int n_in,
                              void* d_out, int out_size)
{
    const float* x = nullptr;
    const int* adj = nullptr;
    const float *W_heads = nullptr, *a_heads = nullptr, *W_out = nullptr, *a_out = nullptr;
    for (int i = 0; i < n_in; i++) {
        switch (in_sizes[i]) {
            case N * FIN:      x       = (const float*)d_in[i]; break;
            case 67108864:     adj     = (const int*)  d_in[i]; break;
            case H * FIN * KH: W_heads = (const float*)d_in[i]; break;
            case H * 2 * KH:   a_heads = (const float*)d_in[i]; break;
            case FIN * NCLS:   W_out   = (const float*)d_in[i]; break;
            case 2 * NCLS:     a_out   = (const float*)d_in[i]; break;
        }
    }

    float *hP, *whoP, *e1P, *f1P, *e1oP, *f1oP, *numP, *denP;
    __half *wh16P, *who16P, *e2hP, *f2hP, *e2ohP, *f2ohP;
    cudaGetSymbolAddress((void**)&wh16P, g_Wh16);
    cudaGetSymbolAddress((void**)&hP,    g_h);
    cudaGetSymbolAddress((void**)&whoP,  g_Whout);
    cudaGetSymbolAddress((void**)&who16P, g_Whout16);
    cudaGetSymbolAddress((void**)&e1P,  g_E1);
    cudaGetSymbolAddress((void**)&f1P,  g_F1);
    cudaGetSymbolAddress((void**)&e2hP, g_E2h);
    cudaGetSymbolAddress((void**)&f2hP, g_F2h);
    cudaGetSymbolAddress((void**)&e1oP, g_E1o);
    cudaGetSymbolAddress((void**)&f1oP, g_F1o);
    cudaGetSymbolAddress((void**)&e2ohP, g_E2oh);
    cudaGetSymbolAddress((void**)&f2ohP, g_F2oh);
    cudaGetSymbolAddress((void**)&numP, g_numO);
    cudaGetSymbolAddress((void**)&denP, g_denO);

    cudaFuncSetAttribute((const void*)attn_hmma<64, NSPL1, false>,
                         cudaFuncAttributeMaxDynamicSharedMemorySize, ATT_DSMEM);
    cudaFuncSetAttribute((const void*)attn_hmma<16, 16, true>,
                         cudaFuncAttributeMaxDynamicSharedMemorySize, ATT_DSMEM);
    cudaFuncSetAttribute(gemm_hmma_kernel,
                         cudaFuncAttributeMaxDynamicSharedMemorySize, GEMM_DSMEM);

    pack_adj_kernel<<<4096, 256>>>(adj);
    convert16_kernel<<<2048, 256>>>(x, W_heads);
    gemm_hmma_kernel<<<dim3(N / 128, H), 256, GEMM_DSMEM>>>();
    s_heads_kernel<<<(N * H) / 8, 256>>>(a_heads);
    cudaMemsetAsync(numP, 0, N * NCLS * sizeof(float));
    cudaMemsetAsync(denP, 0, N * sizeof(float));
    attn_hmma<64, NSPL1, false><<<dim3(N / 128, H, NSPL1), 256, ATT_DSMEM>>>(
        e1P, f1P, e2hP, f2hP, wh16P, FIN);
    finalize1_kernel<<<(N * FIN + 255) / 256, 256>>>();
    gemm_kernel<16, 1, true><<<dim3(N / 128, 1), 256>>>(hP, FIN, W_out, whoP, NCLS, who16P);
    s_out_kernel<<<N / 8, 256>>>(a_out);
    attn_hmma<16, 16, true><<<dim3(N / 128, 1, 16), 256, ATT_DSMEM>>>(
        e1oP, f1oP, e2ohP, f2ohP, who16P, NCLS);
    finalize_kernel<<<(N * NCLS + 255) / 256, 256>>>((float*)d_out);
}

// round 12
// speedup vs baseline: 6.3434x; 1.1118x over previous
#include <cuda_runtime.h>
#include <cuda_fp16.h>
#include <cstdint>
#include <math.h>

#define N    8192
#define NW   (N/32)
#define FIN  512
#define KH   64
#define H    8
#define NCLS 16
#define NSPL1 4

__device__ uint32_t g_bitsT[NW * N];
__device__ __half   g_x16  [N * FIN];
__device__ __half   g_W16  [H * FIN * KH];
__device__ __half   g_Wout16[FIN * NCLS];
__device__ __half   g_Wh16 [N * FIN];
__device__ __half   g_h16  [N * FIN];
__device__ float    g_Whout[N * NCLS];
__device__ __half   g_Whout16[N * NCLS];
__device__ float    g_G1[H * N];
__device__ __half   g_E2h[H * N], g_F2h[H * N];
__device__ float    g_G1o[N];
__device__ __half   g_E2oh[N], g_F2oh[N];
__device__ float    g_numO[N * NCLS];
__device__ float    g_denO[N];
__device__ float    g_part1[NSPL1 * N * FIN];
__device__ float    g_dpart1[NSPL1 * H * N];

#define SWZ128(o) ((o) ^ (((o) >> 3) & 0x70))

// attn dyn smem: sB 3x16KB | sE2 3x256B | sF2 3x256B | sMask 3x2KB
#define OFF_SB   0
#define OFF_SE2  49152
#define OFF_SF2  49920
#define OFF_SM   50688
#define ATT_DSMEM (56832 + 1024)
// gemm dyn smem: sA 3x16KB | sB 3x8KB
#define GOFF_SB  49152
#define GEMM_DSMEM (73728 + 1024)

__device__ __forceinline__ uint32_t smem_u32(const void* p) {
    return (uint32_t)__cvta_generic_to_shared(p);
}
__device__ __forceinline__ void cpasync16(uint32_t dst, const void* src) {
    asm volatile("cp.async.cg.shared.global [%0], [%1], 16;" :: "r"(dst), "l"(src));
}
__device__ __forceinline__ void cpcommit() {
    asm volatile("cp.async.commit_group;");
}
__device__ __forceinline__ void cpwait1() {
    asm volatile("cp.async.wait_group 1;");
}
__device__ __forceinline__ uint32_t lds32(uint32_t addr) {
    uint32_t v;
    asm volatile("ld.shared.b32 %0, [%1];" : "=r"(v) : "r"(addr));
    return v;
}
__device__ __forceinline__ void ldsm4(uint32_t& r0, uint32_t& r1, uint32_t& r2,
                                      uint32_t& r3, uint32_t a) {
    asm volatile("ldmatrix.sync.aligned.m8n8.x4.shared.b16 {%0,%1,%2,%3}, [%4];"
                 : "=r"(r0), "=r"(r1), "=r"(r2), "=r"(r3) : "r"(a));
}
__device__ __forceinline__ void ldsm4t(uint32_t& r0, uint32_t& r1, uint32_t& r2,
                                       uint32_t& r3, uint32_t a) {
    asm volatile("ldmatrix.sync.aligned.m8n8.x4.trans.shared.b16 {%0,%1,%2,%3}, [%4];"
                 : "=r"(r0), "=r"(r1), "=r"(r2), "=r"(r3) : "r"(a));
}
__device__ __forceinline__ void mma16816(float* d, uint32_t a0, uint32_t a1,
                                         uint32_t a2, uint32_t a3,
                                         uint32_t b0, uint32_t b1) {
    asm volatile(
        "mma.sync.aligned.m16n8k16.row.col.f32.f16.f16.f32 "
        "{%0,%1,%2,%3}, {%4,%5,%6,%7}, {%8,%9}, {%0,%1,%2,%3};"
        : "+f"(d[0]), "+f"(d[1]), "+f"(d[2]), "+f"(d[3])
        : "r"(a0), "r"(a1), "r"(a2), "r"(a3), "r"(b0), "r"(b1));
}
// P' = mask .* max(E2, G1*F2)   (row factor E1 cancelled in softmax)
__device__ __forceinline__ uint32_t fragP2(uint32_t g1, uint32_t e2,
                                           uint32_t f2, uint32_t bits) {
    __half2 pf = __hmul2(*(__half2*)&g1, *(__half2*)&f2);
    __half2 pm = __hmax2(*(__half2*)&e2, pf);
    uint32_t m = ((bits & 1u) ? 0xFFFFu : 0u) | ((bits & 2u) ? 0xFFFF0000u : 0u);
    return (*(uint32_t*)&pm) & m;
}

__global__ void pack_adj_kernel(const int* __restrict__ adj) {
    int warps = gridDim.x * (blockDim.x >> 5);
    int gw    = blockIdx.x * (blockDim.x >> 5) + (threadIdx.x >> 5);
    int lane  = threadIdx.x & 31;
    const int total = N * NW;
    for (int w = gw; w < total; w += warps) {
        int v = adj[(size_t)w * 32 + lane];
        unsigned m = __ballot_sync(0xffffffffu, v > 0);
        if (lane == 0) g_bitsT[(size_t)(w & (NW - 1)) * N + (w >> 8)] = m;
    }
}

__global__ void convert16_kernel(const float* __restrict__ x,
                                 const float* __restrict__ W_heads,
                                 const float* __restrict__ W_out) {
    int stride = gridDim.x * blockDim.x;
    int tid = blockIdx.x * blockDim.x + threadIdx.x;
    for (int i = tid; i < (N * FIN) / 4; i += stride) {
        float4 v = *((const float4*)x + i);
        *((__half2*)g_x16 + i * 2)     = __floats2half2_rn(v.x, v.y);
        *((__half2*)g_x16 + i * 2 + 1) = __floats2half2_rn(v.z, v.w);
    }
    for (int i = tid; i < (H * FIN * KH) / 4; i += stride) {
        float4 v = *((const float4*)W_heads + i);
        *((__half2*)g_W16 + i * 2)     = __floats2half2_rn(v.x, v.y);
        *((__half2*)g_W16 + i * 2 + 1) = __floats2half2_rn(v.z, v.w);
    }
    for (int i = tid; i < (FIN * NCLS) / 4; i += stride) {
        float4 v = *((const float4*)W_out + i);
        *((__half2*)g_Wout16 + i * 2)     = __floats2half2_rn(v.x, v.y);
        *((__half2*)g_Wout16 + i * 2 + 1) = __floats2half2_rn(v.z, v.w);
    }
}

// ---------------- layer-1 feature GEMM on HMMA ----------------
__global__ __launch_bounds__(256, 2) void gemm_hmma_kernel()
{
    extern __shared__ char rawsm[];
    uint32_t rawu = smem_u32(rawsm);
    uint32_t base = (rawu + 1023) & ~1023u;
    uint32_t sab = base, sbb = base + GOFF_SB;

    int t = threadIdx.x, warp = t >> 5, lane = t & 31;
    int head = blockIdx.y, i0 = blockIdx.x * 128;
    int l16 = lane & 15, lhi = lane >> 4;
    int row = warp * 16 + l16;

    const __half* asrc[4];
    uint32_t aofs_[4];
#pragma unroll
    for (int i = 0; i < 4; i++) {
        int ch = t + i * 256, r = ch >> 3, c8 = ch & 7;
        asrc[i]  = g_x16 + (size_t)(i0 + r) * FIN + c8 * 8;
        aofs_[i] = sab + SWZ128((uint32_t)(r * 128 + c8 * 16));
    }
    const __half* bsrc[2];
    uint32_t bofs_[2];
#pragma unroll
    for (int i = 0; i < 2; i++) {
        int ch = t + i * 256, r = ch >> 3, c8 = ch & 7;
        bsrc[i]  = g_W16 + (size_t)head * FIN * KH + r * KH + c8 * 8;
        bofs_[i] = sbb + SWZ128((uint32_t)(r * 128 + c8 * 16));
    }

    uint32_t alin  = (uint32_t)(row * 128 + lhi * 16);
    uint32_t bbase = (uint32_t)(l16 * 128 + lhi * 16);

    float acc[8][4];
#pragma unroll
    for (int n = 0; n < 8; n++)
#pragma unroll
        for (int q = 0; q < 4; q++) acc[n][q] = 0.f;

    auto issue = [&](int s, int buf) {
        int k0 = s * 64;
#pragma unroll
        for (int i = 0; i < 4; i++)
            cpasync16(aofs_[i] + buf * 16384, asrc[i] + k0);
#pragma unroll
        for (int i = 0; i < 2; i++)
            cpasync16(bofs_[i] + buf * 8192, bsrc[i] + (size_t)k0 * KH);
    };

    issue(0, 0); cpcommit();
    issue(1, 1); cpcommit();

    constexpr int NSTEP = FIN / 64;
#pragma unroll 1
    for (int step = 0; step < NSTEP; step++) {
        int buf = step % 3;
        cpwait1();
        __syncthreads();
        if (step + 2 < NSTEP) issue(step + 2, (step + 2) % 3);
        cpcommit();

        uint32_t pab = sab + buf * 16384;
        uint32_t pbb = sbb + buf * 8192;
#pragma unroll
        for (int kc = 0; kc < 4; kc++) {
            uint32_t a0, a1, a2, a3;
            ldsm4(a0, a1, a2, a3, pab + SWZ128(alin + kc * 32));
#pragma unroll
            for (int np = 0; np < 4; np++) {
                uint32_t b0, b1, b2, b3;
                ldsm4t(b0, b1, b2, b3, pbb + SWZ128(bbase + kc * 2048 + np * 32));
                mma16816(acc[2 * np],     a0, a1, a2, a3, b0, b1);
                mma16816(acc[2 * np + 1], a0, a1, a2, a3, b2, b3);
            }
        }
    }

    int r0 = warp * 16 + (lane >> 2), c0 = (lane & 3) * 2;
    __half* o0 = g_Wh16 + (size_t)(i0 + r0) * FIN + head * KH + c0;
    __half* o1 = o0 + 8 * FIN;
#pragma unroll
    for (int nt = 0; nt < 8; nt++) {
        *(__half2*)(o0 + nt * 8) = __floats2half2_rn(acc[nt][0], acc[nt][1]);
        *(__half2*)(o1 + nt * 8) = __floats2half2_rn(acc[nt][2], acc[nt][3]);
    }
}

// ---------------- layer-2 feature GEMM on HMMA, split-k, atomic ----------------
// g_Whout[i, n] += sum_{k in slice} h16[i,k] * Wout16[k,n]
__global__ __launch_bounds__(256, 2) void gemm16_kernel()
{
    extern __shared__ char rawsm[];
    uint32_t rawu = smem_u32(rawsm);
    uint32_t base = (rawu + 1023) & ~1023u;
    uint32_t sab = base, sbb = base + GOFF_SB;

    int t = threadIdx.x, warp = t >> 5, lane = t & 31;
    int i0 = blockIdx.x * 128, kbase = blockIdx.y * 128;
    int l16 = lane & 15, lhi = lane >> 4;
    int row = warp * 16 + l16;

    const __half* asrc[4];
    uint32_t aofs_[4];
#pragma unroll
    for (int i = 0; i < 4; i++) {
        int ch = t + i * 256, r = ch >> 3, c8 = ch & 7;
        asrc[i]  = g_h16 + (size_t)(i0 + r) * FIN + kbase + c8 * 8;
        aofs_[i] = sab + SWZ128((uint32_t)(r * 128 + c8 * 16));
    }
    const __half* bsrc = nullptr;
    uint32_t bofs0 = 0;
    if (t < 128) {
        int br = t >> 1, bc = t & 1;
        bsrc = g_Wout16 + (size_t)(kbase + br) * NCLS + bc * 8;
        bofs0 = sbb + SWZ128((uint32_t)(br * 128 + bc * 16));
    }

    uint32_t alin  = (uint32_t)(row * 128 + lhi * 16);
    uint32_t bbase = (uint32_t)(l16 * 128 + lhi * 16);

    float acc[2][4];
#pragma unroll
    for (int n = 0; n < 2; n++)
#pragma unroll
        for (int q = 0; q < 4; q++) acc[n][q] = 0.f;

    auto issue = [&](int s, int buf) {
        int k0 = s * 64;
#pragma unroll
        for (int i = 0; i < 4; i++)
            cpasync16(aofs_[i] + buf * 16384, asrc[i] + k0);
        if (t < 128)
            cpasync16(bofs0 + buf * 8192, bsrc + (size_t)k0 * NCLS);
    };

    issue(0, 0); cpcommit();
    issue(1, 1); cpcommit();

#pragma unroll 1
    for (int step = 0; step < 2; step++) {
        int buf = step % 3;
        cpwait1();
        __syncthreads();
        cpcommit();

        uint32_t pab = sab + buf * 16384;
        uint32_t pbb = sbb + buf * 8192;
#pragma unroll
        for (int kc = 0; kc < 4; kc++) {
            uint32_t a0, a1, a2, a3;
            ldsm4(a0, a1, a2, a3, pab + SWZ128(alin + kc * 32));
            uint32_t b0, b1, b2, b3;
            ldsm4t(b0, b1, b2, b3, pbb + SWZ128(bbase + kc * 2048));
            mma16816(acc[0], a0, a1, a2, a3, b0, b1);
            mma16816(acc[1], a0, a1, a2, a3, b2, b3);
        }
    }

    int r0 = warp * 16 + (lane >> 2), c0 = (lane & 3) * 2;
#pragma unroll
    for (int nt = 0; nt < 2; nt++) {
        atomicAdd(&g_Whout[(i0 + r0) * NCLS + nt * 8 + c0],         acc[nt][0]);
        atomicAdd(&g_Whout[(i0 + r0) * NCLS + nt * 8 + c0 + 1],     acc[nt][1]);
        atomicAdd(&g_Whout[(i0 + r0 + 8) * NCLS + nt * 8 + c0],     acc[nt][2]);
        atomicAdd(&g_Whout[(i0 + r0 + 8) * NCLS + nt * 8 + c0 + 1], acc[nt][3]);
    }
}

__global__ void s_heads_kernel(const float* __restrict__ a_heads) {
    int gw = blockIdx.x * 8 + (threadIdx.x >> 5);
    int lane = threadIdx.x & 31;
    int i = gw >> 3, h = gw & 7;
    if (i >= N) return;
    const __half* wh = g_Wh16 + (size_t)i * FIN + h * KH;
    const float* a  = a_heads + (size_t)h * 2 * KH;
    float w0 = __half2float(wh[lane]);
    float w1 = __half2float(wh[lane + 32]);
    float v1 = w0 * a[lane]      + w1 * a[lane + 32];
    float v2 = w0 * a[KH + lane] + w1 * a[KH + lane + 32];
#pragma unroll
    for (int o = 16; o; o >>= 1) {
        v1 += __shfl_down_sync(0xffffffffu, v1, o);
        v2 += __shfl_down_sync(0xffffffffu, v2, o);
    }
    if (lane == 0) {
        g_G1[h * N + i]  = __expf(-0.8f * v1);
        g_E2h[h * N + i] = __float2half(__expf(v2));
        g_F2h[h * N + i] = __float2half(__expf(0.2f * v2));
    }
}

__global__ void s_out_kernel(const float* __restrict__ a_out) {
    int gw = blockIdx.x * 8 + (threadIdx.x >> 5);
    int lane = threadIdx.x & 31;
    if (gw >= N) return;
    float v1 = 0.f, v2 = 0.f;
    if (lane < NCLS) {
        float w = g_Whout[(size_t)gw * NCLS + lane];
        g_Whout16[(size_t)gw * NCLS + lane] = __float2half(w);
        v1 = w * a_out[lane];
        v2 = w * a_out[NCLS + lane];
    }
#pragma unroll
    for (int o = 16; o; o >>= 1) {
        v1 += __shfl_down_sync(0xffffffffu, v1, o);
        v2 += __shfl_down_sync(0xffffffffu, v2, o);
    }
    if (lane == 0) {
        g_G1o[gw]  = __expf(-0.8f * v1);
        g_E2oh[gw] = __float2half(__expf(v2));
        g_F2oh[gw] = __float2half(__expf(0.2f * v2));
    }
}

// ---- layer-1 finalize: h16 = (sum_z part[z]) / (sum_z den[z]) ----
__global__ void finalize1_kernel() {
    int idx = blockIdx.x * 256 + threadIdx.x;
    if (idx >= N * FIN) return;
    int i = idx >> 9, head = (idx & 511) >> 6;
    float num = 0.f, den = 0.f;
#pragma unroll
    for (int z = 0; z < NSPL1; z++) {
        num += g_part1[(size_t)z * N * FIN + idx];
        den += g_dpart1[(z * H + head) * N + i];
    }
    g_h16[idx] = __float2half(num / den);
}

__global__ void finalize_kernel(float* __restrict__ Out) {
    int i = blockIdx.x * 256 + threadIdx.x;
    if (i >= N * NCLS) return;
    float v = g_numO[i] / g_denO[i >> 4];
    Out[i] = (v > 0.f) ? v : expm1f(v);
}

// ============ attention: direct-fragment P-gen (G1 form), HMMA, j-split ============
template<int NC, int NSPL, bool ATOMIC>
__global__ __launch_bounds__(256, 3) void attn_hmma(
    const float* __restrict__ G1g,
    const __half* __restrict__ E2g, const __half* __restrict__ F2g,
    const __half* __restrict__ Bg, int ldb)
{
    extern __shared__ char rawsm[];
    uint32_t rawu = smem_u32(rawsm);
    uint32_t base = (rawu + 1023) & ~1023u;
    uint32_t sbb = base + OFF_SB;
    uint32_t se2b = base + OFF_SE2, sf2b = base + OFF_SF2;
    uint32_t smb = base + OFF_SM;

    int t = threadIdx.x, warp = t >> 5, lane = t & 31;
    int head  = blockIdx.y;
    int zspl  = blockIdx.z;
    int jbase = zspl * (N / NSPL);
    constexpr int NSTEP = (N / NSPL) / 128;
    int i0 = blockIdx.x * 128;
    int bcol = (NC == 64) ? head * 64 : 0;
    int wbase0 = jbase >> 5;

    int l16 = lane & 15, lhi = lane >> 4;
    int r0l = warp * 16 + (lane >> 2);
    int c0 = (lane & 3) * 2;
    uint32_t g1r0, g1r1;
    {
        __half2 ha = __float2half2_rn(G1g[head * N + i0 + r0l]);
        __half2 hb = __float2half2_rn(G1g[head * N + i0 + r0l + 8]);
        g1r0 = *(uint32_t*)&ha;
        g1r1 = *(uint32_t*)&hb;
    }

    // B loader: single base pointer; chunk i at +i*32 rows (=+i*32*ldb halves,
    // +i*4096 smem bytes — above the swizzle window so offsets stay linear)
    constexpr int CPT = (128 * NC / 8) / 256;
    const __half* bsrc0;
    uint32_t bofs0;
    {
        int br = t / (NC / 8), bc = t % (NC / 8);
        bsrc0 = Bg + (size_t)(jbase + br) * ldb + bcol + bc * 8;
        bofs0 = sbb + SWZ128((uint32_t)(br * 128 + bc * 16));
    }
    const __half* e2base = E2g + head * N + jbase;
    const __half* f2base = F2g + head * N + jbase;

    uint32_t bbase = (uint32_t)(l16 * 128 + lhi * 16);
    uint32_t ones0 = (lane < 4) ? 0x3C003C00u : 0u;

    float acc[NC / 8][4];
#pragma unroll
    for (int n = 0; n < NC / 8; n++)
#pragma unroll
        for (int q = 0; q < 4; q++) acc[n][q] = 0.f;
    float accd[4] = {0.f, 0.f, 0.f, 0.f};

    int mq = t >> 5, ms = t & 31;
    const uint32_t* msrc = g_bitsT + (size_t)mq * N + i0 + ms * 4;

    auto issue = [&](int s, int buf) {
        int j0 = s * 128;
#pragma unroll
        for (int i = 0; i < CPT; i++)
            cpasync16(bofs0 + buf * 16384 + i * 4096,
                      bsrc0 + (size_t)(j0 + i * 32) * ldb);
        if (t < 128)
            cpasync16(smb + buf * 2048 + mq * 512 + ms * 16,
                      msrc + (size_t)(wbase0 + s * 4) * N);
        else if (t < 144)
            cpasync16(se2b + buf * 256 + (t - 128) * 16, e2base + j0 + (t - 128) * 8);
        else if (t < 160)
            cpasync16(sf2b + buf * 256 + (t - 144) * 16, f2base + j0 + (t - 144) * 8);
    };

    issue(0, 0); cpcommit();
    if (NSTEP > 1) issue(1, 1);
    cpcommit();

#pragma unroll 1
    for (int step = 0; step < NSTEP; step++) {
        int buf = step % 3;
        cpwait1();
        __syncthreads();
        if (step + 2 < NSTEP) issue(step + 2, (step + 2) % 3);
        cpcommit();

        uint32_t peb = se2b + buf * 256;
        uint32_t pfb = sf2b + buf * 256;
        uint32_t pmb = smb + buf * 2048 + r0l * 4;
        uint32_t pbb = sbb + buf * 16384;
#pragma unroll
        for (int kcp = 0; kcp < 4; kcp++) {
            uint32_t w0s = lds32(pmb + kcp * 512) >> c0;
            uint32_t w1s = lds32(pmb + kcp * 512 + 32) >> c0;
#pragma unroll
            for (int kh = 0; kh < 2; kh++) {
                int kc = kcp * 2 + kh;
                uint32_t e2lo = lds32(peb + kc * 32 + c0 * 2);
                uint32_t e2hi = lds32(peb + kc * 32 + c0 * 2 + 16);
                uint32_t f2lo = lds32(pfb + kc * 32 + c0 * 2);
                uint32_t f2hi = lds32(pfb + kc * 32 + c0 * 2 + 16);
                uint32_t sh = kh * 16;
                uint32_t a0 = fragP2(g1r0, e2lo, f2lo, (w0s >> sh) & 3u);
                uint32_t a1 = fragP2(g1r1, e2lo, f2lo, (w1s >> sh) & 3u);
                uint32_t a2 = fragP2(g1r0, e2hi, f2hi, (w0s >> (sh + 8)) & 3u);
                uint32_t a3 = fragP2(g1r1, e2hi, f2hi, (w1s >> (sh + 8)) & 3u);

                mma16816(accd, a0, a1, a2, a3, ones0, ones0);
#pragma unroll
                for (int np = 0; np < NC / 16; np++) {
                    uint32_t b0, b1, b2, b3;
                    ldsm4t(b0, b1, b2, b3, pbb + SWZ128(bbase + kc * 2048 + np * 32));
                    mma16816(acc[2 * np],     a0, a1, a2, a3, b0, b1);
                    mma16816(acc[2 * np + 1], a0, a1, a2, a3, b2, b3);
                }
            }
        }
    }

    int r0 = r0l;
    if constexpr (ATOMIC) {
        if ((lane & 3) == 0) {
            atomicAdd(&g_denO[i0 + r0],     accd[0]);
            atomicAdd(&g_denO[i0 + r0 + 8], accd[2]);
        }
#pragma unroll
        for (int nt = 0; nt < NC / 8; nt++) {
            atomicAdd(&g_numO[(i0 + r0) * NCLS + nt * 8 + c0],     acc[nt][0]);
            atomicAdd(&g_numO[(i0 + r0) * NCLS + nt * 8 + c0 + 1], acc[nt][1]);
            atomicAdd(&g_numO[(i0 + r0 + 8) * NCLS + nt * 8 + c0],     acc[nt][2]);
            atomicAdd(&g_numO[(i0 + r0 + 8) * NCLS + nt * 8 + c0 + 1], acc[nt][3]);
        }
    } else {
        if ((lane & 3) == 0) {
            g_dpart1[(zspl * H + head) * N + i0 + r0]     = accd[0];
            g_dpart1[(zspl * H + head) * N + i0 + r0 + 8] = accd[2];
        }
        float* po0 = g_part1 + (size_t)zspl * N * FIN
                   + (size_t)(i0 + r0) * FIN + bcol + c0;
        float* po1 = po0 + 8 * FIN;
#pragma unroll
        for (int nt = 0; nt < NC / 8; nt++) {
            *(float2*)(po0 + nt * 8) = make_float2(acc[nt][0], acc[nt][1]);
            *(float2*)(po1 + nt * 8) = make_float2(acc[nt][2], acc[nt][3]);
        }
    }
}

extern "C" void kernel_launch(void* const* d_in, const int* in_sizes, int n_in,
                              void* d_out, int out_size)
{
    const float* x = nullptr;
    const int* adj = nullptr;
    const float *W_heads = nullptr, *a_heads = nullptr, *W_out = nullptr, *a_out = nullptr;
    for (int i = 0; i < n_in; i++) {
        switch (in_sizes[i]) {
            case N * FIN:      x       = (const float*)d_in[i]; break;
            case 67108864:     adj     = (const int*)  d_in[i]; break;
            case H * FIN * KH: W_heads = (const float*)d_in[i]; break;
            case H * 2 * KH:   a_heads = (const float*)d_in[i]; break;
            case FIN * NCLS:   W_out   = (const float*)d_in[i]; break;
            case 2 * NCLS:     a_out   = (const float*)d_in[i]; break;
        }
    }

    float *whoP, *g1P, *g1oP, *numP, *denP;
    __half *wh16P, *who16P, *e2hP, *f2hP, *e2ohP, *f2ohP;
    cudaGetSymbolAddress((void**)&wh16P, g_Wh16);
    cudaGetSymbolAddress((void**)&whoP,  g_Whout);
    cudaGetSymbolAddress((void**)&who16P, g_Whout16);
    cudaGetSymbolAddress((void**)&g1P,  g_G1);
    cudaGetSymbolAddress((void**)&e2hP, g_E2h);
    cudaGetSymbolAddress((void**)&f2hP, g_F2h);
    cudaGetSymbolAddress((void**)&g1oP, g_G1o);
    cudaGetSymbolAddress((void**)&e2ohP, g_E2oh);
    cudaGetSymbolAddress((void**)&f2ohP, g_F2oh);
    cudaGetSymbolAddress((void**)&numP, g_numO);
    cudaGetSymbolAddress((void**)&denP, g_denO);

    cudaFuncSetAttribute((const void*)attn_hmma<64, NSPL1, false>,
                         cudaFuncAttributeMaxDynamicSharedMemorySize, ATT_DSMEM);
    cudaFuncSetAttribute((const void*)attn_hmma<16, 16, true>,
                         cudaFuncAttributeMaxDynamicSharedMemorySize, ATT_DSMEM);
    cudaFuncSetAttribute(gemm_hmma_kernel,
                         cudaFuncAttributeMaxDynamicSharedMemorySize, GEMM_DSMEM);
    cudaFuncSetAttribute(gemm16_kernel,
                         cudaFuncAttributeMaxDynamicSharedMemorySize, GEMM_DSMEM);

    pack_adj_kernel<<<4096, 256>>>(adj);
    convert16_kernel<<<2048, 256>>>(x, W_heads, W_out);
    gemm_hmma_kernel<<<dim3(N / 128, H), 256, GEMM_DSMEM>>>();
    s_heads_kernel<<<(N * H) / 8, 256>>>(a_heads);
    cudaMemsetAsync(numP, 0, N * NCLS * sizeof(float));
    cudaMemsetAsync(denP, 0, N * sizeof(float));
    cudaMemsetAsync(whoP, 0, N * NCLS * sizeof(float));
    attn_hmma<64, NSPL1, false><<<dim3(N / 128, H, NSPL1), 256, ATT_DSMEM>>>(
        g1P, e2hP, f2hP, wh16P, FIN);
    finalize1_kernel<<<(N * FIN + 255) / 256, 256>>>();
    gemm16_kernel<<<dim3(N / 128, FIN / 128), 256, GEMM_DSMEM>>>();
    s_out_kernel<<<N / 8, 256>>>(a_out);
    attn_hmma<16, 16, true><<<dim3(N / 128, 1, 16), 256, ATT_DSMEM>>>(
        g1oP, e2ohP, f2ohP, who16P, NCLS);
    finalize_kernel<<<(N * NCLS + 255) / 256, 256>>>((float*)d_out);
}

// round 13
// speedup vs baseline: 6.3729x; 1.0046x over previous
#include <cuda_runtime.h>
#include <cuda_fp16.h>
#include <cstdint>
#include <math.h>

#define N    8192
#define NW   (N/32)
#define FIN  512
#define KH   64
#define H    8
#define NCLS 16
#define NSPL1 4

__device__ uint32_t g_bits2[NW * N];       // [wordgrp][row][4 words]
__device__ __half   g_x16  [N * FIN];
__device__ __half   g_W16  [H * FIN * KH];
__device__ __half   g_Wout16[FIN * NCLS];
__device__ __half   g_Wh16 [N * FIN];
__device__ __half   g_h16  [N * FIN];
__device__ float    g_Whout[N * NCLS];
__device__ __half   g_Whout16[N * NCLS];
__device__ float    g_G1[H * N];
__device__ __half   g_E2h[H * N], g_F2h[H * N];
__device__ float    g_G1o[N];
__device__ __half   g_E2oh[N], g_F2oh[N];
__device__ float    g_numO[N * NCLS];
__device__ float    g_denO[N];
__device__ float    g_part1[NSPL1 * N * FIN];
__device__ float    g_dpart1[NSPL1 * H * N];

#define SWZ128(o) ((o) ^ (((o) >> 3) & 0x70))

// attn dyn smem: sB 3x16KB | sE2 3x256B | sF2 3x256B | sMask 3x2KB
#define OFF_SB   0
#define OFF_SE2  49152
#define OFF_SF2  49920
#define OFF_SM   50688
#define ATT_DSMEM (56832 + 1024)
// gemm dyn smem: sA 3x16KB | sB 3x8KB
#define GOFF_SB  49152
#define GEMM_DSMEM (73728 + 1024)

__device__ __forceinline__ uint32_t smem_u32(const void* p) {
    return (uint32_t)__cvta_generic_to_shared(p);
}
__device__ __forceinline__ void cpasync16(uint32_t dst, const void* src) {
    asm volatile("cp.async.cg.shared.global [%0], [%1], 16;" :: "r"(dst), "l"(src));
}
__device__ __forceinline__ void cpcommit() {
    asm volatile("cp.async.commit_group;");
}
__device__ __forceinline__ void cpwait1() {
    asm volatile("cp.async.wait_group 1;");
}
__device__ __forceinline__ uint32_t lds32(uint32_t addr) {
    uint32_t v;
    asm volatile("ld.shared.b32 %0, [%1];" : "=r"(v) : "r"(addr));
    return v;
}
__device__ __forceinline__ uint4 lds128(uint32_t addr) {
    uint4 v;
    asm volatile("ld.shared.v4.b32 {%0,%1,%2,%3}, [%4];"
                 : "=r"(v.x), "=r"(v.y), "=r"(v.z), "=r"(v.w) : "r"(addr));
    return v;
}
__device__ __forceinline__ void ldsm4(uint32_t& r0, uint32_t& r1, uint32_t& r2,
                                      uint32_t& r3, uint32_t a) {
    asm volatile("ldmatrix.sync.aligned.m8n8.x4.shared.b16 {%0,%1,%2,%3}, [%4];"
                 : "=r"(r0), "=r"(r1), "=r"(r2), "=r"(r3) : "r"(a));
}
__device__ __forceinline__ void ldsm4t(uint32_t& r0, uint32_t& r1, uint32_t& r2,
                                       uint32_t& r3, uint32_t a) {
    asm volatile("ldmatrix.sync.aligned.m8n8.x4.trans.shared.b16 {%0,%1,%2,%3}, [%4];"
                 : "=r"(r0), "=r"(r1), "=r"(r2), "=r"(r3) : "r"(a));
}
__device__ __forceinline__ void mma16816(float* d, uint32_t a0, uint32_t a1,
                                         uint32_t a2, uint32_t a3,
                                         uint32_t b0, uint32_t b1) {
    asm volatile(
        "mma.sync.aligned.m16n8k16.row.col.f32.f16.f16.f32 "
        "{%0,%1,%2,%3}, {%4,%5,%6,%7}, {%8,%9}, {%0,%1,%2,%3};"
        : "+f"(d[0]), "+f"(d[1]), "+f"(d[2]), "+f"(d[3])
        : "r"(a0), "r"(a1), "r"(a2), "r"(a3), "r"(b0), "r"(b1));
}
// P' = mask .* max(E2, G1*F2)
__device__ __forceinline__ uint32_t fragP2(uint32_t g1, uint32_t e2,
                                           uint32_t f2, uint32_t bits) {
    __half2 pf = __hmul2(*(__half2*)&g1, *(__half2*)&f2);
    __half2 pm = __hmax2(*(__half2*)&e2, pf);
    uint32_t m = ((bits & 1u) ? 0xFFFFu : 0u) | ((bits & 2u) ? 0xFFFF0000u : 0u);
    return (*(uint32_t*)&pm) & m;
}

// ---------------- adjacency bit-pack: [widx>>2][row][widx&3] ----------------
__global__ void pack_adj_kernel(const int* __restrict__ adj) {
    int warps = gridDim.x * (blockDim.x >> 5);
    int gw    = blockIdx.x * (blockDim.x >> 5) + (threadIdx.x >> 5);
    int lane  = threadIdx.x & 31;
    const int total = N * NW;
    for (int w = gw; w < total; w += warps) {
        int v = adj[(size_t)w * 32 + lane];
        unsigned m = __ballot_sync(0xffffffffu, v > 0);
        if (lane == 0) {
            int row = w >> 8, widx = w & (NW - 1);
            g_bits2[((size_t)(widx >> 2) * N + row) * 4 + (widx & 3)] = m;
        }
    }
}

__global__ void convert16_kernel(const float* __restrict__ x,
                                 const float* __restrict__ W_heads,
                                 const float* __restrict__ W_out) {
    int stride = gridDim.x * blockDim.x;
    int tid = blockIdx.x * blockDim.x + threadIdx.x;
    for (int i = tid; i < (N * FIN) / 4; i += stride) {
        float4 v = *((const float4*)x + i);
        *((__half2*)g_x16 + i * 2)     = __floats2half2_rn(v.x, v.y);
        *((__half2*)g_x16 + i * 2 + 1) = __floats2half2_rn(v.z, v.w);
    }
    for (int i = tid; i < (H * FIN * KH) / 4; i += stride) {
        float4 v = *((const float4*)W_heads + i);
        *((__half2*)g_W16 + i * 2)     = __floats2half2_rn(v.x, v.y);
        *((__half2*)g_W16 + i * 2 + 1) = __floats2half2_rn(v.z, v.w);
    }
    for (int i = tid; i < (FIN * NCLS) / 4; i += stride) {
        float4 v = *((const float4*)W_out + i);
        *((__half2*)g_Wout16 + i * 2)     = __floats2half2_rn(v.x, v.y);
        *((__half2*)g_Wout16 + i * 2 + 1) = __floats2half2_rn(v.z, v.w);
    }
}

// -------- layer-1 feature GEMM on HMMA + fused score factors --------
__global__ __launch_bounds__(256, 2) void gemm_hmma_kernel(
    const float* __restrict__ a_heads)
{
    extern __shared__ char rawsm[];
    uint32_t rawu = smem_u32(rawsm);
    uint32_t base = (rawu + 1023) & ~1023u;
    uint32_t sab = base, sbb = base + GOFF_SB;

    int t = threadIdx.x, warp = t >> 5, lane = t & 31;
    int head = blockIdx.y, i0 = blockIdx.x * 128;
    int l16 = lane & 15, lhi = lane >> 4;
    int row = warp * 16 + l16;

    const __half* asrc[4];
    uint32_t aofs_[4];
#pragma unroll
    for (int i = 0; i < 4; i++) {
        int ch = t + i * 256, r = ch >> 3, c8 = ch & 7;
        asrc[i]  = g_x16 + (size_t)(i0 + r) * FIN + c8 * 8;
        aofs_[i] = sab + SWZ128((uint32_t)(r * 128 + c8 * 16));
    }
    const __half* bsrc[2];
    uint32_t bofs_[2];
#pragma unroll
    for (int i = 0; i < 2; i++) {
        int ch = t + i * 256, r = ch >> 3, c8 = ch & 7;
        bsrc[i]  = g_W16 + (size_t)head * FIN * KH + r * KH + c8 * 8;
        bofs_[i] = sbb + SWZ128((uint32_t)(r * 128 + c8 * 16));
    }

    uint32_t alin  = (uint32_t)(row * 128 + lhi * 16);
    uint32_t bbase = (uint32_t)(l16 * 128 + lhi * 16);

    float acc[8][4];
#pragma unroll
    for (int n = 0; n < 8; n++)
#pragma unroll
        for (int q = 0; q < 4; q++) acc[n][q] = 0.f;

    auto issue = [&](int s, int buf) {
        int k0 = s * 64;
#pragma unroll
        for (int i = 0; i < 4; i++)
            cpasync16(aofs_[i] + buf * 16384, asrc[i] + k0);
#pragma unroll
        for (int i = 0; i < 2; i++)
            cpasync16(bofs_[i] + buf * 8192, bsrc[i] + (size_t)k0 * KH);
    };

    issue(0, 0); cpcommit();
    issue(1, 1); cpcommit();

    constexpr int NSTEP = FIN / 64;
#pragma unroll 1
    for (int step = 0; step < NSTEP; step++) {
        int buf = step % 3;
        cpwait1();
        __syncthreads();
        if (step + 2 < NSTEP) issue(step + 2, (step + 2) % 3);
        cpcommit();

        uint32_t pab = sab + buf * 16384;
        uint32_t pbb = sbb + buf * 8192;
#pragma unroll
        for (int kc = 0; kc < 4; kc++) {
            uint32_t a0, a1, a2, a3;
            ldsm4(a0, a1, a2, a3, pab + SWZ128(alin + kc * 32));
#pragma unroll
            for (int np = 0; np < 4; np++) {
                uint32_t b0, b1, b2, b3;
                ldsm4t(b0, b1, b2, b3, pbb + SWZ128(bbase + kc * 2048 + np * 32));
                mma16816(acc[2 * np],     a0, a1, a2, a3, b0, b1);
                mma16816(acc[2 * np + 1], a0, a1, a2, a3, b2, b3);
            }
        }
    }

    int r0 = warp * 16 + (lane >> 2), c0 = (lane & 3) * 2;
    __half* o0 = g_Wh16 + (size_t)(i0 + r0) * FIN + head * KH + c0;
    __half* o1 = o0 + 8 * FIN;
#pragma unroll
    for (int nt = 0; nt < 8; nt++) {
        *(__half2*)(o0 + nt * 8) = __floats2half2_rn(acc[nt][0], acc[nt][1]);
        *(__half2*)(o1 + nt * 8) = __floats2half2_rn(acc[nt][2], acc[nt][3]);
    }

    // ---- fused score factors: v = Wh . a1, w = Wh . a2 per row ----
    {
        const float* a1 = a_heads + (size_t)head * 2 * KH;
        const float* a2 = a1 + KH;
        float v1 = 0.f, v2 = 0.f, u1 = 0.f, u2 = 0.f;
#pragma unroll
        for (int nt = 0; nt < 8; nt++) {
            int col = nt * 8 + c0;
            float a1x = a1[col], a1y = a1[col + 1];
            float a2x = a2[col], a2y = a2[col + 1];
            v1 += acc[nt][0] * a1x + acc[nt][1] * a1y;
            v2 += acc[nt][0] * a2x + acc[nt][1] * a2y;
            u1 += acc[nt][2] * a1x + acc[nt][3] * a1y;
            u2 += acc[nt][2] * a2x + acc[nt][3] * a2y;
        }
#pragma unroll
        for (int o = 1; o <= 2; o <<= 1) {
            v1 += __shfl_xor_sync(0xffffffffu, v1, o);
            v2 += __shfl_xor_sync(0xffffffffu, v2, o);
            u1 += __shfl_xor_sync(0xffffffffu, u1, o);
            u2 += __shfl_xor_sync(0xffffffffu, u2, o);
        }
        if ((lane & 3) == 0) {
            int i = i0 + r0;
            g_G1[head * N + i]      = __expf(-0.8f * v1);
            g_E2h[head * N + i]     = __float2half(__expf(v2));
            g_F2h[head * N + i]     = __float2half(__expf(0.2f * v2));
            g_G1[head * N + i + 8]  = __expf(-0.8f * u1);
            g_E2h[head * N + i + 8] = __float2half(__expf(u2));
            g_F2h[head * N + i + 8] = __float2half(__expf(0.2f * u2));
        }
    }
}

// -------- layer-2 feature GEMM on HMMA, split-k, atomic --------
__global__ __launch_bounds__(256, 2) void gemm16_kernel()
{
    extern __shared__ char rawsm[];
    uint32_t rawu = smem_u32(rawsm);
    uint32_t base = (rawu + 1023) & ~1023u;
    uint32_t sab = base, sbb = base + GOFF_SB;

    int t = threadIdx.x, warp = t >> 5, lane = t & 31;
    int i0 = blockIdx.x * 128, kbase = blockIdx.y * 128;
    int l16 = lane & 15, lhi = lane >> 4;
    int row = warp * 16 + l16;

    const __half* asrc[4];
    uint32_t aofs_[4];
#pragma unroll
    for (int i = 0; i < 4; i++) {
        int ch = t + i * 256, r = ch >> 3, c8 = ch & 7;
        asrc[i]  = g_h16 + (size_t)(i0 + r) * FIN + kbase + c8 * 8;
        aofs_[i] = sab + SWZ128((uint32_t)(r * 128 + c8 * 16));
    }
    const __half* bsrc = nullptr;
    uint32_t bofs0 = 0;
    if (t < 128) {
        int br = t >> 1, bc = t & 1;
        bsrc = g_Wout16 + (size_t)(kbase + br) * NCLS + bc * 8;
        bofs0 = sbb + SWZ128((uint32_t)(br * 128 + bc * 16));
    }

    uint32_t alin  = (uint32_t)(row * 128 + lhi * 16);
    uint32_t bbase = (uint32_t)(l16 * 128 + lhi * 16);

    float acc[2][4];
#pragma unroll
    for (int n = 0; n < 2; n++)
#pragma unroll
        for (int q = 0; q < 4; q++) acc[n][q] = 0.f;

    auto issue = [&](int s, int buf) {
        int k0 = s * 64;
#pragma unroll
        for (int i = 0; i < 4; i++)
            cpasync16(aofs_[i] + buf * 16384, asrc[i] + k0);
        if (t < 128)
            cpasync16(bofs0 + buf * 8192, bsrc + (size_t)k0 * NCLS);
    };

    issue(0, 0); cpcommit();
    issue(1, 1); cpcommit();

#pragma unroll 1
    for (int step = 0; step < 2; step++) {
        int buf = step % 3;
        cpwait1();
        __syncthreads();
        cpcommit();

        uint32_t pab = sab + buf * 16384;
        uint32_t pbb = sbb + buf * 8192;
#pragma unroll
        for (int kc = 0; kc < 4; kc++) {
            uint32_t a0, a1, a2, a3;
            ldsm4(a0, a1, a2, a3, pab + SWZ128(alin + kc * 32));
            uint32_t b0, b1, b2, b3;
            ldsm4t(b0, b1, b2, b3, pbb + SWZ128(bbase + kc * 2048));
            mma16816(acc[0], a0, a1, a2, a3, b0, b1);
            mma16816(acc[1], a0, a1, a2, a3, b2, b3);
        }
    }

    int r0 = warp * 16 + (lane >> 2), c0 = (lane & 3) * 2;
#pragma unroll
    for (int nt = 0; nt < 2; nt++) {
        atomicAdd(&g_Whout[(i0 + r0) * NCLS + nt * 8 + c0],         acc[nt][0]);
        atomicAdd(&g_Whout[(i0 + r0) * NCLS + nt * 8 + c0 + 1],     acc[nt][1]);
        atomicAdd(&g_Whout[(i0 + r0 + 8) * NCLS + nt * 8 + c0],     acc[nt][2]);
        atomicAdd(&g_Whout[(i0 + r0 + 8) * NCLS + nt * 8 + c0 + 1], acc[nt][3]);
    }
}

__global__ void s_out_kernel(const float* __restrict__ a_out) {
    int gw = blockIdx.x * 8 + (threadIdx.x >> 5);
    int lane = threadIdx.x & 31;
    if (gw >= N) return;
    float v1 = 0.f, v2 = 0.f;
    if (lane < NCLS) {
        float w = g_Whout[(size_t)gw * NCLS + lane];
        g_Whout16[(size_t)gw * NCLS + lane] = __float2half(w);
        v1 = w * a_out[lane];
        v2 = w * a_out[NCLS + lane];
    }
#pragma unroll
    for (int o = 16; o; o >>= 1) {
        v1 += __shfl_down_sync(0xffffffffu, v1, o);
        v2 += __shfl_down_sync(0xffffffffu, v2, o);
    }
    if (lane == 0) {
        g_G1o[gw]  = __expf(-0.8f * v1);
        g_E2oh[gw] = __float2half(__expf(v2));
        g_F2oh[gw] = __float2half(__expf(0.2f * v2));
    }
}

__global__ void finalize1_kernel() {
    int idx = blockIdx.x * 256 + threadIdx.x;
    if (idx >= N * FIN) return;
    int i = idx >> 9, head = (idx & 511) >> 6;
    float num = 0.f, den = 0.f;
#pragma unroll
    for (int z = 0; z < NSPL1; z++) {
        num += g_part1[(size_t)z * N * FIN + idx];
        den += g_dpart1[(z * H + head) * N + i];
    }
    g_h16[idx] = __float2half(num / den);
}

__global__ void finalize_kernel(float* __restrict__ Out) {
    int i = blockIdx.x * 256 + threadIdx.x;
    if (i >= N * NCLS) return;
    float v = g_numO[i] / g_denO[i >> 4];
    Out[i] = (v > 0.f) ? v : expm1f(v);
}

// ============ attention: direct-fragment P-gen (G1 form), HMMA, j-split ============
template<int NC, int NSPL, bool ATOMIC>
__global__ __launch_bounds__(256, 3) void attn_hmma(
    const float* __restrict__ G1g,
    const __half* __restrict__ E2g, const __half* __restrict__ F2g,
    const __half* __restrict__ Bg, int ldb)
{
    extern __shared__ char rawsm[];
    uint32_t rawu = smem_u32(rawsm);
    uint32_t base = (rawu + 1023) & ~1023u;
    uint32_t sbb = base + OFF_SB;
    uint32_t se2b = base + OFF_SE2, sf2b = base + OFF_SF2;
    uint32_t smb = base + OFF_SM;

    int t = threadIdx.x, warp = t >> 5, lane = t & 31;
    int head  = blockIdx.y;
    int zspl  = blockIdx.z;
    int jbase = zspl * (N / NSPL);
    constexpr int NSTEP = (N / NSPL) / 128;
    int i0 = blockIdx.x * 128;
    int bcol = (NC == 64) ? head * 64 : 0;
    int wg0 = jbase >> 7;        // 128-j word-group index

    int l16 = lane & 15, lhi = lane >> 4;
    int r0l = warp * 16 + (lane >> 2);
    int c0 = (lane & 3) * 2;
    uint32_t g1r0, g1r1;
    {
        __half2 ha = __float2half2_rn(G1g[head * N + i0 + r0l]);
        __half2 hb = __float2half2_rn(G1g[head * N + i0 + r0l + 8]);
        g1r0 = *(uint32_t*)&ha;
        g1r1 = *(uint32_t*)&hb;
    }

    constexpr int CPT = (128 * NC / 8) / 256;
    const __half* bsrc0;
    uint32_t bofs0;
    {
        int br = t / (NC / 8), bc = t % (NC / 8);
        bsrc0 = Bg + (size_t)(jbase + br) * ldb + bcol + bc * 8;
        bofs0 = sbb + SWZ128((uint32_t)(br * 128 + bc * 16));
    }
    const __half* e2base = E2g + head * N + jbase;
    const __half* f2base = F2g + head * N + jbase;

    uint32_t bbase = (uint32_t)(l16 * 128 + lhi * 16);
    uint32_t ones0 = (lane < 4) ? 0x3C003C00u : 0u;

    float acc[NC / 8][4];
#pragma unroll
    for (int n = 0; n < NC / 8; n++)
#pragma unroll
        for (int q = 0; q < 4; q++) acc[n][q] = 0.f;
    float accd[4] = {0.f, 0.f, 0.f, 0.f};

    // mask loader: one 16B line (4 words = 128 j) per row per step
    const uint32_t* msrc = g_bits2 + ((size_t)wg0 * N + i0 + t) * 4;

    auto issue = [&](int s, int buf) {
        int j0 = s * 128;
#pragma unroll
        for (int i = 0; i < CPT; i++)
            cpasync16(bofs0 + buf * 16384 + i * 4096,
                      bsrc0 + (size_t)(j0 + i * 32) * ldb);
        if (t < 128)
            cpasync16(smb + buf * 2048 + t * 16, msrc + (size_t)s * N * 4);
        else if (t < 144)
            cpasync16(se2b + buf * 256 + (t - 128) * 16, e2base + j0 + (t - 128) * 8);
        else if (t < 160)
            cpasync16(sf2b + buf * 256 + (t - 144) * 16, f2base + j0 + (t - 144) * 8);
    };

    issue(0, 0); cpcommit();
    if (NSTEP > 1) issue(1, 1);
    cpcommit();

#pragma unroll 1
    for (int step = 0; step < NSTEP; step++) {
        int buf = step % 3;
        cpwait1();
        __syncthreads();
        if (step + 2 < NSTEP) issue(step + 2, (step + 2) % 3);
        cpcommit();

        uint32_t peb = se2b + buf * 256;
        uint32_t pfb = sf2b + buf * 256;
        uint32_t pbb = sbb + buf * 16384;
        uint4 wq0 = lds128(smb + buf * 2048 + r0l * 16);
        uint4 wq1 = lds128(smb + buf * 2048 + r0l * 16 + 128);
#pragma unroll
        for (int kcp = 0; kcp < 4; kcp++) {
            uint32_t w0s = (&wq0.x)[kcp] >> c0;
            uint32_t w1s = (&wq1.x)[kcp] >> c0;
#pragma unroll
            for (int kh = 0; kh < 2; kh++) {
                int kc = kcp * 2 + kh;
                uint32_t e2lo = lds32(peb + kc * 32 + c0 * 2);
                uint32_t e2hi = lds32(peb + kc * 32 + c0 * 2 + 16);
                uint32_t f2lo = lds32(pfb + kc * 32 + c0 * 2);
                uint32_t f2hi = lds32(pfb + kc * 32 + c0 * 2 + 16);
                uint32_t sh = kh * 16;
                uint32_t a0 = fragP2(g1r0, e2lo, f2lo, (w0s >> sh) & 3u);
                uint32_t a1 = fragP2(g1r1, e2lo, f2lo, (w1s >> sh) & 3u);
                uint32_t a2 = fragP2(g1r0, e2hi, f2hi, (w0s >> (sh + 8)) & 3u);
                uint32_t a3 = fragP2(g1r1, e2hi, f2hi, (w1s >> (sh + 8)) & 3u);

                mma16816(accd, a0, a1, a2, a3, ones0, ones0);
#pragma unroll
                for (int np = 0; np < NC / 16; np++) {
                    uint32_t b0, b1, b2, b3;
                    ldsm4t(b0, b1, b2, b3, pbb + SWZ128(bbase + kc * 2048 + np * 32));
                    mma16816(acc[2 * np],     a0, a1, a2, a3, b0, b1);
                    mma16816(acc[2 * np + 1], a0, a1, a2, a3, b2, b3);
                }
            }
        }
    }

    int r0 = r0l;
    if constexpr (ATOMIC) {
        if ((lane & 3) == 0) {
            atomicAdd(&g_denO[i0 + r0],     accd[0]);
            atomicAdd(&g_denO[i0 + r0 + 8], accd[2]);
        }
#pragma unroll
        for (int nt = 0; nt < NC / 8; nt++) {
            atomicAdd(&g_numO[(i0 + r0) * NCLS + nt * 8 + c0],     acc[nt][0]);
            atomicAdd(&g_numO[(i0 + r0) * NCLS + nt * 8 + c0 + 1], acc[nt][1]);
            atomicAdd(&g_numO[(i0 + r0 + 8) * NCLS + nt * 8 + c0],     acc[nt][2]);
            atomicAdd(&g_numO[(i0 + r0 + 8) * NCLS + nt * 8 + c0 + 1], acc[nt][3]);
        }
    } else {
        if ((lane & 3) == 0) {
            g_dpart1[(zspl * H + head) * N + i0 + r0]     = accd[0];
            g_dpart1[(zspl * H + head) * N + i0 + r0 + 8] = accd[2];
        }
        float* po0 = g_part1 + (size_t)zspl * N * FIN
                   + (size_t)(i0 + r0) * FIN + bcol + c0;
        float* po1 = po0 + 8 * FIN;
#pragma unroll
        for (int nt = 0; nt < NC / 8; nt++) {
            *(float2*)(po0 + nt * 8) = make_float2(acc[nt][0], acc[nt][1]);
            *(float2*)(po1 + nt * 8) = make_float2(acc[nt][2], acc[nt][3]);
        }
    }
}

extern "C" void kernel_launch(void* const* d_in, const int* in_sizes, int n_in,
                              void* d_out, int out_size)
{
    const float* x = nullptr;
    const int* adj = nullptr;
    const float *W_heads = nullptr, *a_heads = nullptr, *W_out = nullptr, *a_out = nullptr;
    for (int i = 0; i < n_in; i++) {
        switch (in_sizes[i]) {
            case N * FIN:      x       = (const float*)d_in[i]; break;
            case 67108864:     adj     = (const int*)  d_in[i]; break;
            case H * FIN * KH: W_heads = (const float*)d_in[i]; break;
            case H * 2 * KH:   a_heads = (const float*)d_in[i]; break;
            case FIN * NCLS:   W_out   = (const float*)d_in[i]; break;
            case 2 * NCLS:     a_out   = (const float*)d_in[i]; break;
        }
    }

    float *whoP, *g1P, *g1oP, *numP, *denP;
    __half *wh16P, *who16P, *e2hP, *f2hP, *e2ohP, *f2ohP;
    cudaGetSymbolAddress((void**)&wh16P, g_Wh16);
    cudaGetSymbolAddress((void**)&whoP,  g_Whout);
    cudaGetSymbolAddress((void**)&who16P, g_Whout16);
    cudaGetSymbolAddress((void**)&g1P,  g_G1);
    cudaGetSymbolAddress((void**)&e2hP, g_E2h);
    cudaGetSymbolAddress((void**)&f2hP, g_F2h);
    cudaGetSymbolAddress((void**)&g1oP, g_G1o);
    cudaGetSymbolAddress((void**)&e2ohP, g_E2oh);
    cudaGetSymbolAddress((void**)&f2ohP, g_F2oh);
    cudaGetSymbolAddress((void**)&numP, g_numO);
    cudaGetSymbolAddress((void**)&denP, g_denO);

    cudaFuncSetAttribute((const void*)attn_hmma<64, NSPL1, false>,
                         cudaFuncAttributeMaxDynamicSharedMemorySize, ATT_DSMEM);
    cudaFuncSetAttribute((const void*)attn_hmma<16, 16, true>,
                         cudaFuncAttributeMaxDynamicSharedMemorySize, ATT_DSMEM);
    cudaFuncSetAttribute(gemm_hmma_kernel,
                         cudaFuncAttributeMaxDynamicSharedMemorySize, GEMM_DSMEM);
    cudaFuncSetAttribute(gemm16_kernel,
                         cudaFuncAttributeMaxDynamicSharedMemorySize, GEMM_DSMEM);

    pack_adj_kernel<<<4096, 256>>>(adj);
    convert16_kernel<<<2048, 256>>>(x, W_heads, W_out);
    gemm_hmma_kernel<<<dim3(N / 128, H), 256, GEMM_DSMEM>>>(a_heads);
    cudaMemsetAsync(numP, 0, N * NCLS * sizeof(float));
    cudaMemsetAsync(denP, 0, N * sizeof(float));
    cudaMemsetAsync(whoP, 0, N * NCLS * sizeof(float));
    attn_hmma<64, NSPL1, false><<<dim3(N / 128, H, NSPL1), 256, ATT_DSMEM>>>(
        g1P, e2hP, f2hP, wh16P, FIN);
    finalize1_kernel<<<(N * FIN + 255) / 256, 256>>>();
    gemm16_kernel<<<dim3(N / 128, FIN / 128), 256, GEMM_DSMEM>>>();
    s_out_kernel<<<N / 8, 256>>>(a_out);
    attn_hmma<16, 16, true><<<dim3(N / 128, 1, 16), 256, ATT_DSMEM>>>(
        g1oP, e2ohP, f2ohP, who16P, NCLS);
    finalize_kernel<<<(N * NCLS + 255) / 256, 256>>>((float*)d_out);
}